// round 2
// baseline (speedup 1.0000x reference)
#include <cuda_runtime.h>
#include <math.h>

#define Bb 2
#define Tt 2048
#define Dd 2048
#define Hh 16
#define HDd 128
#define FFd 8192
#define ROWS (Bb*Tt)   /* 4096 */

// ---------------- scratch (no allocations allowed -> device globals) ----------------
__device__ float g_xn  [ROWS*Dd];
__device__ float g_q   [ROWS*Dd];
__device__ float g_k   [ROWS*Dd];
__device__ float g_v   [ROWS*Dd];
__device__ float g_attn[ROWS*Dd];
__device__ float g_ff1 [ROWS*FFd];
__device__ float g_ff2 [ROWS*FFd];

// ---------------- LayerNorm ----------------
__global__ void __launch_bounds__(256) ln_kernel(const float* __restrict__ x,
                                                 const float* __restrict__ g,
                                                 const float* __restrict__ b,
                                                 float* __restrict__ out)
{
    const int row = blockIdx.x;
    const int tid = threadIdx.x;
    const float* xr = x + (size_t)row * Dd;
    __shared__ float red[256];

    float s = 0.f;
    for (int i = tid; i < Dd; i += 256) s += xr[i];
    red[tid] = s; __syncthreads();
    for (int off = 128; off > 0; off >>= 1) {
        if (tid < off) red[tid] += red[tid + off];
        __syncthreads();
    }
    const float mean = red[0] * (1.f / Dd);
    __syncthreads();

    float v = 0.f;
    for (int i = tid; i < Dd; i += 256) { float d = xr[i] - mean; v += d * d; }
    red[tid] = v; __syncthreads();
    for (int off = 128; off > 0; off >>= 1) {
        if (tid < off) red[tid] += red[tid + off];
        __syncthreads();
    }
    const float rstd = rsqrtf(red[0] * (1.f / Dd) + 1e-5f);

    float* orow = out + (size_t)row * Dd;
    for (int i = tid; i < Dd; i += 256)
        orow[i] = (xr[i] - mean) * rstd * g[i] + b[i];
}

// ---------------- GEMM: C[m,n] = sum_k A[m,k]*B[n,k] + bias[n] (+resid) ----------------
// A: MxK row-major, B: NxK row-major (i.e. C = A @ B^T). M,N mult of 128, K mult of 8.
__global__ void __launch_bounds__(256) gemm_kernel(const float* __restrict__ A,
                                                   const float* __restrict__ B,
                                                   const float* __restrict__ bias,
                                                   const float* __restrict__ resid,
                                                   float* __restrict__ C,
                                                   int M, int N, int K)
{
    __shared__ float As[8][128];
    __shared__ float Bs[8][128];
    const int tid = threadIdx.x;
    const int bm = blockIdx.y * 128;
    const int bn = blockIdx.x * 128;
    const int lr = tid >> 1;            // 0..127
    const int lcc = (tid & 1) * 4;      // 0 or 4
    const float* Ap = A + (size_t)(bm + lr) * K + lcc;
    const float* Bp = B + (size_t)(bn + lr) * K + lcc;
    const int tx = tid & 15, ty = tid >> 4;

    float acc[8][8];
#pragma unroll
    for (int i = 0; i < 8; i++)
#pragma unroll
        for (int j = 0; j < 8; j++) acc[i][j] = 0.f;

    for (int k0 = 0; k0 < K; k0 += 8) {
        float4 av = *(const float4*)(Ap + k0);
        float4 bv = *(const float4*)(Bp + k0);
        As[lcc + 0][lr] = av.x; As[lcc + 1][lr] = av.y;
        As[lcc + 2][lr] = av.z; As[lcc + 3][lr] = av.w;
        Bs[lcc + 0][lr] = bv.x; Bs[lcc + 1][lr] = bv.y;
        Bs[lcc + 2][lr] = bv.z; Bs[lcc + 3][lr] = bv.w;
        __syncthreads();
#pragma unroll
        for (int kk = 0; kk < 8; kk++) {
            float a[8], bb[8];
#pragma unroll
            for (int i = 0; i < 8; i++)
                a[i] = As[kk][((i & 4) << 4) + ty * 4 + (i & 3)];
#pragma unroll
            for (int j = 0; j < 8; j++)
                bb[j] = Bs[kk][((j & 4) << 4) + tx * 4 + (j & 3)];
#pragma unroll
            for (int i = 0; i < 8; i++)
#pragma unroll
                for (int j = 0; j < 8; j++)
                    acc[i][j] += a[i] * bb[j];
        }
        __syncthreads();
    }

#pragma unroll
    for (int i = 0; i < 8; i++) {
        const int row = bm + ((i & 4) << 4) + ty * 4 + (i & 3);
#pragma unroll
        for (int j = 0; j < 8; j++) {
            const int col = bn + ((j & 4) << 4) + tx * 4 + (j & 3);
            float vv = acc[i][j] + bias[col];
            if (resid) vv += resid[(size_t)row * N + col];
            C[(size_t)row * N + col] = vv;
        }
    }
}

// ---------------- RoPE (head-indexed freqs, faithful to reference) ----------------
__global__ void rope_kernel(float* __restrict__ q, float* __restrict__ k,
                            const float* __restrict__ fr)
{
    const int idx = blockIdx.x * blockDim.x + threadIdx.x;   // < B*T*H*(HD/2)
    const int j  = idx & 63;
    const int h  = (idx >> 6) & 15;
    const int bt = idx >> 10;
    const size_t base = (size_t)bt * Dd + h * HDd + 2 * j;
    const float cr = fr[h * 128 + 2 * j];
    const float ci = fr[h * 128 + 2 * j + 1];
    float a = q[base], b2 = q[base + 1];
    q[base]     = a * cr - b2 * ci;
    q[base + 1] = a * ci + b2 * cr;
    a = k[base]; b2 = k[base + 1];
    k[base]     = a * cr - b2 * ci;
    k[base + 1] = a * ci + b2 * cr;
}

// ---------------- Flash attention, causal, fp32, HD=128 ----------------
// grid (T/64, H, B), 256 threads. Each thread: query qi=tid>>2, dims slice (tid&3)*32..+31.
__global__ void __launch_bounds__(256) flash_kernel(const float* __restrict__ Q,
                                                    const float* __restrict__ K,
                                                    const float* __restrict__ V,
                                                    float* __restrict__ Out)
{
    extern __shared__ float sm[];
    float* sQ = sm;                 // 64*128
    float* sK = sm + 64 * 128;      // 64*128
    float* sV = sm + 2 * 64 * 128;  // 64*128
    float* sP = sm + 3 * 64 * 128;  // 64*68 (padded rows)

    const int tid = threadIdx.x;
    const int qb = blockIdx.x, h = blockIdx.y, b = blockIdx.z;
    const int q0 = qb * 64;
    const size_t qbase = ((size_t)(b * Tt + q0)) * Dd + h * HDd;

#pragma unroll
    for (int it = 0; it < 8; it++) {
        int f = tid + it * 256;
        int r = f >> 5, c = f & 31;
        *(float4*)(sQ + r * 128 + c * 4) =
            *(const float4*)(Q + qbase + (size_t)r * Dd + c * 4);
    }

    const int qi = tid >> 2;
    const int lc = tid & 3;
    const int rp = ((tid >> 2) + 2 * lc) & 7;   // bank-stagger permutation
    const int dbase = lc * 32;
    const float scale = 0.088388347648318447f;  // 1/sqrt(128)

    float4 O[8];
#pragma unroll
    for (int i = 0; i < 8; i++) O[i] = make_float4(0.f, 0.f, 0.f, 0.f);
    float mrow = -1e30f, lrow = 0.f;

    for (int kb = 0; kb <= qb; kb++) {
        const int j0 = kb * 64;
        const size_t kbase = ((size_t)(b * Tt + j0)) * Dd + h * HDd;
#pragma unroll
        for (int it = 0; it < 8; it++) {
            int f = tid + it * 256;
            int r = f >> 5, c = f & 31;
            *(float4*)(sK + r * 128 + c * 4) =
                *(const float4*)(K + kbase + (size_t)r * Dd + c * 4);
            *(float4*)(sV + r * 128 + c * 4) =
                *(const float4*)(V + kbase + (size_t)r * Dd + c * 4);
        }
        __syncthreads();

        float acc[16];
#pragma unroll
        for (int kk = 0; kk < 16; kk++) acc[kk] = 0.f;

#pragma unroll
        for (int ch = 0; ch < 4; ch++) {
            float4 qreg[8];
#pragma unroll
            for (int i = 0; i < 8; i++) {
                int g = (i + rp) & 7;
                qreg[i] = *(const float4*)(sQ + qi * 128 + ch * 32 + g * 4);
            }
#pragma unroll
            for (int kk = 0; kk < 16; kk++) {
                const float* kr = sK + (lc * 16 + kk) * 128 + ch * 32;
                float s = 0.f;
#pragma unroll
                for (int i = 0; i < 8; i++) {
                    int g = (i + rp) & 7;
                    float4 kv = *(const float4*)(kr + g * 4);
                    s += qreg[i].x * kv.x + qreg[i].y * kv.y
                       + qreg[i].z * kv.z + qreg[i].w * kv.w;
                }
                acc[kk] += s;
            }
        }

        float tmax = -1e30f;
#pragma unroll
        for (int kk = 0; kk < 16; kk++) {
            float s = acc[kk] * scale;
            if (j0 + lc * 16 + kk > q0 + qi) s = -1e30f;
            acc[kk] = s;
            tmax = fmaxf(tmax, s);
        }
        tmax = fmaxf(tmax, __shfl_xor_sync(0xffffffffu, tmax, 1));
        tmax = fmaxf(tmax, __shfl_xor_sync(0xffffffffu, tmax, 2));
        const float mnew = fmaxf(mrow, tmax);
        const float alpha = __expf(mrow - mnew);
        mrow = mnew;

        float psum = 0.f;
#pragma unroll
        for (int kk = 0; kk < 16; kk++) {
            float p = __expf(acc[kk] - mnew);
            psum += p;
            sP[qi * 68 + lc * 16 + kk] = p;
        }
        psum += __shfl_xor_sync(0xffffffffu, psum, 1);
        psum += __shfl_xor_sync(0xffffffffu, psum, 2);
        lrow = lrow * alpha + psum;
#pragma unroll
        for (int i = 0; i < 8; i++) {
            O[i].x *= alpha; O[i].y *= alpha; O[i].z *= alpha; O[i].w *= alpha;
        }
        __syncthreads();

#pragma unroll 4
        for (int k2 = 0; k2 < 64; k2++) {
            const float pv = sP[qi * 68 + k2];
            const float* vr = sV + k2 * 128 + dbase;
#pragma unroll
            for (int i = 0; i < 8; i++) {
                int g = (i + rp) & 7;
                float4 vv = *(const float4*)(vr + g * 4);
                O[i].x += pv * vv.x; O[i].y += pv * vv.y;
                O[i].z += pv * vv.z; O[i].w += pv * vv.w;
            }
        }
        __syncthreads();
    }

    const float inv = 1.f / lrow;
    const size_t obase = ((size_t)(b * Tt + q0 + qi)) * Dd + h * HDd + dbase;
#pragma unroll
    for (int i = 0; i < 8; i++) {
        int g = (i + rp) & 7;
        float4 o = O[i];
        o.x *= inv; o.y *= inv; o.z *= inv; o.w *= inv;
        *(float4*)(Out + obase + g * 4) = o;
    }
}

// ---------------- fused SiLU(gate)*up ----------------
__global__ void silu_mul_kernel(float* __restrict__ gbuf, const float* __restrict__ ubuf)
{
    const int idx = blockIdx.x * blockDim.x + threadIdx.x;
    const float gt = gbuf[idx];
    const float s = gt / (1.f + __expf(-gt));
    gbuf[idx] = s * ubuf[idx];
}

// ---------------- launch ----------------
extern "C" void kernel_launch(void* const* d_in, const int* in_sizes, int n_in,
                              void* d_out, int out_size)
{
    const float* x   = (const float*)d_in[0];
    const float* fr  = (const float*)d_in[1];
    const float* Wq  = (const float*)d_in[2];
    const float* bq  = (const float*)d_in[3];
    const float* Wk  = (const float*)d_in[4];
    const float* bk  = (const float*)d_in[5];
    const float* Wv  = (const float*)d_in[6];
    const float* bv  = (const float*)d_in[7];
    const float* Wo  = (const float*)d_in[8];
    const float* bo  = (const float*)d_in[9];
    const float* g1  = (const float*)d_in[10];
    const float* be1 = (const float*)d_in[11];
    const float* g2  = (const float*)d_in[12];
    const float* be2 = (const float*)d_in[13];
    const float* Wg  = (const float*)d_in[14];
    const float* bg  = (const float*)d_in[15];
    const float* Wu  = (const float*)d_in[16];
    const float* bu  = (const float*)d_in[17];
    const float* Wd  = (const float*)d_in[18];
    const float* bd  = (const float*)d_in[19];
    float* out = (float*)d_out;

    float *xn, *q, *k, *v, *attn, *ff1, *ff2;
    cudaGetSymbolAddress((void**)&xn,   g_xn);
    cudaGetSymbolAddress((void**)&q,    g_q);
    cudaGetSymbolAddress((void**)&k,    g_k);
    cudaGetSymbolAddress((void**)&v,    g_v);
    cudaGetSymbolAddress((void**)&attn, g_attn);
    cudaGetSymbolAddress((void**)&ff1,  g_ff1);
    cudaGetSymbolAddress((void**)&ff2,  g_ff2);

    const int smemF = (3 * 64 * 128 + 64 * 68) * (int)sizeof(float);   // 113 KB
    cudaFuncSetAttribute(flash_kernel, cudaFuncAttributeMaxDynamicSharedMemorySize, smemF);

    // 1) LN1
    ln_kernel<<<ROWS, 256>>>(x, g1, be1, xn);

    // 2) Q,K,V projections
    dim3 gD(Dd / 128, ROWS / 128);
    gemm_kernel<<<gD, 256>>>(xn, Wq, bq, nullptr, q, ROWS, Dd, Dd);
    gemm_kernel<<<gD, 256>>>(xn, Wk, bk, nullptr, k, ROWS, Dd, Dd);
    gemm_kernel<<<gD, 256>>>(xn, Wv, bv, nullptr, v, ROWS, Dd, Dd);

    // 3) RoPE (head-indexed freqs, matching reference)
    rope_kernel<<<(Bb * Tt * Hh * (HDd / 2)) / 256, 256>>>(q, k, fr);

    // 4) causal flash attention -> attn in (B,T,H*HD) layout
    flash_kernel<<<dim3(Tt / 64, Hh, Bb), 256, smemF>>>(q, k, v, attn);

    // 5) output projection + residual(x) -> out
    gemm_kernel<<<gD, 256>>>(attn, Wo, bo, x, out, ROWS, Dd, Dd);

    // 6) LN2
    ln_kernel<<<ROWS, 256>>>(out, g2, be2, xn);

    // 7) gate / up
    dim3 gF(FFd / 128, ROWS / 128);
    gemm_kernel<<<gF, 256>>>(xn, Wg, bg, nullptr, ff1, ROWS, FFd, Dd);
    gemm_kernel<<<gF, 256>>>(xn, Wu, bu, nullptr, ff2, ROWS, FFd, Dd);

    // 8) SiLU(gate)*up
    silu_mul_kernel<<<(ROWS * FFd) / 256, 256>>>(ff1, ff2);

    // 9) down projection + residual(out) -> out
    gemm_kernel<<<gD, 256>>>(ff1, Wd, bd, out, out, ROWS, Dd, FFd);
}

// round 4
// speedup vs baseline: 2.0152x; 2.0152x over previous
#include <cuda_runtime.h>
#include <cuda_bf16.h>
#include <cstdint>
#include <math.h>

#define Bb 2
#define Tt 2048
#define Dd 2048
#define Hh 16
#define HDd 128
#define FFd 8192
#define ROWS (Bb*Tt)   /* 4096 */

// tcgen05 only exists in arch-specific (sm_10xa) compilation phases.
#if defined(__CUDA_ARCH_FEAT_SM103_ALL) || defined(__CUDA_ARCH_FEAT_SM100_ALL) || \
    defined(__CUDA_ARCH_FEAT_SM101_ALL) || \
    (defined(__CUDA_ARCH_SPECIFIC__) && (__CUDA_ARCH_SPECIFIC__ >= 1000)) || \
    (defined(__CUDA_ARCH_FAMILY_SPECIFIC__) && (__CUDA_ARCH_FAMILY_SPECIFIC__ >= 1000))
#define HAS_TCGEN05 1
#else
#define HAS_TCGEN05 0
#endif

// ---------------- scratch (no allocations allowed -> device globals) ----------------
__device__ float g_xn  [ROWS*Dd];
__device__ float g_q   [ROWS*Dd];
__device__ float g_k   [ROWS*Dd];
__device__ float g_v   [ROWS*Dd];
__device__ float g_attn[ROWS*Dd];
__device__ float g_ff1 [ROWS*FFd];
__device__ float g_ff2 [ROWS*FFd];

// ================= tcgen05 helpers (PTX only emitted under HAS_TCGEN05) =================
__device__ __forceinline__ uint32_t smem_u32(const void* p) {
    uint32_t a;
    asm("{ .reg .u64 t; cvta.to.shared.u64 t, %1; cvt.u32.u64 %0, t; }"
        : "=r"(a) : "l"(p));
    return a;
}

#define SW128(o) ((o) ^ (((o) >> 3) & 0x70))

static constexpr uint64_t DESC_BASE_SW128 =
    (uint64_t(2)  << 61) | (uint64_t(1) << 46) | (uint64_t(64) << 32) | (uint64_t(1) << 16);

// idesc: dtype=F32(1<<4), atype=BF16(1<<7), btype=BF16(1<<10), N=256 (32<<17), M=128 (8<<24)
#define MMA_IDESC 0x8400490u

#if HAS_TCGEN05
__device__ __forceinline__ uint32_t elect1() {
    uint32_t p;
    asm volatile("{\n\t.reg .pred p;\n\telect.sync _|p, 0xFFFFFFFF;\n\tselp.b32 %0,1,0,p;\n\t}"
                 : "=r"(p));
    return p;
}
__device__ __forceinline__ uint64_t mkdesc(uint32_t addr) {
    return DESC_BASE_SW128 | ((uint64_t)(addr >> 4) & 0x3FFF);
}
__device__ __forceinline__ void mma_bf16_ss(uint32_t d, uint64_t ad, uint64_t bd, uint32_t en) {
    asm volatile(
        "{\n\t.reg .pred p;\n\tsetp.ne.u32 p, %4, 0;\n\t"
        "tcgen05.mma.cta_group::1.kind::f16 [%0], %1, %2, %3, {%5,%5,%5,%5}, p;\n\t}"
        :: "r"(d), "l"(ad), "l"(bd), "r"(MMA_IDESC), "r"(en), "r"(0u) : "memory");
}
__device__ __forceinline__ void mbar_init(uint32_t m, uint32_t cnt) {
    asm volatile("mbarrier.init.shared.b64 [%0], %1;" :: "r"(m), "r"(cnt) : "memory");
}
__device__ __forceinline__ void mbar_wait(uint32_t m, uint32_t parity) {
    asm volatile(
        "{\n\t.reg .pred P1;\n"
        "W%=:\n\t"
        "mbarrier.try_wait.parity.acquire.cta.shared::cta.b64 P1, [%0], %1, 0x989680;\n\t"
        "@P1 bra.uni D%=;\n\t"
        "bra.uni W%=;\n"
        "D%=:\n\t}"
        :: "r"(m), "r"(parity) : "memory");
}
__device__ __forceinline__ void tc_commit(uint32_t m) {
    asm volatile("tcgen05.commit.cta_group::1.mbarrier::arrive::one.shared::cluster.b64 [%0];"
                 :: "r"(m) : "memory");
}
__device__ __forceinline__ void ldtm32(uint32_t* r, uint32_t a) {
    asm volatile(
        "tcgen05.ld.sync.aligned.32x32b.x32.b32 "
        "{%0,%1,%2,%3,%4,%5,%6,%7,%8,%9,%10,%11,%12,%13,%14,%15,"
        "%16,%17,%18,%19,%20,%21,%22,%23,%24,%25,%26,%27,%28,%29,%30,%31}, [%32];"
        : "=r"(r[0]),"=r"(r[1]),"=r"(r[2]),"=r"(r[3]),"=r"(r[4]),"=r"(r[5]),"=r"(r[6]),"=r"(r[7]),
          "=r"(r[8]),"=r"(r[9]),"=r"(r[10]),"=r"(r[11]),"=r"(r[12]),"=r"(r[13]),"=r"(r[14]),"=r"(r[15]),
          "=r"(r[16]),"=r"(r[17]),"=r"(r[18]),"=r"(r[19]),"=r"(r[20]),"=r"(r[21]),"=r"(r[22]),"=r"(r[23]),
          "=r"(r[24]),"=r"(r[25]),"=r"(r[26]),"=r"(r[27]),"=r"(r[28]),"=r"(r[29]),"=r"(r[30]),"=r"(r[31])
        : "r"(a));
}
#endif  // HAS_TCGEN05

__device__ __forceinline__ void split4(float4 v, uint2& hi, uint2& lo) {
    __nv_bfloat162 h0 = __floats2bfloat162_rn(v.x, v.y);
    __nv_bfloat162 h1 = __floats2bfloat162_rn(v.z, v.w);
    float lx = v.x - __bfloat162float(__low2bfloat16(h0));
    float ly = v.y - __bfloat162float(__high2bfloat16(h0));
    float lz = v.z - __bfloat162float(__low2bfloat16(h1));
    float lw = v.w - __bfloat162float(__high2bfloat16(h1));
    __nv_bfloat162 l0 = __floats2bfloat162_rn(lx, ly);
    __nv_bfloat162 l1 = __floats2bfloat162_rn(lz, lw);
    hi.x = *reinterpret_cast<uint32_t*>(&h0);
    hi.y = *reinterpret_cast<uint32_t*>(&h1);
    lo.x = *reinterpret_cast<uint32_t*>(&l0);
    lo.y = *reinterpret_cast<uint32_t*>(&l1);
}

// ============ GEMM: C[m,n] = sum_k A[m,k]*B[n,k] + bias[n] (+resid) ============
// Grid: (N/256, M/128), 256 threads. A: MxK row-major fp32, B: NxK row-major fp32.
// sm_103a phase: tcgen05 bf16x3 split GEMM (BM=128,BN=256,BK=64, 2-stage pipeline).
// baseline phase: SIMT fp32 GEMM (two 128-col halves per block).
#define STAGE_BYTES 98304   /* A_hi 16K | A_lo 16K | B_hi 32K | B_lo 32K */
#define GEMM_SMEM (2 * STAGE_BYTES + 2048)

__global__ void __launch_bounds__(256, 1)
mma_gemm_kernel(const float* __restrict__ A, const float* __restrict__ B,
                const float* __restrict__ bias, const float* __restrict__ resid,
                float* __restrict__ C, int M, int N, int K)
{
    extern __shared__ char smem[];
#if HAS_TCGEN05
    const uint32_t sbase = smem_u32(smem);
    const int tid  = threadIdx.x;
    const int wid  = tid >> 5;
    const int lane = tid & 31;
    const int bn = blockIdx.x * 256;
    const int bm = blockIdx.y * 128;

    const uint32_t tile_abs = (sbase + 32 + 1023) & ~1023u;
    const uint32_t tile_off = tile_abs - sbase;
    const uint32_t mbar0 = sbase + 8;
    const uint32_t mbar1 = sbase + 16;

    if (wid == 0) {
        asm volatile("tcgen05.alloc.cta_group::1.sync.aligned.shared::cta.b32 [%0], %1;"
                     :: "r"(sbase), "r"(256u) : "memory");
        asm volatile("tcgen05.relinquish_alloc_permit.cta_group::1.sync.aligned;");
    }
    if (tid == 0) { mbar_init(mbar0, 1); mbar_init(mbar1, 1); }
    __syncthreads();
    uint32_t tmem;
    asm volatile("ld.shared.b32 %0, [%1];" : "=r"(tmem) : "r"(sbase));

    const int arow = tid >> 1;
    const float* Aptr = A + (size_t)(bm + arow) * K + (tid & 1) * 32;
    const float* Bptr = B + (size_t)(bn + tid) * K;
    const uint32_t aoff = arow * 128 + (tid & 1) * 64;
    const uint32_t boff = tid * 128;

    const int nchunk = K >> 6;

    for (int i = 0; i < nchunk; i++) {
        const int s = i & 1;
        const uint32_t stage_off = tile_off + s * STAGE_BYTES;
        const uint32_t stage_abs = tile_abs + s * STAGE_BYTES;

        float4 av[8], bv[16];
#pragma unroll
        for (int j = 0; j < 8; j++)  av[j] = *(const float4*)(Aptr + j * 4);
#pragma unroll
        for (int j = 0; j < 16; j++) bv[j] = *(const float4*)(Bptr + j * 4);
        Aptr += 64; Bptr += 64;

        if (i >= 2) mbar_wait(s ? mbar1 : mbar0, ((i >> 1) - 1) & 1);

#pragma unroll
        for (int j = 0; j < 8; j++) {
            uint2 hi, lo; split4(av[j], hi, lo);
            uint32_t o = SW128(aoff + j * 8);
            *(uint2*)(smem + stage_off + o)         = hi;
            *(uint2*)(smem + stage_off + 16384 + o) = lo;
        }
#pragma unroll
        for (int j = 0; j < 16; j++) {
            uint2 hi, lo; split4(bv[j], hi, lo);
            uint32_t o = SW128(boff + j * 8);
            *(uint2*)(smem + stage_off + 32768 + o) = hi;
            *(uint2*)(smem + stage_off + 65536 + o) = lo;
        }
        asm volatile("fence.proxy.async.shared::cta;" ::: "memory");
        __syncthreads();

        if (wid == 0 && elect1()) {
            const uint64_t ah = mkdesc(stage_abs);
            const uint64_t al = mkdesc(stage_abs + 16384);
            const uint64_t bh = mkdesc(stage_abs + 32768);
            const uint64_t bl = mkdesc(stage_abs + 65536);
#pragma unroll
            for (int k = 0; k < 4; k++)
                mma_bf16_ss(tmem, ah + k * 2, bh + k * 2, (i > 0 || k > 0) ? 1u : 0u);
#pragma unroll
            for (int k = 0; k < 4; k++)
                mma_bf16_ss(tmem, ah + k * 2, bl + k * 2, 1u);
#pragma unroll
            for (int k = 0; k < 4; k++)
                mma_bf16_ss(tmem, al + k * 2, bh + k * 2, 1u);
            tc_commit(s ? mbar1 : mbar0);
        }
    }

    {
        const int il = nchunk - 1, s = il & 1;
        mbar_wait(s ? mbar1 : mbar0, ((il >> 1) & 1));
    }
    asm volatile("tcgen05.fence::after_thread_sync;" ::: "memory");

    const int sub  = wid & 3;
    const int half = wid >> 2;
    const int row  = bm + sub * 32 + lane;
    const float* rrow = resid ? resid + (size_t)row * N : nullptr;
    float* crow = C + (size_t)row * N;
#pragma unroll 1
    for (int c32 = 0; c32 < 4; c32++) {
        uint32_t d[32];
        ldtm32(d, tmem + half * 128 + c32 * 32);
        asm volatile("tcgen05.wait::ld.sync.aligned;" ::: "memory");
        const int col0 = bn + half * 128 + c32 * 32;
        if (rrow) {
#pragma unroll
            for (int j = 0; j < 32; j++)
                crow[col0 + j] = __uint_as_float(d[j]) + bias[col0 + j] + rrow[col0 + j];
        } else {
#pragma unroll
            for (int j = 0; j < 32; j++)
                crow[col0 + j] = __uint_as_float(d[j]) + bias[col0 + j];
        }
    }
    __syncthreads();
    if (wid == 0) {
        asm volatile("tcgen05.dealloc.cta_group::1.sync.aligned.b32 %0, %1;"
                     :: "r"(tmem), "r"(256u));
    }
#else
    // ---------- baseline-PTX fallback: SIMT fp32, two 128-wide halves ----------
    float* As = (float*)smem;            // [8][128]
    float* Bs = As + 8 * 128;            // [8][128]
    const int tid = threadIdx.x;
    const int bm = blockIdx.y * 128;
    const int lr  = tid >> 1;
    const int lcc = (tid & 1) * 4;
    const int tx = tid & 15, ty = tid >> 4;
    const float* Ap = A + (size_t)(bm + lr) * K + lcc;

    for (int h = 0; h < 2; h++) {
        const int bn = blockIdx.x * 256 + h * 128;
        const float* Bp = B + (size_t)(bn + lr) * K + lcc;

        float acc[8][8];
#pragma unroll
        for (int i = 0; i < 8; i++)
#pragma unroll
            for (int j = 0; j < 8; j++) acc[i][j] = 0.f;

        for (int k0 = 0; k0 < K; k0 += 8) {
            float4 av = *(const float4*)(Ap + k0);
            float4 bv = *(const float4*)(Bp + k0);
            As[(lcc + 0) * 128 + lr] = av.x; As[(lcc + 1) * 128 + lr] = av.y;
            As[(lcc + 2) * 128 + lr] = av.z; As[(lcc + 3) * 128 + lr] = av.w;
            Bs[(lcc + 0) * 128 + lr] = bv.x; Bs[(lcc + 1) * 128 + lr] = bv.y;
            Bs[(lcc + 2) * 128 + lr] = bv.z; Bs[(lcc + 3) * 128 + lr] = bv.w;
            __syncthreads();
#pragma unroll
            for (int kk = 0; kk < 8; kk++) {
                float a[8], bb[8];
#pragma unroll
                for (int i = 0; i < 8; i++)
                    a[i] = As[kk * 128 + ((i & 4) << 4) + ty * 4 + (i & 3)];
#pragma unroll
                for (int j = 0; j < 8; j++)
                    bb[j] = Bs[kk * 128 + ((j & 4) << 4) + tx * 4 + (j & 3)];
#pragma unroll
                for (int i = 0; i < 8; i++)
#pragma unroll
                    for (int j = 0; j < 8; j++)
                        acc[i][j] += a[i] * bb[j];
            }
            __syncthreads();
        }

#pragma unroll
        for (int i = 0; i < 8; i++) {
            const int row = bm + ((i & 4) << 4) + ty * 4 + (i & 3);
#pragma unroll
            for (int j = 0; j < 8; j++) {
                const int col = bn + ((j & 4) << 4) + tx * 4 + (j & 3);
                float vv = acc[i][j] + bias[col];
                if (resid) vv += resid[(size_t)row * N + col];
                C[(size_t)row * N + col] = vv;
            }
        }
    }
#endif
}

// ---------------- LayerNorm ----------------
__global__ void __launch_bounds__(256) ln_kernel(const float* __restrict__ x,
                                                 const float* __restrict__ g,
                                                 const float* __restrict__ b,
                                                 float* __restrict__ out)
{
    const int row = blockIdx.x;
    const int tid = threadIdx.x;
    const float* xr = x + (size_t)row * Dd;
    __shared__ float red[256];

    float s = 0.f;
    for (int i = tid; i < Dd; i += 256) s += xr[i];
    red[tid] = s; __syncthreads();
    for (int off = 128; off > 0; off >>= 1) {
        if (tid < off) red[tid] += red[tid + off];
        __syncthreads();
    }
    const float mean = red[0] * (1.f / Dd);
    __syncthreads();

    float v = 0.f;
    for (int i = tid; i < Dd; i += 256) { float d = xr[i] - mean; v += d * d; }
    red[tid] = v; __syncthreads();
    for (int off = 128; off > 0; off >>= 1) {
        if (tid < off) red[tid] += red[tid + off];
        __syncthreads();
    }
    const float rstd = rsqrtf(red[0] * (1.f / Dd) + 1e-5f);

    float* orow = out + (size_t)row * Dd;
    for (int i = tid; i < Dd; i += 256)
        orow[i] = (xr[i] - mean) * rstd * g[i] + b[i];
}

// ---------------- RoPE (head-indexed freqs, faithful to reference) ----------------
__global__ void rope_kernel(float* __restrict__ q, float* __restrict__ k,
                            const float* __restrict__ fr)
{
    const int idx = blockIdx.x * blockDim.x + threadIdx.x;
    const int j  = idx & 63;
    const int h  = (idx >> 6) & 15;
    const int bt = idx >> 10;
    const size_t base = (size_t)bt * Dd + h * HDd + 2 * j;
    const float cr = fr[h * 128 + 2 * j];
    const float ci = fr[h * 128 + 2 * j + 1];
    float a = q[base], b2 = q[base + 1];
    q[base]     = a * cr - b2 * ci;
    q[base + 1] = a * ci + b2 * cr;
    a = k[base]; b2 = k[base + 1];
    k[base]     = a * cr - b2 * ci;
    k[base + 1] = a * ci + b2 * cr;
}

// ---------------- Flash attention, causal, fp32, HD=128 ----------------
__global__ void __launch_bounds__(256) flash_kernel(const float* __restrict__ Q,
                                                    const float* __restrict__ K,
                                                    const float* __restrict__ V,
                                                    float* __restrict__ Out)
{
    extern __shared__ float sm[];
    float* sQ = sm;
    float* sK = sm + 64 * 128;
    float* sV = sm + 2 * 64 * 128;
    float* sP = sm + 3 * 64 * 128;

    const int tid = threadIdx.x;
    const int qb = blockIdx.x, h = blockIdx.y, b = blockIdx.z;
    const int q0 = qb * 64;
    const size_t qbase = ((size_t)(b * Tt + q0)) * Dd + h * HDd;

#pragma unroll
    for (int it = 0; it < 8; it++) {
        int f = tid + it * 256;
        int r = f >> 5, c = f & 31;
        *(float4*)(sQ + r * 128 + c * 4) =
            *(const float4*)(Q + qbase + (size_t)r * Dd + c * 4);
    }

    const int qi = tid >> 2;
    const int lc = tid & 3;
    const int rp = ((tid >> 2) + 2 * lc) & 7;
    const int dbase = lc * 32;
    const float scale = 0.088388347648318447f;

    float4 O[8];
#pragma unroll
    for (int i = 0; i < 8; i++) O[i] = make_float4(0.f, 0.f, 0.f, 0.f);
    float mrow = -1e30f, lrow = 0.f;

    for (int kb = 0; kb <= qb; kb++) {
        const int j0 = kb * 64;
        const size_t kbase = ((size_t)(b * Tt + j0)) * Dd + h * HDd;
#pragma unroll
        for (int it = 0; it < 8; it++) {
            int f = tid + it * 256;
            int r = f >> 5, c = f & 31;
            *(float4*)(sK + r * 128 + c * 4) =
                *(const float4*)(K + kbase + (size_t)r * Dd + c * 4);
            *(float4*)(sV + r * 128 + c * 4) =
                *(const float4*)(V + kbase + (size_t)r * Dd + c * 4);
        }
        __syncthreads();

        float acc[16];
#pragma unroll
        for (int kk = 0; kk < 16; kk++) acc[kk] = 0.f;

#pragma unroll
        for (int ch = 0; ch < 4; ch++) {
            float4 qreg[8];
#pragma unroll
            for (int i = 0; i < 8; i++) {
                int g = (i + rp) & 7;
                qreg[i] = *(const float4*)(sQ + qi * 128 + ch * 32 + g * 4);
            }
#pragma unroll
            for (int kk = 0; kk < 16; kk++) {
                const float* kr = sK + (lc * 16 + kk) * 128 + ch * 32;
                float s = 0.f;
#pragma unroll
                for (int i = 0; i < 8; i++) {
                    int g = (i + rp) & 7;
                    float4 kv = *(const float4*)(kr + g * 4);
                    s += qreg[i].x * kv.x + qreg[i].y * kv.y
                       + qreg[i].z * kv.z + qreg[i].w * kv.w;
                }
                acc[kk] += s;
            }
        }

        float tmax = -1e30f;
#pragma unroll
        for (int kk = 0; kk < 16; kk++) {
            float s = acc[kk] * scale;
            if (j0 + lc * 16 + kk > q0 + qi) s = -1e30f;
            acc[kk] = s;
            tmax = fmaxf(tmax, s);
        }
        tmax = fmaxf(tmax, __shfl_xor_sync(0xffffffffu, tmax, 1));
        tmax = fmaxf(tmax, __shfl_xor_sync(0xffffffffu, tmax, 2));
        const float mnew = fmaxf(mrow, tmax);
        const float alpha = __expf(mrow - mnew);
        mrow = mnew;

        float psum = 0.f;
#pragma unroll
        for (int kk = 0; kk < 16; kk++) {
            float p = __expf(acc[kk] - mnew);
            psum += p;
            sP[qi * 68 + lc * 16 + kk] = p;
        }
        psum += __shfl_xor_sync(0xffffffffu, psum, 1);
        psum += __shfl_xor_sync(0xffffffffu, psum, 2);
        lrow = lrow * alpha + psum;
#pragma unroll
        for (int i = 0; i < 8; i++) {
            O[i].x *= alpha; O[i].y *= alpha; O[i].z *= alpha; O[i].w *= alpha;
        }
        __syncthreads();

#pragma unroll 4
        for (int k2 = 0; k2 < 64; k2++) {
            const float pv = sP[qi * 68 + k2];
            const float* vr = sV + k2 * 128 + dbase;
#pragma unroll
            for (int i = 0; i < 8; i++) {
                int g = (i + rp) & 7;
                float4 vv = *(const float4*)(vr + g * 4);
                O[i].x += pv * vv.x; O[i].y += pv * vv.y;
                O[i].z += pv * vv.z; O[i].w += pv * vv.w;
            }
        }
        __syncthreads();
    }

    const float inv = 1.f / lrow;
    const size_t obase = ((size_t)(b * Tt + q0 + qi)) * Dd + h * HDd + dbase;
#pragma unroll
    for (int i = 0; i < 8; i++) {
        int g = (i + rp) & 7;
        float4 o = O[i];
        o.x *= inv; o.y *= inv; o.z *= inv; o.w *= inv;
        *(float4*)(Out + obase + g * 4) = o;
    }
}

// ---------------- fused SiLU(gate)*up ----------------
__global__ void silu_mul_kernel(float* __restrict__ gbuf, const float* __restrict__ ubuf)
{
    const int idx = blockIdx.x * blockDim.x + threadIdx.x;
    const float gt = gbuf[idx];
    const float s = gt / (1.f + __expf(-gt));
    gbuf[idx] = s * ubuf[idx];
}

// ---------------- launch ----------------
extern "C" void kernel_launch(void* const* d_in, const int* in_sizes, int n_in,
                              void* d_out, int out_size)
{
    const float* x   = (const float*)d_in[0];
    const float* fr  = (const float*)d_in[1];
    const float* Wq  = (const float*)d_in[2];
    const float* bq  = (const float*)d_in[3];
    const float* Wk  = (const float*)d_in[4];
    const float* bk  = (const float*)d_in[5];
    const float* Wv  = (const float*)d_in[6];
    const float* bv  = (const float*)d_in[7];
    const float* Wo  = (const float*)d_in[8];
    const float* bo  = (const float*)d_in[9];
    const float* g1  = (const float*)d_in[10];
    const float* be1 = (const float*)d_in[11];
    const float* g2  = (const float*)d_in[12];
    const float* be2 = (const float*)d_in[13];
    const float* Wg  = (const float*)d_in[14];
    const float* bg  = (const float*)d_in[15];
    const float* Wu  = (const float*)d_in[16];
    const float* bu  = (const float*)d_in[17];
    const float* Wd  = (const float*)d_in[18];
    const float* bd  = (const float*)d_in[19];
    float* out = (float*)d_out;

    float *xn, *q, *k, *v, *attn, *ff1, *ff2;
    cudaGetSymbolAddress((void**)&xn,   g_xn);
    cudaGetSymbolAddress((void**)&q,    g_q);
    cudaGetSymbolAddress((void**)&k,    g_k);
    cudaGetSymbolAddress((void**)&v,    g_v);
    cudaGetSymbolAddress((void**)&attn, g_attn);
    cudaGetSymbolAddress((void**)&ff1,  g_ff1);
    cudaGetSymbolAddress((void**)&ff2,  g_ff2);

    const int smemF = (3 * 64 * 128 + 64 * 68) * (int)sizeof(float);   // 113 KB
    cudaFuncSetAttribute(flash_kernel, cudaFuncAttributeMaxDynamicSharedMemorySize, smemF);
    cudaFuncSetAttribute(mma_gemm_kernel, cudaFuncAttributeMaxDynamicSharedMemorySize, GEMM_SMEM);

    // 1) LN1
    ln_kernel<<<ROWS, 256>>>(x, g1, be1, xn);

    // 2) Q,K,V projections
    dim3 gD(Dd / 256, ROWS / 128);
    mma_gemm_kernel<<<gD, 256, GEMM_SMEM>>>(xn, Wq, bq, nullptr, q, ROWS, Dd, Dd);
    mma_gemm_kernel<<<gD, 256, GEMM_SMEM>>>(xn, Wk, bk, nullptr, k, ROWS, Dd, Dd);
    mma_gemm_kernel<<<gD, 256, GEMM_SMEM>>>(xn, Wv, bv, nullptr, v, ROWS, Dd, Dd);

    // 3) RoPE
    rope_kernel<<<(Bb * Tt * Hh * (HDd / 2)) / 256, 256>>>(q, k, fr);

    // 4) causal flash attention
    flash_kernel<<<dim3(Tt / 64, Hh, Bb), 256, smemF>>>(q, k, v, attn);

    // 5) output projection + residual(x) -> out
    mma_gemm_kernel<<<gD, 256, GEMM_SMEM>>>(attn, Wo, bo, x, out, ROWS, Dd, Dd);

    // 6) LN2
    ln_kernel<<<ROWS, 256>>>(out, g2, be2, xn);

    // 7) gate / up
    dim3 gF(FFd / 256, ROWS / 128);
    mma_gemm_kernel<<<gF, 256, GEMM_SMEM>>>(xn, Wg, bg, nullptr, ff1, ROWS, FFd, Dd);
    mma_gemm_kernel<<<gF, 256, GEMM_SMEM>>>(xn, Wu, bu, nullptr, ff2, ROWS, FFd, Dd);

    // 8) SiLU(gate)*up
    silu_mul_kernel<<<(ROWS * FFd) / 256, 256>>>(ff1, ff2);

    // 9) down projection + residual(out) -> out
    mma_gemm_kernel<<<gD, 256, GEMM_SMEM>>>(ff1, Wd, bd, out, out, ROWS, Dd, FFd);
}

// round 5
// speedup vs baseline: 2.2325x; 1.1078x over previous
#include <cuda_runtime.h>
#include <cuda_bf16.h>
#include <cstdint>
#include <math.h>

#define Bb 2
#define Tt 2048
#define Dd 2048
#define Hh 16
#define HDd 128
#define FFd 8192
#define ROWS (Bb*Tt)   /* 4096 */

// tcgen05 only exists in arch-specific (sm_10xa) compilation phases.
#if defined(__CUDA_ARCH_FEAT_SM103_ALL) || defined(__CUDA_ARCH_FEAT_SM100_ALL) || \
    defined(__CUDA_ARCH_FEAT_SM101_ALL) || \
    (defined(__CUDA_ARCH_SPECIFIC__) && (__CUDA_ARCH_SPECIFIC__ >= 1000)) || \
    (defined(__CUDA_ARCH_FAMILY_SPECIFIC__) && (__CUDA_ARCH_FAMILY_SPECIFIC__ >= 1000))
#define HAS_TCGEN05 1
#else
#define HAS_TCGEN05 0
#endif

// ---------------- scratch (no allocations allowed -> device globals) ----------------
__device__ float g_xn  [ROWS*Dd];
__device__ float g_q   [ROWS*Dd];
__device__ float g_k   [ROWS*Dd];
__device__ float g_v   [ROWS*Dd];
__device__ float g_attn[ROWS*Dd];
__device__ float g_ff1 [ROWS*FFd];
__device__ float g_ff2 [ROWS*FFd];
// bf16 split buffers: A side up to ROWS*FFd elems, B side up to FFd*Dd elems
__device__ __nv_bfloat16 g_Ahi[ROWS*FFd];
__device__ __nv_bfloat16 g_Alo[ROWS*FFd];
__device__ __nv_bfloat16 g_Bhi[FFd*Dd];
__device__ __nv_bfloat16 g_Blo[FFd*Dd];

// ================= tcgen05 helpers =================
__device__ __forceinline__ uint32_t smem_u32(const void* p) {
    uint32_t a;
    asm("{ .reg .u64 t; cvta.to.shared.u64 t, %1; cvt.u32.u64 %0, t; }"
        : "=r"(a) : "l"(p));
    return a;
}

#define SW128(o) ((o) ^ (((o) >> 3) & 0x70))

static constexpr uint64_t DESC_BASE_SW128 =
    (uint64_t(2)  << 61) | (uint64_t(1) << 46) | (uint64_t(64) << 32) | (uint64_t(1) << 16);

// idesc: dtype=F32(1<<4), atype=BF16(1<<7), btype=BF16(1<<10), N=256 (32<<17), M=128 (8<<24)
#define MMA_IDESC 0x8400490u

#if HAS_TCGEN05
__device__ __forceinline__ uint32_t elect1() {
    uint32_t p;
    asm volatile("{\n\t.reg .pred p;\n\telect.sync _|p, 0xFFFFFFFF;\n\tselp.b32 %0,1,0,p;\n\t}"
                 : "=r"(p));
    return p;
}
__device__ __forceinline__ uint64_t mkdesc(uint32_t addr) {
    return DESC_BASE_SW128 | ((uint64_t)(addr >> 4) & 0x3FFF);
}
__device__ __forceinline__ void mma_bf16_ss(uint32_t d, uint64_t ad, uint64_t bd, uint32_t en) {
    asm volatile(
        "{\n\t.reg .pred p;\n\tsetp.ne.u32 p, %4, 0;\n\t"
        "tcgen05.mma.cta_group::1.kind::f16 [%0], %1, %2, %3, {%5,%5,%5,%5}, p;\n\t}"
        :: "r"(d), "l"(ad), "l"(bd), "r"(MMA_IDESC), "r"(en), "r"(0u) : "memory");
}
__device__ __forceinline__ void mbar_init(uint32_t m, uint32_t cnt) {
    asm volatile("mbarrier.init.shared.b64 [%0], %1;" :: "r"(m), "r"(cnt) : "memory");
}
__device__ __forceinline__ void mbar_wait(uint32_t m, uint32_t parity) {
    asm volatile(
        "{\n\t.reg .pred P1;\n"
        "W%=:\n\t"
        "mbarrier.try_wait.parity.acquire.cta.shared::cta.b64 P1, [%0], %1, 0x989680;\n\t"
        "@P1 bra.uni D%=;\n\t"
        "bra.uni W%=;\n"
        "D%=:\n\t}"
        :: "r"(m), "r"(parity) : "memory");
}
__device__ __forceinline__ void tc_commit(uint32_t m) {
    asm volatile("tcgen05.commit.cta_group::1.mbarrier::arrive::one.shared::cluster.b64 [%0];"
                 :: "r"(m) : "memory");
}
__device__ __forceinline__ void ldtm32(uint32_t* r, uint32_t a) {
    asm volatile(
        "tcgen05.ld.sync.aligned.32x32b.x32.b32 "
        "{%0,%1,%2,%3,%4,%5,%6,%7,%8,%9,%10,%11,%12,%13,%14,%15,"
        "%16,%17,%18,%19,%20,%21,%22,%23,%24,%25,%26,%27,%28,%29,%30,%31}, [%32];"
        : "=r"(r[0]),"=r"(r[1]),"=r"(r[2]),"=r"(r[3]),"=r"(r[4]),"=r"(r[5]),"=r"(r[6]),"=r"(r[7]),
          "=r"(r[8]),"=r"(r[9]),"=r"(r[10]),"=r"(r[11]),"=r"(r[12]),"=r"(r[13]),"=r"(r[14]),"=r"(r[15]),
          "=r"(r[16]),"=r"(r[17]),"=r"(r[18]),"=r"(r[19]),"=r"(r[20]),"=r"(r[21]),"=r"(r[22]),"=r"(r[23]),
          "=r"(r[24]),"=r"(r[25]),"=r"(r[26]),"=r"(r[27]),"=r"(r[28]),"=r"(r[29]),"=r"(r[30]),"=r"(r[31])
        : "r"(a));
}
#endif  // HAS_TCGEN05

// ---------------- split fp32 -> bf16 hi/lo ----------------
__global__ void __launch_bounds__(256) split_kernel(const float* __restrict__ src,
                                                    __nv_bfloat16* __restrict__ hi,
                                                    __nv_bfloat16* __restrict__ lo,
                                                    int n4)
{
    int idx = blockIdx.x * blockDim.x + threadIdx.x;
    if (idx >= n4) return;
    float4 v = ((const float4*)src)[idx];
    __nv_bfloat162 h0 = __floats2bfloat162_rn(v.x, v.y);
    __nv_bfloat162 h1 = __floats2bfloat162_rn(v.z, v.w);
    float lx = v.x - __bfloat162float(__low2bfloat16(h0));
    float ly = v.y - __bfloat162float(__high2bfloat16(h0));
    float lz = v.z - __bfloat162float(__low2bfloat16(h1));
    float lw = v.w - __bfloat162float(__high2bfloat16(h1));
    __nv_bfloat162 l0 = __floats2bfloat162_rn(lx, ly);
    __nv_bfloat162 l1 = __floats2bfloat162_rn(lz, lw);
    uint2 ho, loo;
    ho.x  = *reinterpret_cast<uint32_t*>(&h0);
    ho.y  = *reinterpret_cast<uint32_t*>(&h1);
    loo.x = *reinterpret_cast<uint32_t*>(&l0);
    loo.y = *reinterpret_cast<uint32_t*>(&l1);
    ((uint2*)hi)[idx] = ho;
    ((uint2*)lo)[idx] = loo;
}

// ============ GEMM: C[m,n] = sum_k A[m,k]*B[n,k] + bias[n] (+resid), pre-split bf16 ============
// Grid: (N/256, M/128), 256 threads. Ah/Al: MxK bf16, Bh/Bl: NxK bf16.
#define STAGE_BYTES 98304   /* A_hi 16K | A_lo 16K | B_hi 32K | B_lo 32K */
#define GEMM_SMEM (2 * STAGE_BYTES + 2048)

__global__ void __launch_bounds__(256, 1)
mma_gemm_kernel(const __nv_bfloat16* __restrict__ Ah, const __nv_bfloat16* __restrict__ Al,
                const __nv_bfloat16* __restrict__ Bh, const __nv_bfloat16* __restrict__ Bl,
                const float* __restrict__ bias, const float* __restrict__ resid,
                float* __restrict__ C, int M, int N, int K)
{
    extern __shared__ char smem[];
#if HAS_TCGEN05
    const uint32_t sbase = smem_u32(smem);
    const int tid  = threadIdx.x;
    const int wid  = tid >> 5;
    const int lane = tid & 31;
    const int bn = blockIdx.x * 256;
    const int bm = blockIdx.y * 128;

    const uint32_t tile_abs = (sbase + 32 + 1023) & ~1023u;
    const uint32_t tile_off = tile_abs - sbase;
    const uint32_t mbar0 = sbase + 8;
    const uint32_t mbar1 = sbase + 16;

    if (wid == 0) {
        asm volatile("tcgen05.alloc.cta_group::1.sync.aligned.shared::cta.b32 [%0], %1;"
                     :: "r"(sbase), "r"(256u) : "memory");
        asm volatile("tcgen05.relinquish_alloc_permit.cta_group::1.sync.aligned;");
    }
    if (tid == 0) { mbar_init(mbar0, 1); mbar_init(mbar1, 1); }
    __syncthreads();
    uint32_t tmem;
    asm volatile("ld.shared.b32 %0, [%1];" : "=r"(tmem) : "r"(sbase));

    // producer mapping (bf16 tiles, 128B per row-chunk):
    // A: 128 rows; thread t -> row t>>1, 64B half (t&1):  4 x uint4 per operand
    // B: 256 rows; thread t -> row t, full 128B:           8 x uint4 per operand
    const int arow = tid >> 1;
    const int ahalf = tid & 1;
    const __nv_bfloat16* ApH = Ah + (size_t)(bm + arow) * K + ahalf * 32;
    const __nv_bfloat16* ApL = Al + (size_t)(bm + arow) * K + ahalf * 32;
    const __nv_bfloat16* BpH = Bh + (size_t)(bn + tid) * K;
    const __nv_bfloat16* BpL = Bl + (size_t)(bn + tid) * K;
    const uint32_t aoff = arow * 128 + ahalf * 64;
    const uint32_t boff = tid * 128;

    const int nchunk = K >> 6;

    for (int i = 0; i < nchunk; i++) {
        const int s = i & 1;
        const uint32_t stage_off = tile_off + s * STAGE_BYTES;
        const uint32_t stage_abs = tile_abs + s * STAGE_BYTES;

        uint4 avh[4], avl[4], bvh[8], bvl[8];
#pragma unroll
        for (int j = 0; j < 4; j++) avh[j] = ((const uint4*)ApH)[j];
#pragma unroll
        for (int j = 0; j < 4; j++) avl[j] = ((const uint4*)ApL)[j];
#pragma unroll
        for (int j = 0; j < 8; j++) bvh[j] = ((const uint4*)BpH)[j];
#pragma unroll
        for (int j = 0; j < 8; j++) bvl[j] = ((const uint4*)BpL)[j];
        ApH += 64; ApL += 64; BpH += 64; BpL += 64;

        if (i >= 2) mbar_wait(s ? mbar1 : mbar0, ((i >> 1) - 1) & 1);

#pragma unroll
        for (int j = 0; j < 4; j++) {
            uint32_t o = SW128(aoff + j * 16);
            *(uint4*)(smem + stage_off + o)         = avh[j];
            *(uint4*)(smem + stage_off + 16384 + o) = avl[j];
        }
#pragma unroll
        for (int j = 0; j < 8; j++) {
            uint32_t o = SW128(boff + j * 16);
            *(uint4*)(smem + stage_off + 32768 + o) = bvh[j];
            *(uint4*)(smem + stage_off + 65536 + o) = bvl[j];
        }
        asm volatile("fence.proxy.async.shared::cta;" ::: "memory");
        __syncthreads();

        if (wid == 0 && elect1()) {
            const uint64_t ah = mkdesc(stage_abs);
            const uint64_t al = mkdesc(stage_abs + 16384);
            const uint64_t bh = mkdesc(stage_abs + 32768);
            const uint64_t bl = mkdesc(stage_abs + 65536);
#pragma unroll
            for (int k = 0; k < 4; k++)
                mma_bf16_ss(tmem, ah + k * 2, bh + k * 2, (i > 0 || k > 0) ? 1u : 0u);
#pragma unroll
            for (int k = 0; k < 4; k++)
                mma_bf16_ss(tmem, ah + k * 2, bl + k * 2, 1u);
#pragma unroll
            for (int k = 0; k < 4; k++)
                mma_bf16_ss(tmem, al + k * 2, bh + k * 2, 1u);
            tc_commit(s ? mbar1 : mbar0);
        }
    }

    {
        const int il = nchunk - 1, s = il & 1;
        mbar_wait(s ? mbar1 : mbar0, ((il >> 1) & 1));
    }
    asm volatile("tcgen05.fence::after_thread_sync;" ::: "memory");

    const int sub  = wid & 3;
    const int half = wid >> 2;
    const int row  = bm + sub * 32 + lane;
    const float* rrow = resid ? resid + (size_t)row * N : nullptr;
    float* crow = C + (size_t)row * N;
#pragma unroll 1
    for (int c32 = 0; c32 < 4; c32++) {
        uint32_t d[32];
        ldtm32(d, tmem + half * 128 + c32 * 32);
        asm volatile("tcgen05.wait::ld.sync.aligned;" ::: "memory");
        const int col0 = bn + half * 128 + c32 * 32;
        if (rrow) {
#pragma unroll
            for (int j = 0; j < 32; j++)
                crow[col0 + j] = __uint_as_float(d[j]) + bias[col0 + j] + rrow[col0 + j];
        } else {
#pragma unroll
            for (int j = 0; j < 32; j++)
                crow[col0 + j] = __uint_as_float(d[j]) + bias[col0 + j];
        }
    }
    __syncthreads();
    if (wid == 0) {
        asm volatile("tcgen05.dealloc.cta_group::1.sync.aligned.b32 %0, %1;"
                     :: "r"(tmem), "r"(256u));
    }
#else
    // ---------- baseline-PTX fallback: SIMT, reconstruct fp32 = hi + lo ----------
    float* As = (float*)smem;            // [8][128]
    float* Bs = As + 8 * 128;            // [8][128]
    const int tid = threadIdx.x;
    const int bm = blockIdx.y * 128;
    const int lr  = tid >> 1;
    const int lcc = (tid & 1) * 4;
    const int tx = tid & 15, ty = tid >> 4;

    for (int h = 0; h < 2; h++) {
        const int bn = blockIdx.x * 256 + h * 128;
        float acc[8][8];
#pragma unroll
        for (int i = 0; i < 8; i++)
#pragma unroll
            for (int j = 0; j < 8; j++) acc[i][j] = 0.f;

        for (int k0 = 0; k0 < K; k0 += 8) {
            const __nv_bfloat16* aph = Ah + (size_t)(bm + lr) * K + k0 + lcc;
            const __nv_bfloat16* apl = Al + (size_t)(bm + lr) * K + k0 + lcc;
            const __nv_bfloat16* bph = Bh + (size_t)(bn + lr) * K + k0 + lcc;
            const __nv_bfloat16* bpl = Bl + (size_t)(bn + lr) * K + k0 + lcc;
#pragma unroll
            for (int j = 0; j < 4; j++) {
                As[(lcc + j) * 128 + lr] = __bfloat162float(aph[j]) + __bfloat162float(apl[j]);
                Bs[(lcc + j) * 128 + lr] = __bfloat162float(bph[j]) + __bfloat162float(bpl[j]);
            }
            __syncthreads();
#pragma unroll
            for (int kk = 0; kk < 8; kk++) {
                float a[8], bb[8];
#pragma unroll
                for (int i = 0; i < 8; i++)
                    a[i] = As[kk * 128 + ((i & 4) << 4) + ty * 4 + (i & 3)];
#pragma unroll
                for (int j = 0; j < 8; j++)
                    bb[j] = Bs[kk * 128 + ((j & 4) << 4) + tx * 4 + (j & 3)];
#pragma unroll
                for (int i = 0; i < 8; i++)
#pragma unroll
                    for (int j = 0; j < 8; j++)
                        acc[i][j] += a[i] * bb[j];
            }
            __syncthreads();
        }

#pragma unroll
        for (int i = 0; i < 8; i++) {
            const int row = bm + ((i & 4) << 4) + ty * 4 + (i & 3);
#pragma unroll
            for (int j = 0; j < 8; j++) {
                const int col = bn + ((j & 4) << 4) + tx * 4 + (j & 3);
                float vv = acc[i][j] + bias[col];
                if (resid) vv += resid[(size_t)row * N + col];
                C[(size_t)row * N + col] = vv;
            }
        }
    }
#endif
}

// ---------------- LayerNorm ----------------
__global__ void __launch_bounds__(256) ln_kernel(const float* __restrict__ x,
                                                 const float* __restrict__ g,
                                                 const float* __restrict__ b,
                                                 float* __restrict__ out)
{
    const int row = blockIdx.x;
    const int tid = threadIdx.x;
    const float* xr = x + (size_t)row * Dd;
    __shared__ float red[256];

    float s = 0.f;
    for (int i = tid; i < Dd; i += 256) s += xr[i];
    red[tid] = s; __syncthreads();
    for (int off = 128; off > 0; off >>= 1) {
        if (tid < off) red[tid] += red[tid + off];
        __syncthreads();
    }
    const float mean = red[0] * (1.f / Dd);
    __syncthreads();

    float v = 0.f;
    for (int i = tid; i < Dd; i += 256) { float d = xr[i] - mean; v += d * d; }
    red[tid] = v; __syncthreads();
    for (int off = 128; off > 0; off >>= 1) {
        if (tid < off) red[tid] += red[tid + off];
        __syncthreads();
    }
    const float rstd = rsqrtf(red[0] * (1.f / Dd) + 1e-5f);

    float* orow = out + (size_t)row * Dd;
    for (int i = tid; i < Dd; i += 256)
        orow[i] = (xr[i] - mean) * rstd * g[i] + b[i];
}

// ---------------- RoPE (head-indexed freqs, faithful to reference) ----------------
__global__ void rope_kernel(float* __restrict__ q, float* __restrict__ k,
                            const float* __restrict__ fr)
{
    const int idx = blockIdx.x * blockDim.x + threadIdx.x;
    const int j  = idx & 63;
    const int h  = (idx >> 6) & 15;
    const int bt = idx >> 10;
    const size_t base = (size_t)bt * Dd + h * HDd + 2 * j;
    const float cr = fr[h * 128 + 2 * j];
    const float ci = fr[h * 128 + 2 * j + 1];
    float a = q[base], b2 = q[base + 1];
    q[base]     = a * cr - b2 * ci;
    q[base + 1] = a * ci + b2 * cr;
    a = k[base]; b2 = k[base + 1];
    k[base]     = a * cr - b2 * ci;
    k[base + 1] = a * ci + b2 * cr;
}

// ---------------- Flash attention, causal, fp32, HD=128 ----------------
__global__ void __launch_bounds__(256) flash_kernel(const float* __restrict__ Q,
                                                    const float* __restrict__ K,
                                                    const float* __restrict__ V,
                                                    float* __restrict__ Out)
{
    extern __shared__ float sm[];
    float* sQ = sm;
    float* sK = sm + 64 * 128;
    float* sV = sm + 2 * 64 * 128;
    float* sP = sm + 3 * 64 * 128;

    const int tid = threadIdx.x;
    const int qb = blockIdx.x, h = blockIdx.y, b = blockIdx.z;
    const int q0 = qb * 64;
    const size_t qbase = ((size_t)(b * Tt + q0)) * Dd + h * HDd;

#pragma unroll
    for (int it = 0; it < 8; it++) {
        int f = tid + it * 256;
        int r = f >> 5, c = f & 31;
        *(float4*)(sQ + r * 128 + c * 4) =
            *(const float4*)(Q + qbase + (size_t)r * Dd + c * 4);
    }

    const int qi = tid >> 2;
    const int lc = tid & 3;
    const int rp = ((tid >> 2) + 2 * lc) & 7;
    const int dbase = lc * 32;
    const float scale = 0.088388347648318447f;

    float4 O[8];
#pragma unroll
    for (int i = 0; i < 8; i++) O[i] = make_float4(0.f, 0.f, 0.f, 0.f);
    float mrow = -1e30f, lrow = 0.f;

    for (int kb = 0; kb <= qb; kb++) {
        const int j0 = kb * 64;
        const size_t kbase = ((size_t)(b * Tt + j0)) * Dd + h * HDd;
#pragma unroll
        for (int it = 0; it < 8; it++) {
            int f = tid + it * 256;
            int r = f >> 5, c = f & 31;
            *(float4*)(sK + r * 128 + c * 4) =
                *(const float4*)(K + kbase + (size_t)r * Dd + c * 4);
            *(float4*)(sV + r * 128 + c * 4) =
                *(const float4*)(V + kbase + (size_t)r * Dd + c * 4);
        }
        __syncthreads();

        float acc[16];
#pragma unroll
        for (int kk = 0; kk < 16; kk++) acc[kk] = 0.f;

#pragma unroll
        for (int ch = 0; ch < 4; ch++) {
            float4 qreg[8];
#pragma unroll
            for (int i = 0; i < 8; i++) {
                int g = (i + rp) & 7;
                qreg[i] = *(const float4*)(sQ + qi * 128 + ch * 32 + g * 4);
            }
#pragma unroll
            for (int kk = 0; kk < 16; kk++) {
                const float* kr = sK + (lc * 16 + kk) * 128 + ch * 32;
                float s = 0.f;
#pragma unroll
                for (int i = 0; i < 8; i++) {
                    int g = (i + rp) & 7;
                    float4 kv = *(const float4*)(kr + g * 4);
                    s += qreg[i].x * kv.x + qreg[i].y * kv.y
                       + qreg[i].z * kv.z + qreg[i].w * kv.w;
                }
                acc[kk] += s;
            }
        }

        float tmax = -1e30f;
#pragma unroll
        for (int kk = 0; kk < 16; kk++) {
            float s = acc[kk] * scale;
            if (j0 + lc * 16 + kk > q0 + qi) s = -1e30f;
            acc[kk] = s;
            tmax = fmaxf(tmax, s);
        }
        tmax = fmaxf(tmax, __shfl_xor_sync(0xffffffffu, tmax, 1));
        tmax = fmaxf(tmax, __shfl_xor_sync(0xffffffffu, tmax, 2));
        const float mnew = fmaxf(mrow, tmax);
        const float alpha = __expf(mrow - mnew);
        mrow = mnew;

        float psum = 0.f;
#pragma unroll
        for (int kk = 0; kk < 16; kk++) {
            float p = __expf(acc[kk] - mnew);
            psum += p;
            sP[qi * 68 + lc * 16 + kk] = p;
        }
        psum += __shfl_xor_sync(0xffffffffu, psum, 1);
        psum += __shfl_xor_sync(0xffffffffu, psum, 2);
        lrow = lrow * alpha + psum;
#pragma unroll
        for (int i = 0; i < 8; i++) {
            O[i].x *= alpha; O[i].y *= alpha; O[i].z *= alpha; O[i].w *= alpha;
        }
        __syncthreads();

#pragma unroll 4
        for (int k2 = 0; k2 < 64; k2++) {
            const float pv = sP[qi * 68 + k2];
            const float* vr = sV + k2 * 128 + dbase;
#pragma unroll
            for (int i = 0; i < 8; i++) {
                int g = (i + rp) & 7;
                float4 vv = *(const float4*)(vr + g * 4);
                O[i].x += pv * vv.x; O[i].y += pv * vv.y;
                O[i].z += pv * vv.z; O[i].w += pv * vv.w;
            }
        }
        __syncthreads();
    }

    const float inv = 1.f / lrow;
    const size_t obase = ((size_t)(b * Tt + q0 + qi)) * Dd + h * HDd + dbase;
#pragma unroll
    for (int i = 0; i < 8; i++) {
        int g = (i + rp) & 7;
        float4 o = O[i];
        o.x *= inv; o.y *= inv; o.z *= inv; o.w *= inv;
        *(float4*)(Out + obase + g * 4) = o;
    }
}

// ---------------- fused SiLU(gate)*up ----------------
__global__ void silu_mul_kernel(float* __restrict__ gbuf, const float* __restrict__ ubuf)
{
    const int idx = blockIdx.x * blockDim.x + threadIdx.x;
    const float gt = gbuf[idx];
    const float s = gt / (1.f + __expf(-gt));
    gbuf[idx] = s * ubuf[idx];
}

// ---------------- launch ----------------
extern "C" void kernel_launch(void* const* d_in, const int* in_sizes, int n_in,
                              void* d_out, int out_size)
{
    const float* x   = (const float*)d_in[0];
    const float* fr  = (const float*)d_in[1];
    const float* Wq  = (const float*)d_in[2];
    const float* bq  = (const float*)d_in[3];
    const float* Wk  = (const float*)d_in[4];
    const float* bk  = (const float*)d_in[5];
    const float* Wv  = (const float*)d_in[6];
    const float* bv  = (const float*)d_in[7];
    const float* Wo  = (const float*)d_in[8];
    const float* bo  = (const float*)d_in[9];
    const float* g1  = (const float*)d_in[10];
    const float* be1 = (const float*)d_in[11];
    const float* g2  = (const float*)d_in[12];
    const float* be2 = (const float*)d_in[13];
    const float* Wg  = (const float*)d_in[14];
    const float* bg  = (const float*)d_in[15];
    const float* Wu  = (const float*)d_in[16];
    const float* bu  = (const float*)d_in[17];
    const float* Wd  = (const float*)d_in[18];
    const float* bd  = (const float*)d_in[19];
    float* out = (float*)d_out;

    float *xn, *q, *k, *v, *attn, *ff1, *ff2;
    __nv_bfloat16 *Ahi, *Alo, *Bhi, *Blo;
    cudaGetSymbolAddress((void**)&xn,   g_xn);
    cudaGetSymbolAddress((void**)&q,    g_q);
    cudaGetSymbolAddress((void**)&k,    g_k);
    cudaGetSymbolAddress((void**)&v,    g_v);
    cudaGetSymbolAddress((void**)&attn, g_attn);
    cudaGetSymbolAddress((void**)&ff1,  g_ff1);
    cudaGetSymbolAddress((void**)&ff2,  g_ff2);
    cudaGetSymbolAddress((void**)&Ahi,  g_Ahi);
    cudaGetSymbolAddress((void**)&Alo,  g_Alo);
    cudaGetSymbolAddress((void**)&Bhi,  g_Bhi);
    cudaGetSymbolAddress((void**)&Blo,  g_Blo);

    const int smemF = (3 * 64 * 128 + 64 * 68) * (int)sizeof(float);   // 113 KB
    cudaFuncSetAttribute(flash_kernel, cudaFuncAttributeMaxDynamicSharedMemorySize, smemF);
    cudaFuncSetAttribute(mma_gemm_kernel, cudaFuncAttributeMaxDynamicSharedMemorySize, GEMM_SMEM);

    const int DD  = ROWS * Dd;   // 8M
    const int DW  = Dd * Dd;     // 4M
    const int FW  = FFd * Dd;    // 16M
    const int DF  = ROWS * FFd;  // 32M

#define SPLIT(src, hi, lo, n) split_kernel<<<((n)/4 + 255)/256, 256>>>(src, hi, lo, (n)/4)

    // 1) LN1
    ln_kernel<<<ROWS, 256>>>(x, g1, be1, xn);

    // 2) Q,K,V projections
    SPLIT(xn, Ahi, Alo, DD);
    dim3 gD(Dd / 256, ROWS / 128);
    SPLIT(Wq, Bhi, Blo, DW);
    mma_gemm_kernel<<<gD, 256, GEMM_SMEM>>>(Ahi, Alo, Bhi, Blo, bq, nullptr, q, ROWS, Dd, Dd);
    SPLIT(Wk, Bhi, Blo, DW);
    mma_gemm_kernel<<<gD, 256, GEMM_SMEM>>>(Ahi, Alo, Bhi, Blo, bk, nullptr, k, ROWS, Dd, Dd);
    SPLIT(Wv, Bhi, Blo, DW);
    mma_gemm_kernel<<<gD, 256, GEMM_SMEM>>>(Ahi, Alo, Bhi, Blo, bv, nullptr, v, ROWS, Dd, Dd);

    // 3) RoPE
    rope_kernel<<<(Bb * Tt * Hh * (HDd / 2)) / 256, 256>>>(q, k, fr);

    // 4) causal flash attention
    flash_kernel<<<dim3(Tt / 64, Hh, Bb), 256, smemF>>>(q, k, v, attn);

    // 5) output projection + residual(x) -> out
    SPLIT(attn, Ahi, Alo, DD);
    SPLIT(Wo, Bhi, Blo, DW);
    mma_gemm_kernel<<<gD, 256, GEMM_SMEM>>>(Ahi, Alo, Bhi, Blo, bo, x, out, ROWS, Dd, Dd);

    // 6) LN2
    ln_kernel<<<ROWS, 256>>>(out, g2, be2, xn);

    // 7) gate / up
    SPLIT(xn, Ahi, Alo, DD);
    dim3 gF(FFd / 256, ROWS / 128);
    SPLIT(Wg, Bhi, Blo, FW);
    mma_gemm_kernel<<<gF, 256, GEMM_SMEM>>>(Ahi, Alo, Bhi, Blo, bg, nullptr, ff1, ROWS, FFd, Dd);
    SPLIT(Wu, Bhi, Blo, FW);
    mma_gemm_kernel<<<gF, 256, GEMM_SMEM>>>(Ahi, Alo, Bhi, Blo, bu, nullptr, ff2, ROWS, FFd, Dd);

    // 8) SiLU(gate)*up
    silu_mul_kernel<<<(ROWS * FFd) / 256, 256>>>(ff1, ff2);

    // 9) down projection + residual(out) -> out
    SPLIT(ff1, Ahi, Alo, DF);
    SPLIT(Wd, Bhi, Blo, FW);
    mma_gemm_kernel<<<gD, 256, GEMM_SMEM>>>(Ahi, Alo, Bhi, Blo, bd, out, out, ROWS, Dd, FFd);
}

// round 6
// speedup vs baseline: 2.2986x; 1.0296x over previous
#include <cuda_runtime.h>
#include <cuda_bf16.h>
#include <cstdint>
#include <math.h>

#define Bb 2
#define Tt 2048
#define Dd 2048
#define Hh 16
#define HDd 128
#define FFd 8192
#define ROWS (Bb*Tt)   /* 4096 */

// tcgen05 only exists in arch-specific (sm_10xa) compilation phases.
#if defined(__CUDA_ARCH_FEAT_SM103_ALL) || defined(__CUDA_ARCH_FEAT_SM100_ALL) || \
    defined(__CUDA_ARCH_FEAT_SM101_ALL) || \
    (defined(__CUDA_ARCH_SPECIFIC__) && (__CUDA_ARCH_SPECIFIC__ >= 1000)) || \
    (defined(__CUDA_ARCH_FAMILY_SPECIFIC__) && (__CUDA_ARCH_FAMILY_SPECIFIC__ >= 1000))
#define HAS_TCGEN05 1
#else
#define HAS_TCGEN05 0
#endif

// ---------------- scratch (no allocations allowed -> device globals) ----------------
__device__ float g_xn  [ROWS*Dd];
__device__ float g_q   [ROWS*Dd];
__device__ float g_k   [ROWS*Dd];
__device__ float g_v   [ROWS*Dd];
__device__ float g_attn[ROWS*Dd];
__device__ float g_ff1 [ROWS*FFd];
__device__ float g_ff2 [ROWS*FFd];
// bf16 split buffers
__device__ __nv_bfloat16 g_Ahi[ROWS*FFd];
__device__ __nv_bfloat16 g_Alo[ROWS*FFd];
__device__ __nv_bfloat16 g_Bhi[FFd*Dd];
__device__ __nv_bfloat16 g_Blo[FFd*Dd];

// ================= tcgen05 helpers =================
__device__ __forceinline__ uint32_t smem_u32(const void* p) {
    uint32_t a;
    asm("{ .reg .u64 t; cvta.to.shared.u64 t, %1; cvt.u32.u64 %0, t; }"
        : "=r"(a) : "l"(p));
    return a;
}

#define SW128(o) ((o) ^ (((o) >> 3) & 0x70))

static constexpr uint64_t DESC_BASE_SW128 =
    (uint64_t(2)  << 61) | (uint64_t(1) << 46) | (uint64_t(64) << 32) | (uint64_t(1) << 16);

// idesc: dtype=F32(1<<4), atype=BF16(1<<7), btype=BF16(1<<10), N=256 (32<<17), M=128 (8<<24)
#define MMA_IDESC 0x8400490u

#if HAS_TCGEN05
__device__ __forceinline__ uint32_t elect1() {
    uint32_t p;
    asm volatile("{\n\t.reg .pred p;\n\telect.sync _|p, 0xFFFFFFFF;\n\tselp.b32 %0,1,0,p;\n\t}"
                 : "=r"(p));
    return p;
}
__device__ __forceinline__ uint64_t mkdesc(uint32_t addr) {
    return DESC_BASE_SW128 | ((uint64_t)(addr >> 4) & 0x3FFF);
}
__device__ __forceinline__ void mma_bf16_ss(uint32_t d, uint64_t ad, uint64_t bd, uint32_t en) {
    asm volatile(
        "{\n\t.reg .pred p;\n\tsetp.ne.u32 p, %4, 0;\n\t"
        "tcgen05.mma.cta_group::1.kind::f16 [%0], %1, %2, %3, {%5,%5,%5,%5}, p;\n\t}"
        :: "r"(d), "l"(ad), "l"(bd), "r"(MMA_IDESC), "r"(en), "r"(0u) : "memory");
}
__device__ __forceinline__ void mbar_init(uint32_t m, uint32_t cnt) {
    asm volatile("mbarrier.init.shared.b64 [%0], %1;" :: "r"(m), "r"(cnt) : "memory");
}
__device__ __forceinline__ void mbar_wait(uint32_t m, uint32_t parity) {
    asm volatile(
        "{\n\t.reg .pred P1;\n"
        "W%=:\n\t"
        "mbarrier.try_wait.parity.acquire.cta.shared::cta.b64 P1, [%0], %1, 0x989680;\n\t"
        "@P1 bra.uni D%=;\n\t"
        "bra.uni W%=;\n"
        "D%=:\n\t}"
        :: "r"(m), "r"(parity) : "memory");
}
__device__ __forceinline__ void tc_commit(uint32_t m) {
    asm volatile("tcgen05.commit.cta_group::1.mbarrier::arrive::one.shared::cluster.b64 [%0];"
                 :: "r"(m) : "memory");
}
__device__ __forceinline__ void ldtm32(uint32_t* r, uint32_t a) {
    asm volatile(
        "tcgen05.ld.sync.aligned.32x32b.x32.b32 "
        "{%0,%1,%2,%3,%4,%5,%6,%7,%8,%9,%10,%11,%12,%13,%14,%15,"
        "%16,%17,%18,%19,%20,%21,%22,%23,%24,%25,%26,%27,%28,%29,%30,%31}, [%32];"
        : "=r"(r[0]),"=r"(r[1]),"=r"(r[2]),"=r"(r[3]),"=r"(r[4]),"=r"(r[5]),"=r"(r[6]),"=r"(r[7]),
          "=r"(r[8]),"=r"(r[9]),"=r"(r[10]),"=r"(r[11]),"=r"(r[12]),"=r"(r[13]),"=r"(r[14]),"=r"(r[15]),
          "=r"(r[16]),"=r"(r[17]),"=r"(r[18]),"=r"(r[19]),"=r"(r[20]),"=r"(r[21]),"=r"(r[22]),"=r"(r[23]),
          "=r"(r[24]),"=r"(r[25]),"=r"(r[26]),"=r"(r[27]),"=r"(r[28]),"=r"(r[29]),"=r"(r[30]),"=r"(r[31])
        : "r"(a));
}
__device__ __forceinline__ void cpasync16(uint32_t dst, const void* src) {
    asm volatile("cp.async.cg.shared.global [%0], [%1], 16;" :: "r"(dst), "l"(src) : "memory");
}
#define CP_COMMIT() asm volatile("cp.async.commit_group;" ::: "memory")
#define CP_WAIT1()  asm volatile("cp.async.wait_group 1;" ::: "memory")
#endif  // HAS_TCGEN05

// ---------------- split fp32 -> bf16 hi/lo ----------------
__global__ void __launch_bounds__(256) split_kernel(const float* __restrict__ src,
                                                    __nv_bfloat16* __restrict__ hi,
                                                    __nv_bfloat16* __restrict__ lo,
                                                    int n4)
{
    int idx = blockIdx.x * blockDim.x + threadIdx.x;
    if (idx >= n4) return;
    float4 v = ((const float4*)src)[idx];
    __nv_bfloat162 h0 = __floats2bfloat162_rn(v.x, v.y);
    __nv_bfloat162 h1 = __floats2bfloat162_rn(v.z, v.w);
    float lx = v.x - __bfloat162float(__low2bfloat16(h0));
    float ly = v.y - __bfloat162float(__high2bfloat16(h0));
    float lz = v.z - __bfloat162float(__low2bfloat16(h1));
    float lw = v.w - __bfloat162float(__high2bfloat16(h1));
    __nv_bfloat162 l0 = __floats2bfloat162_rn(lx, ly);
    __nv_bfloat162 l1 = __floats2bfloat162_rn(lz, lw);
    uint2 ho, loo;
    ho.x  = *reinterpret_cast<uint32_t*>(&h0);
    ho.y  = *reinterpret_cast<uint32_t*>(&h1);
    loo.x = *reinterpret_cast<uint32_t*>(&l0);
    loo.y = *reinterpret_cast<uint32_t*>(&l1);
    ((uint2*)hi)[idx] = ho;
    ((uint2*)lo)[idx] = loo;
}

// ============ GEMM: C[m,n] = sum_k A[m,k]*B[n,k] + bias[n] (+resid), pre-split bf16 ============
// BM=128, BN=256, BK=64, 2-stage cp.async pipeline. Ah/Al: MxK bf16, Bh/Bl: NxK bf16.
#define STAGE_BYTES 98304   /* A_hi 16K | A_lo 16K | B_hi 32K | B_lo 32K */
#define GEMM_SMEM (2 * STAGE_BYTES + 2048)

__global__ void __launch_bounds__(256, 1)
mma_gemm_kernel(const __nv_bfloat16* __restrict__ Ah, const __nv_bfloat16* __restrict__ Al,
                const __nv_bfloat16* __restrict__ Bh, const __nv_bfloat16* __restrict__ Bl,
                const float* __restrict__ bias, const float* __restrict__ resid,
                float* __restrict__ C, int M, int N, int K)
{
    extern __shared__ char smem[];
#if HAS_TCGEN05
    const uint32_t sbase = smem_u32(smem);
    const int tid  = threadIdx.x;
    const int wid  = tid >> 5;
    const int lane = tid & 31;
    const int bn = blockIdx.x * 256;
    const int bm = blockIdx.y * 128;

    const uint32_t tile_abs = (sbase + 32 + 1023) & ~1023u;
    const uint32_t mbar0 = sbase + 8;
    const uint32_t mbar1 = sbase + 16;

    if (wid == 0) {
        asm volatile("tcgen05.alloc.cta_group::1.sync.aligned.shared::cta.b32 [%0], %1;"
                     :: "r"(sbase), "r"(256u) : "memory");
        asm volatile("tcgen05.relinquish_alloc_permit.cta_group::1.sync.aligned;");
    }
    if (tid == 0) { mbar_init(mbar0, 1); mbar_init(mbar1, 1); }
    __syncthreads();
    uint32_t tmem;
    asm volatile("ld.shared.b32 %0, [%1];" : "=r"(tmem) : "r"(sbase));

    // producer mapping (per stage 96KB, 384B per thread = 24 x 16B cp.async):
    // A: 128 rows x 128B; thread t -> row t>>1, 64B half (t&1): 4 x 16B per operand.
    // B: 256 rows x 128B; thread t -> row t: 8 x 16B per operand.
    const int arow  = tid >> 1;
    const int asel  = tid & 1;
    const uint32_t aoffb = arow * 128 + asel * 64;   // byte offset within A tile
    const uint32_t boffb = tid * 128;                // byte offset within B tile
    const __nv_bfloat16* AgH = Ah + (size_t)(bm + arow) * K + asel * 32;
    const __nv_bfloat16* AgL = Al + (size_t)(bm + arow) * K + asel * 32;
    const __nv_bfloat16* BgH = Bh + (size_t)(bn + tid) * K;
    const __nv_bfloat16* BgL = Bl + (size_t)(bn + tid) * K;

    const int n = K >> 6;   // 64-wide K chunks

    // issue cp.async for chunk c into stage c&1
    auto issue = [&](int c) {
        const uint32_t sb = tile_abs + (c & 1) * STAGE_BYTES;
        const size_t kof = (size_t)c * 64;
#pragma unroll
        for (int j = 0; j < 4; j++) {
            uint32_t o = SW128(aoffb + j * 16);
            cpasync16(sb + o,         AgH + kof + j * 8);
            cpasync16(sb + 16384 + o, AgL + kof + j * 8);
        }
#pragma unroll
        for (int j = 0; j < 8; j++) {
            uint32_t o = SW128(boffb + j * 16);
            cpasync16(sb + 32768 + o, BgH + kof + j * 8);
            cpasync16(sb + 65536 + o, BgL + kof + j * 8);
        }
    };

    // prologue: chunk 0 in flight
    issue(0);
    CP_COMMIT();

    for (int i = 0; i < n; i++) {
        const int s = i & 1;

        // prefetch chunk i+1 into the other stage (after its previous MMA user completes)
        if (i + 1 < n) {
            if (i >= 1) mbar_wait(s ? mbar0 : mbar1, ((i - 1) >> 1) & 1);
            issue(i + 1);
        }
        CP_COMMIT();           // always commit (possibly empty) to keep group counting fixed

        CP_WAIT1();            // chunk i's data has landed
        asm volatile("fence.proxy.async.shared::cta;" ::: "memory");
        __syncthreads();

        if (wid == 0 && elect1()) {
            const uint32_t sb = tile_abs + s * STAGE_BYTES;
            const uint64_t ah = mkdesc(sb);
            const uint64_t al = mkdesc(sb + 16384);
            const uint64_t bh = mkdesc(sb + 32768);
            const uint64_t bl = mkdesc(sb + 65536);
#pragma unroll
            for (int k = 0; k < 4; k++)
                mma_bf16_ss(tmem, ah + k * 2, bh + k * 2, (i > 0 || k > 0) ? 1u : 0u);
#pragma unroll
            for (int k = 0; k < 4; k++)
                mma_bf16_ss(tmem, ah + k * 2, bl + k * 2, 1u);
#pragma unroll
            for (int k = 0; k < 4; k++)
                mma_bf16_ss(tmem, al + k * 2, bh + k * 2, 1u);
            tc_commit(s ? mbar1 : mbar0);
        }
    }

    // wait for the final chunk's MMA
    {
        const int il = n - 1, s = il & 1;
        mbar_wait(s ? mbar1 : mbar0, (il >> 1) & 1);
    }
    asm volatile("tcgen05.fence::after_thread_sync;" ::: "memory");

    // epilogue: warp w -> rows (w&3)*32..+31, col half (w>>2)*128
    const int sub  = wid & 3;
    const int half = wid >> 2;
    const int row  = bm + sub * 32 + lane;
    const float* rrow = resid ? resid + (size_t)row * N : nullptr;
    float* crow = C + (size_t)row * N;
#pragma unroll 1
    for (int c32 = 0; c32 < 4; c32++) {
        uint32_t d[32];
        ldtm32(d, tmem + half * 128 + c32 * 32);
        asm volatile("tcgen05.wait::ld.sync.aligned;" ::: "memory");
        const int col0 = bn + half * 128 + c32 * 32;
        if (rrow) {
#pragma unroll
            for (int j = 0; j < 32; j++)
                crow[col0 + j] = __uint_as_float(d[j]) + bias[col0 + j] + rrow[col0 + j];
        } else {
#pragma unroll
            for (int j = 0; j < 32; j++)
                crow[col0 + j] = __uint_as_float(d[j]) + bias[col0 + j];
        }
    }
    __syncthreads();
    if (wid == 0) {
        asm volatile("tcgen05.dealloc.cta_group::1.sync.aligned.b32 %0, %1;"
                     :: "r"(tmem), "r"(256u));
    }
#else
    // ---------- baseline-PTX fallback: SIMT, reconstruct fp32 = hi + lo ----------
    float* As = (float*)smem;            // [8][128]
    float* Bs = As + 8 * 128;            // [8][128]
    const int tid = threadIdx.x;
    const int bm = blockIdx.y * 128;
    const int lr  = tid >> 1;
    const int lcc = (tid & 1) * 4;
    const int tx = tid & 15, ty = tid >> 4;

    for (int h = 0; h < 2; h++) {
        const int bn = blockIdx.x * 256 + h * 128;
        float acc[8][8];
#pragma unroll
        for (int i = 0; i < 8; i++)
#pragma unroll
            for (int j = 0; j < 8; j++) acc[i][j] = 0.f;

        for (int k0 = 0; k0 < K; k0 += 8) {
            const __nv_bfloat16* aph = Ah + (size_t)(bm + lr) * K + k0 + lcc;
            const __nv_bfloat16* apl = Al + (size_t)(bm + lr) * K + k0 + lcc;
            const __nv_bfloat16* bph = Bh + (size_t)(bn + lr) * K + k0 + lcc;
            const __nv_bfloat16* bpl = Bl + (size_t)(bn + lr) * K + k0 + lcc;
#pragma unroll
            for (int j = 0; j < 4; j++) {
                As[(lcc + j) * 128 + lr] = __bfloat162float(aph[j]) + __bfloat162float(apl[j]);
                Bs[(lcc + j) * 128 + lr] = __bfloat162float(bph[j]) + __bfloat162float(bpl[j]);
            }
            __syncthreads();
#pragma unroll
            for (int kk = 0; kk < 8; kk++) {
                float a[8], bb[8];
#pragma unroll
                for (int i = 0; i < 8; i++)
                    a[i] = As[kk * 128 + ((i & 4) << 4) + ty * 4 + (i & 3)];
#pragma unroll
                for (int j = 0; j < 8; j++)
                    bb[j] = Bs[kk * 128 + ((j & 4) << 4) + tx * 4 + (j & 3)];
#pragma unroll
                for (int i = 0; i < 8; i++)
#pragma unroll
                    for (int j = 0; j < 8; j++)
                        acc[i][j] += a[i] * bb[j];
            }
            __syncthreads();
        }

#pragma unroll
        for (int i = 0; i < 8; i++) {
            const int row = bm + ((i & 4) << 4) + ty * 4 + (i & 3);
#pragma unroll
            for (int j = 0; j < 8; j++) {
                const int col = bn + ((j & 4) << 4) + tx * 4 + (j & 3);
                float vv = acc[i][j] + bias[col];
                if (resid) vv += resid[(size_t)row * N + col];
                C[(size_t)row * N + col] = vv;
            }
        }
    }
#endif
}

// ---------------- LayerNorm ----------------
__global__ void __launch_bounds__(256) ln_kernel(const float* __restrict__ x,
                                                 const float* __restrict__ g,
                                                 const float* __restrict__ b,
                                                 float* __restrict__ out)
{
    const int row = blockIdx.x;
    const int tid = threadIdx.x;
    const float* xr = x + (size_t)row * Dd;
    __shared__ float red[256];

    float s = 0.f;
    for (int i = tid; i < Dd; i += 256) s += xr[i];
    red[tid] = s; __syncthreads();
    for (int off = 128; off > 0; off >>= 1) {
        if (tid < off) red[tid] += red[tid + off];
        __syncthreads();
    }
    const float mean = red[0] * (1.f / Dd);
    __syncthreads();

    float v = 0.f;
    for (int i = tid; i < Dd; i += 256) { float d = xr[i] - mean; v += d * d; }
    red[tid] = v; __syncthreads();
    for (int off = 128; off > 0; off >>= 1) {
        if (tid < off) red[tid] += red[tid + off];
        __syncthreads();
    }
    const float rstd = rsqrtf(red[0] * (1.f / Dd) + 1e-5f);

    float* orow = out + (size_t)row * Dd;
    for (int i = tid; i < Dd; i += 256)
        orow[i] = (xr[i] - mean) * rstd * g[i] + b[i];
}

// ---------------- RoPE (head-indexed freqs, faithful to reference) ----------------
__global__ void rope_kernel(float* __restrict__ q, float* __restrict__ k,
                            const float* __restrict__ fr)
{
    const int idx = blockIdx.x * blockDim.x + threadIdx.x;
    const int j  = idx & 63;
    const int h  = (idx >> 6) & 15;
    const int bt = idx >> 10;
    const size_t base = (size_t)bt * Dd + h * HDd + 2 * j;
    const float cr = fr[h * 128 + 2 * j];
    const float ci = fr[h * 128 + 2 * j + 1];
    float a = q[base], b2 = q[base + 1];
    q[base]     = a * cr - b2 * ci;
    q[base + 1] = a * ci + b2 * cr;
    a = k[base]; b2 = k[base + 1];
    k[base]     = a * cr - b2 * ci;
    k[base + 1] = a * ci + b2 * cr;
}

// ---------------- Flash attention, causal, fp32, HD=128 ----------------
__global__ void __launch_bounds__(256) flash_kernel(const float* __restrict__ Q,
                                                    const float* __restrict__ K,
                                                    const float* __restrict__ V,
                                                    float* __restrict__ Out)
{
    extern __shared__ float sm[];
    float* sQ = sm;
    float* sK = sm + 64 * 128;
    float* sV = sm + 2 * 64 * 128;
    float* sP = sm + 3 * 64 * 128;

    const int tid = threadIdx.x;
    const int qb = blockIdx.x, h = blockIdx.y, b = blockIdx.z;
    const int q0 = qb * 64;
    const size_t qbase = ((size_t)(b * Tt + q0)) * Dd + h * HDd;

#pragma unroll
    for (int it = 0; it < 8; it++) {
        int f = tid + it * 256;
        int r = f >> 5, c = f & 31;
        *(float4*)(sQ + r * 128 + c * 4) =
            *(const float4*)(Q + qbase + (size_t)r * Dd + c * 4);
    }

    const int qi = tid >> 2;
    const int lc = tid & 3;
    const int rp = ((tid >> 2) + 2 * lc) & 7;
    const int dbase = lc * 32;
    const float scale = 0.088388347648318447f;

    float4 O[8];
#pragma unroll
    for (int i = 0; i < 8; i++) O[i] = make_float4(0.f, 0.f, 0.f, 0.f);
    float mrow = -1e30f, lrow = 0.f;

    for (int kb = 0; kb <= qb; kb++) {
        const int j0 = kb * 64;
        const size_t kbase = ((size_t)(b * Tt + j0)) * Dd + h * HDd;
#pragma unroll
        for (int it = 0; it < 8; it++) {
            int f = tid + it * 256;
            int r = f >> 5, c = f & 31;
            *(float4*)(sK + r * 128 + c * 4) =
                *(const float4*)(K + kbase + (size_t)r * Dd + c * 4);
            *(float4*)(sV + r * 128 + c * 4) =
                *(const float4*)(V + kbase + (size_t)r * Dd + c * 4);
        }
        __syncthreads();

        float acc[16];
#pragma unroll
        for (int kk = 0; kk < 16; kk++) acc[kk] = 0.f;

#pragma unroll
        for (int ch = 0; ch < 4; ch++) {
            float4 qreg[8];
#pragma unroll
            for (int i = 0; i < 8; i++) {
                int g = (i + rp) & 7;
                qreg[i] = *(const float4*)(sQ + qi * 128 + ch * 32 + g * 4);
            }
#pragma unroll
            for (int kk = 0; kk < 16; kk++) {
                const float* kr = sK + (lc * 16 + kk) * 128 + ch * 32;
                float s = 0.f;
#pragma unroll
                for (int i = 0; i < 8; i++) {
                    int g = (i + rp) & 7;
                    float4 kv = *(const float4*)(kr + g * 4);
                    s += qreg[i].x * kv.x + qreg[i].y * kv.y
                       + qreg[i].z * kv.z + qreg[i].w * kv.w;
                }
                acc[kk] += s;
            }
        }

        float tmax = -1e30f;
#pragma unroll
        for (int kk = 0; kk < 16; kk++) {
            float s = acc[kk] * scale;
            if (j0 + lc * 16 + kk > q0 + qi) s = -1e30f;
            acc[kk] = s;
            tmax = fmaxf(tmax, s);
        }
        tmax = fmaxf(tmax, __shfl_xor_sync(0xffffffffu, tmax, 1));
        tmax = fmaxf(tmax, __shfl_xor_sync(0xffffffffu, tmax, 2));
        const float mnew = fmaxf(mrow, tmax);
        const float alpha = __expf(mrow - mnew);
        mrow = mnew;

        float psum = 0.f;
#pragma unroll
        for (int kk = 0; kk < 16; kk++) {
            float p = __expf(acc[kk] - mnew);
            psum += p;
            sP[qi * 68 + lc * 16 + kk] = p;
        }
        psum += __shfl_xor_sync(0xffffffffu, psum, 1);
        psum += __shfl_xor_sync(0xffffffffu, psum, 2);
        lrow = lrow * alpha + psum;
#pragma unroll
        for (int i = 0; i < 8; i++) {
            O[i].x *= alpha; O[i].y *= alpha; O[i].z *= alpha; O[i].w *= alpha;
        }
        __syncthreads();

#pragma unroll 4
        for (int k2 = 0; k2 < 64; k2++) {
            const float pv = sP[qi * 68 + k2];
            const float* vr = sV + k2 * 128 + dbase;
#pragma unroll
            for (int i = 0; i < 8; i++) {
                int g = (i + rp) & 7;
                float4 vv = *(const float4*)(vr + g * 4);
                O[i].x += pv * vv.x; O[i].y += pv * vv.y;
                O[i].z += pv * vv.z; O[i].w += pv * vv.w;
            }
        }
        __syncthreads();
    }

    const float inv = 1.f / lrow;
    const size_t obase = ((size_t)(b * Tt + q0 + qi)) * Dd + h * HDd + dbase;
#pragma unroll
    for (int i = 0; i < 8; i++) {
        int g = (i + rp) & 7;
        float4 o = O[i];
        o.x *= inv; o.y *= inv; o.z *= inv; o.w *= inv;
        *(float4*)(Out + obase + g * 4) = o;
    }
}

// ---------------- fused SiLU(gate)*up ----------------
__global__ void silu_mul_kernel(float* __restrict__ gbuf, const float* __restrict__ ubuf)
{
    const int idx = blockIdx.x * blockDim.x + threadIdx.x;
    const float gt = gbuf[idx];
    const float s = gt / (1.f + __expf(-gt));
    gbuf[idx] = s * ubuf[idx];
}

// ---------------- launch ----------------
extern "C" void kernel_launch(void* const* d_in, const int* in_sizes, int n_in,
                              void* d_out, int out_size)
{
    const float* x   = (const float*)d_in[0];
    const float* fr  = (const float*)d_in[1];
    const float* Wq  = (const float*)d_in[2];
    const float* bq  = (const float*)d_in[3];
    const float* Wk  = (const float*)d_in[4];
    const float* bk  = (const float*)d_in[5];
    const float* Wv  = (const float*)d_in[6];
    const float* bv  = (const float*)d_in[7];
    const float* Wo  = (const float*)d_in[8];
    const float* bo  = (const float*)d_in[9];
    const float* g1  = (const float*)d_in[10];
    const float* be1 = (const float*)d_in[11];
    const float* g2  = (const float*)d_in[12];
    const float* be2 = (const float*)d_in[13];
    const float* Wg  = (const float*)d_in[14];
    const float* bg  = (const float*)d_in[15];
    const float* Wu  = (const float*)d_in[16];
    const float* bu  = (const float*)d_in[17];
    const float* Wd  = (const float*)d_in[18];
    const float* bd  = (const float*)d_in[19];
    float* out = (float*)d_out;

    float *xn, *q, *k, *v, *attn, *ff1, *ff2;
    __nv_bfloat16 *Ahi, *Alo, *Bhi, *Blo;
    cudaGetSymbolAddress((void**)&xn,   g_xn);
    cudaGetSymbolAddress((void**)&q,    g_q);
    cudaGetSymbolAddress((void**)&k,    g_k);
    cudaGetSymbolAddress((void**)&v,    g_v);
    cudaGetSymbolAddress((void**)&attn, g_attn);
    cudaGetSymbolAddress((void**)&ff1,  g_ff1);
    cudaGetSymbolAddress((void**)&ff2,  g_ff2);
    cudaGetSymbolAddress((void**)&Ahi,  g_Ahi);
    cudaGetSymbolAddress((void**)&Alo,  g_Alo);
    cudaGetSymbolAddress((void**)&Bhi,  g_Bhi);
    cudaGetSymbolAddress((void**)&Blo,  g_Blo);

    const int smemF = (3 * 64 * 128 + 64 * 68) * (int)sizeof(float);   // 113 KB
    cudaFuncSetAttribute(flash_kernel, cudaFuncAttributeMaxDynamicSharedMemorySize, smemF);
    cudaFuncSetAttribute(mma_gemm_kernel, cudaFuncAttributeMaxDynamicSharedMemorySize, GEMM_SMEM);

    const int DD  = ROWS * Dd;   // 8M
    const int DW  = Dd * Dd;     // 4M
    const int FW  = FFd * Dd;    // 16M
    const int DF  = ROWS * FFd;  // 32M

#define SPLIT(src, hi, lo, n) split_kernel<<<((n)/4 + 255)/256, 256>>>(src, hi, lo, (n)/4)

    // 1) LN1
    ln_kernel<<<ROWS, 256>>>(x, g1, be1, xn);

    // 2) Q,K,V projections
    SPLIT(xn, Ahi, Alo, DD);
    dim3 gD(Dd / 256, ROWS / 128);
    SPLIT(Wq, Bhi, Blo, DW);
    mma_gemm_kernel<<<gD, 256, GEMM_SMEM>>>(Ahi, Alo, Bhi, Blo, bq, nullptr, q, ROWS, Dd, Dd);
    SPLIT(Wk, Bhi, Blo, DW);
    mma_gemm_kernel<<<gD, 256, GEMM_SMEM>>>(Ahi, Alo, Bhi, Blo, bk, nullptr, k, ROWS, Dd, Dd);
    SPLIT(Wv, Bhi, Blo, DW);
    mma_gemm_kernel<<<gD, 256, GEMM_SMEM>>>(Ahi, Alo, Bhi, Blo, bv, nullptr, v, ROWS, Dd, Dd);

    // 3) RoPE
    rope_kernel<<<(Bb * Tt * Hh * (HDd / 2)) / 256, 256>>>(q, k, fr);

    // 4) causal flash attention
    flash_kernel<<<dim3(Tt / 64, Hh, Bb), 256, smemF>>>(q, k, v, attn);

    // 5) output projection + residual(x) -> out
    SPLIT(attn, Ahi, Alo, DD);
    SPLIT(Wo, Bhi, Blo, DW);
    mma_gemm_kernel<<<gD, 256, GEMM_SMEM>>>(Ahi, Alo, Bhi, Blo, bo, x, out, ROWS, Dd, Dd);

    // 6) LN2
    ln_kernel<<<ROWS, 256>>>(out, g2, be2, xn);

    // 7) gate / up
    SPLIT(xn, Ahi, Alo, DD);
    dim3 gF(FFd / 256, ROWS / 128);
    SPLIT(Wg, Bhi, Blo, FW);
    mma_gemm_kernel<<<gF, 256, GEMM_SMEM>>>(Ahi, Alo, Bhi, Blo, bg, nullptr, ff1, ROWS, FFd, Dd);
    SPLIT(Wu, Bhi, Blo, FW);
    mma_gemm_kernel<<<gF, 256, GEMM_SMEM>>>(Ahi, Alo, Bhi, Blo, bu, nullptr, ff2, ROWS, FFd, Dd);

    // 8) SiLU(gate)*up
    silu_mul_kernel<<<(ROWS * FFd) / 256, 256>>>(ff1, ff2);

    // 9) down projection + residual(out) -> out
    SPLIT(ff1, Ahi, Alo, DF);
    SPLIT(Wd, Bhi, Blo, FW);
    mma_gemm_kernel<<<gD, 256, GEMM_SMEM>>>(Ahi, Alo, Bhi, Blo, bd, out, out, ROWS, Dd, FFd);
}

// round 7
// speedup vs baseline: 2.4808x; 1.0793x over previous
#include <cuda_runtime.h>
#include <cuda_bf16.h>
#include <cstdint>
#include <math.h>

#define Bb 2
#define Tt 2048
#define Dd 2048
#define Hh 16
#define HDd 128
#define FFd 8192
#define ROWS (Bb*Tt)   /* 4096 */

// tcgen05 only exists in arch-specific (sm_10xa) compilation phases.
#if defined(__CUDA_ARCH_FEAT_SM103_ALL) || defined(__CUDA_ARCH_FEAT_SM100_ALL) || \
    defined(__CUDA_ARCH_FEAT_SM101_ALL) || \
    (defined(__CUDA_ARCH_SPECIFIC__) && (__CUDA_ARCH_SPECIFIC__ >= 1000)) || \
    (defined(__CUDA_ARCH_FAMILY_SPECIFIC__) && (__CUDA_ARCH_FAMILY_SPECIFIC__ >= 1000))
#define HAS_TCGEN05 1
#else
#define HAS_TCGEN05 0
#endif

// ---------------- scratch (no allocations allowed -> device globals) ----------------
__device__ float g_xn  [ROWS*Dd];
__device__ float g_q   [ROWS*Dd];
__device__ float g_k   [ROWS*Dd];
__device__ float g_v   [ROWS*Dd];
__device__ float g_attn[ROWS*Dd];
__device__ float g_ff1 [ROWS*FFd];
__device__ float g_ff2 [ROWS*FFd];
// bf16 split buffers
__device__ __nv_bfloat16 g_Ahi[ROWS*FFd];
__device__ __nv_bfloat16 g_Alo[ROWS*FFd];
__device__ __nv_bfloat16 g_Bhi[FFd*Dd];
__device__ __nv_bfloat16 g_Blo[FFd*Dd];

// ================= tcgen05 helpers =================
__device__ __forceinline__ uint32_t smem_u32(const void* p) {
    uint32_t a;
    asm("{ .reg .u64 t; cvta.to.shared.u64 t, %1; cvt.u32.u64 %0, t; }"
        : "=r"(a) : "l"(p));
    return a;
}

#define SW128(o) ((o) ^ (((o) >> 3) & 0x70))

static constexpr uint64_t DESC_BASE_SW128 =
    (uint64_t(2)  << 61) | (uint64_t(1) << 46) | (uint64_t(64) << 32) | (uint64_t(1) << 16);

// idesc: dtype=F32(1<<4), atype=BF16(1<<7), btype=BF16(1<<10), N=128 (16<<17), M=128 (8<<24)
#define MMA_IDESC 0x8200490u

#if HAS_TCGEN05
__device__ __forceinline__ uint32_t elect1() {
    uint32_t p;
    asm volatile("{\n\t.reg .pred p;\n\telect.sync _|p, 0xFFFFFFFF;\n\tselp.b32 %0,1,0,p;\n\t}"
                 : "=r"(p));
    return p;
}
__device__ __forceinline__ uint64_t mkdesc(uint32_t addr) {
    return DESC_BASE_SW128 | ((uint64_t)(addr >> 4) & 0x3FFF);
}
__device__ __forceinline__ void mma_bf16_ss(uint32_t d, uint64_t ad, uint64_t bd, uint32_t en) {
    asm volatile(
        "{\n\t.reg .pred p;\n\tsetp.ne.u32 p, %4, 0;\n\t"
        "tcgen05.mma.cta_group::1.kind::f16 [%0], %1, %2, %3, {%5,%5,%5,%5}, p;\n\t}"
        :: "r"(d), "l"(ad), "l"(bd), "r"(MMA_IDESC), "r"(en), "r"(0u) : "memory");
}
__device__ __forceinline__ void mbar_init(uint32_t m, uint32_t cnt) {
    asm volatile("mbarrier.init.shared.b64 [%0], %1;" :: "r"(m), "r"(cnt) : "memory");
}
__device__ __forceinline__ void mbar_wait(uint32_t m, uint32_t parity) {
    asm volatile(
        "{\n\t.reg .pred P1;\n"
        "W%=:\n\t"
        "mbarrier.try_wait.parity.acquire.cta.shared::cta.b64 P1, [%0], %1, 0x989680;\n\t"
        "@P1 bra.uni D%=;\n\t"
        "bra.uni W%=;\n"
        "D%=:\n\t}"
        :: "r"(m), "r"(parity) : "memory");
}
__device__ __forceinline__ void tc_commit(uint32_t m) {
    asm volatile("tcgen05.commit.cta_group::1.mbarrier::arrive::one.shared::cluster.b64 [%0];"
                 :: "r"(m) : "memory");
}
__device__ __forceinline__ void ldtm32(uint32_t* r, uint32_t a) {
    asm volatile(
        "tcgen05.ld.sync.aligned.32x32b.x32.b32 "
        "{%0,%1,%2,%3,%4,%5,%6,%7,%8,%9,%10,%11,%12,%13,%14,%15,"
        "%16,%17,%18,%19,%20,%21,%22,%23,%24,%25,%26,%27,%28,%29,%30,%31}, [%32];"
        : "=r"(r[0]),"=r"(r[1]),"=r"(r[2]),"=r"(r[3]),"=r"(r[4]),"=r"(r[5]),"=r"(r[6]),"=r"(r[7]),
          "=r"(r[8]),"=r"(r[9]),"=r"(r[10]),"=r"(r[11]),"=r"(r[12]),"=r"(r[13]),"=r"(r[14]),"=r"(r[15]),
          "=r"(r[16]),"=r"(r[17]),"=r"(r[18]),"=r"(r[19]),"=r"(r[20]),"=r"(r[21]),"=r"(r[22]),"=r"(r[23]),
          "=r"(r[24]),"=r"(r[25]),"=r"(r[26]),"=r"(r[27]),"=r"(r[28]),"=r"(r[29]),"=r"(r[30]),"=r"(r[31])
        : "r"(a));
}
__device__ __forceinline__ void cpasync16(uint32_t dst, const void* src) {
    asm volatile("cp.async.cg.shared.global [%0], [%1], 16;" :: "r"(dst), "l"(src) : "memory");
}
__device__ __forceinline__ void cp_arrive(uint32_t m) {
    asm volatile("cp.async.mbarrier.arrive.noinc.shared.b64 [%0];" :: "r"(m) : "memory");
}
#endif  // HAS_TCGEN05

// ---------------- split fp32 -> bf16 hi/lo ----------------
__global__ void __launch_bounds__(256) split_kernel(const float* __restrict__ src,
                                                    __nv_bfloat16* __restrict__ hi,
                                                    __nv_bfloat16* __restrict__ lo,
                                                    int n4)
{
    int idx = blockIdx.x * blockDim.x + threadIdx.x;
    if (idx >= n4) return;
    float4 v = ((const float4*)src)[idx];
    __nv_bfloat162 h0 = __floats2bfloat162_rn(v.x, v.y);
    __nv_bfloat162 h1 = __floats2bfloat162_rn(v.z, v.w);
    float lx = v.x - __bfloat162float(__low2bfloat16(h0));
    float ly = v.y - __bfloat162float(__high2bfloat16(h0));
    float lz = v.z - __bfloat162float(__low2bfloat16(h1));
    float lw = v.w - __bfloat162float(__high2bfloat16(h1));
    __nv_bfloat162 l0 = __floats2bfloat162_rn(lx, ly);
    __nv_bfloat162 l1 = __floats2bfloat162_rn(lz, lw);
    uint2 ho, loo;
    ho.x  = *reinterpret_cast<uint32_t*>(&h0);
    ho.y  = *reinterpret_cast<uint32_t*>(&h1);
    loo.x = *reinterpret_cast<uint32_t*>(&l0);
    loo.y = *reinterpret_cast<uint32_t*>(&l1);
    ((uint2*)hi)[idx] = ho;
    ((uint2*)lo)[idx] = loo;
}

// ============ GEMM: C[m,n] = sum_k A[m,k]*B[n,k] + bias[n] (+resid), pre-split bf16 ============
// BM=128, BN=128, BK=64, 3-stage decoupled cp.async/mbarrier pipeline (no __syncthreads in loop).
#define NSTAGE 3
#define STAGE_BYTES 65536   /* A_hi 16K | A_lo 16K | B_hi 16K | B_lo 16K */
#define GEMM_SMEM (1024 + NSTAGE * STAGE_BYTES)

__global__ void __launch_bounds__(256, 1)
mma_gemm_kernel(const __nv_bfloat16* __restrict__ Ah, const __nv_bfloat16* __restrict__ Al,
                const __nv_bfloat16* __restrict__ Bh, const __nv_bfloat16* __restrict__ Bl,
                const float* __restrict__ bias, const float* __restrict__ resid,
                float* __restrict__ C, int M, int N, int K)
{
    extern __shared__ char smem[];
#if HAS_TCGEN05
    const uint32_t sbase = smem_u32(smem);
    const int tid  = threadIdx.x;
    const int wid  = tid >> 5;
    const int lane = tid & 31;
    const int bn = blockIdx.x * 128;
    const int bm = blockIdx.y * 128;

    const uint32_t tile_abs = (sbase + 64 + 1023) & ~1023u;
    // mbarriers: full[s] at +8..24 (count 256), empty[s] at +32..48 (count 1)
    const uint32_t mb_full  = sbase + 8;
    const uint32_t mb_empty = sbase + 32;

    if (wid == 0) {
        asm volatile("tcgen05.alloc.cta_group::1.sync.aligned.shared::cta.b32 [%0], %1;"
                     :: "r"(sbase), "r"(128u) : "memory");
        asm volatile("tcgen05.relinquish_alloc_permit.cta_group::1.sync.aligned;");
    }
    if (tid == 0) {
#pragma unroll
        for (int s = 0; s < NSTAGE; s++) {
            mbar_init(mb_full  + s * 8, 256);
            mbar_init(mb_empty + s * 8, 1);
        }
    }
    __syncthreads();
    uint32_t tmem;
    asm volatile("ld.shared.b32 %0, [%1];" : "=r"(tmem) : "r"(sbase));

    // producer mapping: all four 16KB tiles are 128 rows x 128B SW128.
    // thread t -> row t>>1, 64B half (t&1); 4 x 16B cp.async per tile.
    const int r  = tid >> 1;
    const int hh = tid & 1;
    const uint32_t off = r * 128 + hh * 64;
    const __nv_bfloat16* AgH = Ah + (size_t)(bm + r) * K + hh * 32;
    const __nv_bfloat16* AgL = Al + (size_t)(bm + r) * K + hh * 32;
    const __nv_bfloat16* BgH = Bh + (size_t)(bn + r) * K + hh * 32;
    const __nv_bfloat16* BgL = Bl + (size_t)(bn + r) * K + hh * 32;

    const bool lead = (wid == 0) && elect1();
    const int n = K >> 6;

    for (int c = 0; c < n; c++) {
        const int s = c % NSTAGE;
        const int use = c / NSTAGE;
        if (c >= NSTAGE) mbar_wait(mb_empty + s * 8, (use - 1) & 1);

        const uint32_t sb = tile_abs + s * STAGE_BYTES;
        const size_t kof = (size_t)c * 64;
#pragma unroll
        for (int j = 0; j < 4; j++) {
            const uint32_t o = SW128(off + j * 16);
            cpasync16(sb + o,         AgH + kof + j * 8);
            cpasync16(sb + 16384 + o, AgL + kof + j * 8);
            cpasync16(sb + 32768 + o, BgH + kof + j * 8);
            cpasync16(sb + 49152 + o, BgL + kof + j * 8);
        }
        cp_arrive(mb_full + s * 8);

        if (lead && c >= 1) {
            const int i = c - 1, si = i % NSTAGE;
            mbar_wait(mb_full + si * 8, (i / NSTAGE) & 1);
            asm volatile("fence.proxy.async.shared::cta;" ::: "memory");
            const uint32_t sbi = tile_abs + si * STAGE_BYTES;
            const uint64_t ah = mkdesc(sbi);
            const uint64_t al = mkdesc(sbi + 16384);
            const uint64_t bh = mkdesc(sbi + 32768);
            const uint64_t bl = mkdesc(sbi + 49152);
#pragma unroll
            for (int k = 0; k < 4; k++)
                mma_bf16_ss(tmem, ah + k * 2, bh + k * 2, (i > 0 || k > 0) ? 1u : 0u);
#pragma unroll
            for (int k = 0; k < 4; k++)
                mma_bf16_ss(tmem, ah + k * 2, bl + k * 2, 1u);
#pragma unroll
            for (int k = 0; k < 4; k++)
                mma_bf16_ss(tmem, al + k * 2, bh + k * 2, 1u);
            tc_commit(mb_empty + si * 8);
        }
    }

    if (lead) {   // last chunk's MMAs
        const int i = n - 1, si = i % NSTAGE;
        mbar_wait(mb_full + si * 8, (i / NSTAGE) & 1);
        asm volatile("fence.proxy.async.shared::cta;" ::: "memory");
        const uint32_t sbi = tile_abs + si * STAGE_BYTES;
        const uint64_t ah = mkdesc(sbi);
        const uint64_t al = mkdesc(sbi + 16384);
        const uint64_t bh = mkdesc(sbi + 32768);
        const uint64_t bl = mkdesc(sbi + 49152);
#pragma unroll
        for (int k = 0; k < 4; k++)
            mma_bf16_ss(tmem, ah + k * 2, bh + k * 2, 1u);
#pragma unroll
        for (int k = 0; k < 4; k++)
            mma_bf16_ss(tmem, ah + k * 2, bl + k * 2, 1u);
#pragma unroll
        for (int k = 0; k < 4; k++)
            mma_bf16_ss(tmem, al + k * 2, bh + k * 2, 1u);
        tc_commit(mb_empty + si * 8);
    }

    // all threads wait for the final chunk's MMA completion
    {
        const int i = n - 1, si = i % NSTAGE;
        mbar_wait(mb_empty + si * 8, (i / NSTAGE) & 1);
    }
    asm volatile("tcgen05.fence::after_thread_sync;" ::: "memory");

    // epilogue: warp w -> rows (w&3)*32..+31, col half (w>>2)*64
    const int sub  = wid & 3;
    const int half = wid >> 2;
    const int row  = bm + sub * 32 + lane;
    const float* rrow = resid ? resid + (size_t)row * N : nullptr;
    float* crow = C + (size_t)row * N;
#pragma unroll 1
    for (int c32 = 0; c32 < 2; c32++) {
        uint32_t d[32];
        ldtm32(d, tmem + half * 64 + c32 * 32);
        asm volatile("tcgen05.wait::ld.sync.aligned;" ::: "memory");
        const int col0 = bn + half * 64 + c32 * 32;
        if (rrow) {
#pragma unroll
            for (int j = 0; j < 32; j++)
                crow[col0 + j] = __uint_as_float(d[j]) + bias[col0 + j] + rrow[col0 + j];
        } else {
#pragma unroll
            for (int j = 0; j < 32; j++)
                crow[col0 + j] = __uint_as_float(d[j]) + bias[col0 + j];
        }
    }
    __syncthreads();
    if (wid == 0) {
        asm volatile("tcgen05.dealloc.cta_group::1.sync.aligned.b32 %0, %1;"
                     :: "r"(tmem), "r"(128u));
    }
#else
    // ---------- baseline-PTX fallback: SIMT, reconstruct fp32 = hi + lo ----------
    float* As = (float*)smem;            // [8][128]
    float* Bs = As + 8 * 128;            // [8][128]
    const int tid = threadIdx.x;
    const int bm = blockIdx.y * 128;
    const int bn = blockIdx.x * 128;
    const int lr  = tid >> 1;
    const int lcc = (tid & 1) * 4;
    const int tx = tid & 15, ty = tid >> 4;

    float acc[8][8];
#pragma unroll
    for (int i = 0; i < 8; i++)
#pragma unroll
        for (int j = 0; j < 8; j++) acc[i][j] = 0.f;

    for (int k0 = 0; k0 < K; k0 += 8) {
        const __nv_bfloat16* aph = Ah + (size_t)(bm + lr) * K + k0 + lcc;
        const __nv_bfloat16* apl = Al + (size_t)(bm + lr) * K + k0 + lcc;
        const __nv_bfloat16* bph = Bh + (size_t)(bn + lr) * K + k0 + lcc;
        const __nv_bfloat16* bpl = Bl + (size_t)(bn + lr) * K + k0 + lcc;
#pragma unroll
        for (int j = 0; j < 4; j++) {
            As[(lcc + j) * 128 + lr] = __bfloat162float(aph[j]) + __bfloat162float(apl[j]);
            Bs[(lcc + j) * 128 + lr] = __bfloat162float(bph[j]) + __bfloat162float(bpl[j]);
        }
        __syncthreads();
#pragma unroll
        for (int kk = 0; kk < 8; kk++) {
            float a[8], bb[8];
#pragma unroll
            for (int i = 0; i < 8; i++)
                a[i] = As[kk * 128 + ((i & 4) << 4) + ty * 4 + (i & 3)];
#pragma unroll
            for (int j = 0; j < 8; j++)
                bb[j] = Bs[kk * 128 + ((j & 4) << 4) + tx * 4 + (j & 3)];
#pragma unroll
            for (int i = 0; i < 8; i++)
#pragma unroll
                for (int j = 0; j < 8; j++)
                    acc[i][j] += a[i] * bb[j];
        }
        __syncthreads();
    }

#pragma unroll
    for (int i = 0; i < 8; i++) {
        const int row = bm + ((i & 4) << 4) + ty * 4 + (i & 3);
#pragma unroll
        for (int j = 0; j < 8; j++) {
            const int col = bn + ((j & 4) << 4) + tx * 4 + (j & 3);
            float vv = acc[i][j] + bias[col];
            if (resid) vv += resid[(size_t)row * N + col];
            C[(size_t)row * N + col] = vv;
        }
    }
#endif
}

// ---------------- LayerNorm ----------------
__global__ void __launch_bounds__(256) ln_kernel(const float* __restrict__ x,
                                                 const float* __restrict__ g,
                                                 const float* __restrict__ b,
                                                 float* __restrict__ out)
{
    const int row = blockIdx.x;
    const int tid = threadIdx.x;
    const float* xr = x + (size_t)row * Dd;
    __shared__ float red[256];

    float s = 0.f;
    for (int i = tid; i < Dd; i += 256) s += xr[i];
    red[tid] = s; __syncthreads();
    for (int off = 128; off > 0; off >>= 1) {
        if (tid < off) red[tid] += red[tid + off];
        __syncthreads();
    }
    const float mean = red[0] * (1.f / Dd);
    __syncthreads();

    float v = 0.f;
    for (int i = tid; i < Dd; i += 256) { float d = xr[i] - mean; v += d * d; }
    red[tid] = v; __syncthreads();
    for (int off = 128; off > 0; off >>= 1) {
        if (tid < off) red[tid] += red[tid + off];
        __syncthreads();
    }
    const float rstd = rsqrtf(red[0] * (1.f / Dd) + 1e-5f);

    float* orow = out + (size_t)row * Dd;
    for (int i = tid; i < Dd; i += 256)
        orow[i] = (xr[i] - mean) * rstd * g[i] + b[i];
}

// ---------------- RoPE (head-indexed freqs, faithful to reference) ----------------
__global__ void rope_kernel(float* __restrict__ q, float* __restrict__ k,
                            const float* __restrict__ fr)
{
    const int idx = blockIdx.x * blockDim.x + threadIdx.x;
    const int j  = idx & 63;
    const int h  = (idx >> 6) & 15;
    const int bt = idx >> 10;
    const size_t base = (size_t)bt * Dd + h * HDd + 2 * j;
    const float cr = fr[h * 128 + 2 * j];
    const float ci = fr[h * 128 + 2 * j + 1];
    float a = q[base], b2 = q[base + 1];
    q[base]     = a * cr - b2 * ci;
    q[base + 1] = a * ci + b2 * cr;
    a = k[base]; b2 = k[base + 1];
    k[base]     = a * cr - b2 * ci;
    k[base + 1] = a * ci + b2 * cr;
}

// ---------------- Flash attention, causal, fp32, HD=128 ----------------
__global__ void __launch_bounds__(256) flash_kernel(const float* __restrict__ Q,
                                                    const float* __restrict__ K,
                                                    const float* __restrict__ V,
                                                    float* __restrict__ Out)
{
    extern __shared__ float sm[];
    float* sQ = sm;
    float* sK = sm + 64 * 128;
    float* sV = sm + 2 * 64 * 128;
    float* sP = sm + 3 * 64 * 128;

    const int tid = threadIdx.x;
    const int qb = blockIdx.x, h = blockIdx.y, b = blockIdx.z;
    const int q0 = qb * 64;
    const size_t qbase = ((size_t)(b * Tt + q0)) * Dd + h * HDd;

#pragma unroll
    for (int it = 0; it < 8; it++) {
        int f = tid + it * 256;
        int r = f >> 5, c = f & 31;
        *(float4*)(sQ + r * 128 + c * 4) =
            *(const float4*)(Q + qbase + (size_t)r * Dd + c * 4);
    }

    const int qi = tid >> 2;
    const int lc = tid & 3;
    const int rp = ((tid >> 2) + 2 * lc) & 7;
    const int dbase = lc * 32;
    const float scale = 0.088388347648318447f;

    float4 O[8];
#pragma unroll
    for (int i = 0; i < 8; i++) O[i] = make_float4(0.f, 0.f, 0.f, 0.f);
    float mrow = -1e30f, lrow = 0.f;

    for (int kb = 0; kb <= qb; kb++) {
        const int j0 = kb * 64;
        const size_t kbase = ((size_t)(b * Tt + j0)) * Dd + h * HDd;
#pragma unroll
        for (int it = 0; it < 8; it++) {
            int f = tid + it * 256;
            int r = f >> 5, c = f & 31;
            *(float4*)(sK + r * 128 + c * 4) =
                *(const float4*)(K + kbase + (size_t)r * Dd + c * 4);
            *(float4*)(sV + r * 128 + c * 4) =
                *(const float4*)(V + kbase + (size_t)r * Dd + c * 4);
        }
        __syncthreads();

        float acc[16];
#pragma unroll
        for (int kk = 0; kk < 16; kk++) acc[kk] = 0.f;

#pragma unroll
        for (int ch = 0; ch < 4; ch++) {
            float4 qreg[8];
#pragma unroll
            for (int i = 0; i < 8; i++) {
                int g = (i + rp) & 7;
                qreg[i] = *(const float4*)(sQ + qi * 128 + ch * 32 + g * 4);
            }
#pragma unroll
            for (int kk = 0; kk < 16; kk++) {
                const float* kr = sK + (lc * 16 + kk) * 128 + ch * 32;
                float s = 0.f;
#pragma unroll
                for (int i = 0; i < 8; i++) {
                    int g = (i + rp) & 7;
                    float4 kv = *(const float4*)(kr + g * 4);
                    s += qreg[i].x * kv.x + qreg[i].y * kv.y
                       + qreg[i].z * kv.z + qreg[i].w * kv.w;
                }
                acc[kk] += s;
            }
        }

        float tmax = -1e30f;
#pragma unroll
        for (int kk = 0; kk < 16; kk++) {
            float s = acc[kk] * scale;
            if (j0 + lc * 16 + kk > q0 + qi) s = -1e30f;
            acc[kk] = s;
            tmax = fmaxf(tmax, s);
        }
        tmax = fmaxf(tmax, __shfl_xor_sync(0xffffffffu, tmax, 1));
        tmax = fmaxf(tmax, __shfl_xor_sync(0xffffffffu, tmax, 2));
        const float mnew = fmaxf(mrow, tmax);
        const float alpha = __expf(mrow - mnew);
        mrow = mnew;

        float psum = 0.f;
#pragma unroll
        for (int kk = 0; kk < 16; kk++) {
            float p = __expf(acc[kk] - mnew);
            psum += p;
            sP[qi * 68 + lc * 16 + kk] = p;
        }
        psum += __shfl_xor_sync(0xffffffffu, psum, 1);
        psum += __shfl_xor_sync(0xffffffffu, psum, 2);
        lrow = lrow * alpha + psum;
#pragma unroll
        for (int i = 0; i < 8; i++) {
            O[i].x *= alpha; O[i].y *= alpha; O[i].z *= alpha; O[i].w *= alpha;
        }
        __syncthreads();

#pragma unroll 4
        for (int k2 = 0; k2 < 64; k2++) {
            const float pv = sP[qi * 68 + k2];
            const float* vr = sV + k2 * 128 + dbase;
#pragma unroll
            for (int i = 0; i < 8; i++) {
                int g = (i + rp) & 7;
                float4 vv = *(const float4*)(vr + g * 4);
                O[i].x += pv * vv.x; O[i].y += pv * vv.y;
                O[i].z += pv * vv.z; O[i].w += pv * vv.w;
            }
        }
        __syncthreads();
    }

    const float inv = 1.f / lrow;
    const size_t obase = ((size_t)(b * Tt + q0 + qi)) * Dd + h * HDd + dbase;
#pragma unroll
    for (int i = 0; i < 8; i++) {
        int g = (i + rp) & 7;
        float4 o = O[i];
        o.x *= inv; o.y *= inv; o.z *= inv; o.w *= inv;
        *(float4*)(Out + obase + g * 4) = o;
    }
}

// ---------------- fused SiLU(gate)*up ----------------
__global__ void silu_mul_kernel(float* __restrict__ gbuf, const float* __restrict__ ubuf)
{
    const int idx = blockIdx.x * blockDim.x + threadIdx.x;
    const float gt = gbuf[idx];
    const float s = gt / (1.f + __expf(-gt));
    gbuf[idx] = s * ubuf[idx];
}

// ---------------- launch ----------------
extern "C" void kernel_launch(void* const* d_in, const int* in_sizes, int n_in,
                              void* d_out, int out_size)
{
    const float* x   = (const float*)d_in[0];
    const float* fr  = (const float*)d_in[1];
    const float* Wq  = (const float*)d_in[2];
    const float* bq  = (const float*)d_in[3];
    const float* Wk  = (const float*)d_in[4];
    const float* bk  = (const float*)d_in[5];
    const float* Wv  = (const float*)d_in[6];
    const float* bv  = (const float*)d_in[7];
    const float* Wo  = (const float*)d_in[8];
    const float* bo  = (const float*)d_in[9];
    const float* g1  = (const float*)d_in[10];
    const float* be1 = (const float*)d_in[11];
    const float* g2  = (const float*)d_in[12];
    const float* be2 = (const float*)d_in[13];
    const float* Wg  = (const float*)d_in[14];
    const float* bg  = (const float*)d_in[15];
    const float* Wu  = (const float*)d_in[16];
    const float* bu  = (const float*)d_in[17];
    const float* Wd  = (const float*)d_in[18];
    const float* bd  = (const float*)d_in[19];
    float* out = (float*)d_out;

    float *xn, *q, *k, *v, *attn, *ff1, *ff2;
    __nv_bfloat16 *Ahi, *Alo, *Bhi, *Blo;
    cudaGetSymbolAddress((void**)&xn,   g_xn);
    cudaGetSymbolAddress((void**)&q,    g_q);
    cudaGetSymbolAddress((void**)&k,    g_k);
    cudaGetSymbolAddress((void**)&v,    g_v);
    cudaGetSymbolAddress((void**)&attn, g_attn);
    cudaGetSymbolAddress((void**)&ff1,  g_ff1);
    cudaGetSymbolAddress((void**)&ff2,  g_ff2);
    cudaGetSymbolAddress((void**)&Ahi,  g_Ahi);
    cudaGetSymbolAddress((void**)&Alo,  g_Alo);
    cudaGetSymbolAddress((void**)&Bhi,  g_Bhi);
    cudaGetSymbolAddress((void**)&Blo,  g_Blo);

    const int smemF = (3 * 64 * 128 + 64 * 68) * (int)sizeof(float);   // 113 KB
    cudaFuncSetAttribute(flash_kernel, cudaFuncAttributeMaxDynamicSharedMemorySize, smemF);
    cudaFuncSetAttribute(mma_gemm_kernel, cudaFuncAttributeMaxDynamicSharedMemorySize, GEMM_SMEM);

    const int DD  = ROWS * Dd;   // 8M
    const int DW  = Dd * Dd;     // 4M
    const int FW  = FFd * Dd;    // 16M
    const int DF  = ROWS * FFd;  // 32M

#define SPLIT(src, hi, lo, n) split_kernel<<<((n)/4 + 255)/256, 256>>>(src, hi, lo, (n)/4)

    // 1) LN1
    ln_kernel<<<ROWS, 256>>>(x, g1, be1, xn);

    // 2) Q,K,V projections
    SPLIT(xn, Ahi, Alo, DD);
    dim3 gD(Dd / 128, ROWS / 128);
    SPLIT(Wq, Bhi, Blo, DW);
    mma_gemm_kernel<<<gD, 256, GEMM_SMEM>>>(Ahi, Alo, Bhi, Blo, bq, nullptr, q, ROWS, Dd, Dd);
    SPLIT(Wk, Bhi, Blo, DW);
    mma_gemm_kernel<<<gD, 256, GEMM_SMEM>>>(Ahi, Alo, Bhi, Blo, bk, nullptr, k, ROWS, Dd, Dd);
    SPLIT(Wv, Bhi, Blo, DW);
    mma_gemm_kernel<<<gD, 256, GEMM_SMEM>>>(Ahi, Alo, Bhi, Blo, bv, nullptr, v, ROWS, Dd, Dd);

    // 3) RoPE
    rope_kernel<<<(Bb * Tt * Hh * (HDd / 2)) / 256, 256>>>(q, k, fr);

    // 4) causal flash attention
    flash_kernel<<<dim3(Tt / 64, Hh, Bb), 256, smemF>>>(q, k, v, attn);

    // 5) output projection + residual(x) -> out
    SPLIT(attn, Ahi, Alo, DD);
    SPLIT(Wo, Bhi, Blo, DW);
    mma_gemm_kernel<<<gD, 256, GEMM_SMEM>>>(Ahi, Alo, Bhi, Blo, bo, x, out, ROWS, Dd, Dd);

    // 6) LN2
    ln_kernel<<<ROWS, 256>>>(out, g2, be2, xn);

    // 7) gate / up
    SPLIT(xn, Ahi, Alo, DD);
    dim3 gF(FFd / 128, ROWS / 128);
    SPLIT(Wg, Bhi, Blo, FW);
    mma_gemm_kernel<<<gF, 256, GEMM_SMEM>>>(Ahi, Alo, Bhi, Blo, bg, nullptr, ff1, ROWS, FFd, Dd);
    SPLIT(Wu, Bhi, Blo, FW);
    mma_gemm_kernel<<<gF, 256, GEMM_SMEM>>>(Ahi, Alo, Bhi, Blo, bu, nullptr, ff2, ROWS, FFd, Dd);

    // 8) SiLU(gate)*up
    silu_mul_kernel<<<(ROWS * FFd) / 256, 256>>>(ff1, ff2);

    // 9) down projection + residual(out) -> out
    SPLIT(ff1, Ahi, Alo, DF);
    SPLIT(Wd, Bhi, Blo, FW);
    mma_gemm_kernel<<<gD, 256, GEMM_SMEM>>>(Ahi, Alo, Bhi, Blo, bd, out, out, ROWS, Dd, FFd);
}

// round 8
// speedup vs baseline: 3.1913x; 1.2864x over previous
#include <cuda_runtime.h>
#include <cuda_bf16.h>
#include <cstdint>
#include <math.h>

#define Bb 2
#define Tt 2048
#define Dd 2048
#define Hh 16
#define HDd 128
#define FFd 8192
#define ROWS (Bb*Tt)   /* 4096 */

// tcgen05 only exists in arch-specific (sm_10xa) compilation phases.
#if defined(__CUDA_ARCH_FEAT_SM103_ALL) || defined(__CUDA_ARCH_FEAT_SM100_ALL) || \
    defined(__CUDA_ARCH_FEAT_SM101_ALL) || \
    (defined(__CUDA_ARCH_SPECIFIC__) && (__CUDA_ARCH_SPECIFIC__ >= 1000)) || \
    (defined(__CUDA_ARCH_FAMILY_SPECIFIC__) && (__CUDA_ARCH_FAMILY_SPECIFIC__ >= 1000))
#define HAS_TCGEN05 1
#else
#define HAS_TCGEN05 0
#endif

// ---------------- scratch (no allocations allowed -> device globals) ----------------
__device__ float g_xn  [ROWS*Dd];
__device__ float g_q   [ROWS*Dd];
__device__ float g_k   [ROWS*Dd];
__device__ float g_v   [ROWS*Dd];
__device__ float g_attn[ROWS*Dd];
__device__ float g_ff1 [ROWS*FFd];
__device__ float g_ff2 [ROWS*FFd];
// bf16 split buffers
__device__ __nv_bfloat16 g_Ahi[ROWS*FFd];
__device__ __nv_bfloat16 g_Alo[ROWS*FFd];
__device__ __nv_bfloat16 g_Bhi[FFd*Dd];
__device__ __nv_bfloat16 g_Blo[FFd*Dd];

// ================= helpers =================
__device__ __forceinline__ uint32_t smem_u32(const void* p) {
    uint32_t a;
    asm("{ .reg .u64 t; cvta.to.shared.u64 t, %1; cvt.u32.u64 %0, t; }"
        : "=r"(a) : "l"(p));
    return a;
}

#define SW128(o) ((o) ^ (((o) >> 3) & 0x70))

static constexpr uint64_t DESC_BASE_SW128 =
    (uint64_t(2)  << 61) | (uint64_t(1) << 46) | (uint64_t(64) << 32) | (uint64_t(1) << 16);

// idesc (kind::f16): dtype=F32(1<<4), atype=BF16(1<<7), btype=BF16(1<<10),
// N=256 ((256/8)<<17), M=256 ((256/16)<<24)
#define MMA_IDESC_CG2 0x10400490u

#if HAS_TCGEN05
__device__ __forceinline__ uint64_t mkdesc(uint32_t addr) {
    return DESC_BASE_SW128 | ((uint64_t)(addr >> 4) & 0x3FFF);
}
__device__ __forceinline__ void mma_bf16_ss_cg2(uint32_t d, uint64_t ad, uint64_t bd, uint32_t en) {
    asm volatile(
        "{\n\t.reg .pred p;\n\tsetp.ne.u32 p, %4, 0;\n\t"
        "tcgen05.mma.cta_group::2.kind::f16 [%0], %1, %2, %3, {%5,%5,%5,%5,%5,%5,%5,%5}, p;\n\t}"
        :: "r"(d), "l"(ad), "l"(bd), "r"(MMA_IDESC_CG2), "r"(en), "r"(0u) : "memory");
}
__device__ __forceinline__ void mbar_init(uint32_t m, uint32_t cnt) {
    asm volatile("mbarrier.init.shared.b64 [%0], %1;" :: "r"(m), "r"(cnt) : "memory");
}
__device__ __forceinline__ void mbar_wait(uint32_t m, uint32_t parity) {
    asm volatile(
        "{\n\t.reg .pred P1;\n"
        "W%=:\n\t"
        "mbarrier.try_wait.parity.acquire.cta.shared::cta.b64 P1, [%0], %1, 0x989680;\n\t"
        "@P1 bra.uni D%=;\n\t"
        "bra.uni W%=;\n"
        "D%=:\n\t}"
        :: "r"(m), "r"(parity) : "memory");
}
__device__ __forceinline__ void tc_commit_mc2(uint32_t m) {
    asm volatile(
        "tcgen05.commit.cta_group::2.mbarrier::arrive::one.shared::cluster.multicast::cluster.b64 [%0], %1;"
        :: "r"(m), "h"((uint16_t)0x3) : "memory");
}
__device__ __forceinline__ void mbar_arrive_rank0(uint32_t local_addr) {
    asm volatile(
        "{\n\t.reg .b32 ra;\n\t"
        "mapa.shared::cluster.u32 ra, %0, %1;\n\t"
        "mbarrier.arrive.shared::cluster.b64 _, [ra];\n\t}"
        :: "r"(local_addr), "r"(0) : "memory");
}
__device__ __forceinline__ void ldtm32(uint32_t* r, uint32_t a) {
    asm volatile(
        "tcgen05.ld.sync.aligned.32x32b.x32.b32 "
        "{%0,%1,%2,%3,%4,%5,%6,%7,%8,%9,%10,%11,%12,%13,%14,%15,"
        "%16,%17,%18,%19,%20,%21,%22,%23,%24,%25,%26,%27,%28,%29,%30,%31}, [%32];"
        : "=r"(r[0]),"=r"(r[1]),"=r"(r[2]),"=r"(r[3]),"=r"(r[4]),"=r"(r[5]),"=r"(r[6]),"=r"(r[7]),
          "=r"(r[8]),"=r"(r[9]),"=r"(r[10]),"=r"(r[11]),"=r"(r[12]),"=r"(r[13]),"=r"(r[14]),"=r"(r[15]),
          "=r"(r[16]),"=r"(r[17]),"=r"(r[18]),"=r"(r[19]),"=r"(r[20]),"=r"(r[21]),"=r"(r[22]),"=r"(r[23]),
          "=r"(r[24]),"=r"(r[25]),"=r"(r[26]),"=r"(r[27]),"=r"(r[28]),"=r"(r[29]),"=r"(r[30]),"=r"(r[31])
        : "r"(a));
}
__device__ __forceinline__ void cpasync16(uint32_t dst, const void* src) {
    asm volatile("cp.async.cg.shared.global [%0], [%1], 16;" :: "r"(dst), "l"(src) : "memory");
}
__device__ __forceinline__ void cp_arrive(uint32_t m) {
    asm volatile("cp.async.mbarrier.arrive.noinc.shared.b64 [%0];" :: "r"(m) : "memory");
}
#define CLUSTER_SYNC() do { \
    asm volatile("barrier.cluster.arrive.aligned;" ::: "memory"); \
    asm volatile("barrier.cluster.wait.aligned;" ::: "memory"); \
} while (0)
#endif  // HAS_TCGEN05

// ---------------- split fp32 -> bf16 hi/lo ----------------
__global__ void __launch_bounds__(256) split_kernel(const float* __restrict__ src,
                                                    __nv_bfloat16* __restrict__ hi,
                                                    __nv_bfloat16* __restrict__ lo,
                                                    int n4)
{
    int idx = blockIdx.x * blockDim.x + threadIdx.x;
    if (idx >= n4) return;
    float4 v = ((const float4*)src)[idx];
    __nv_bfloat162 h0 = __floats2bfloat162_rn(v.x, v.y);
    __nv_bfloat162 h1 = __floats2bfloat162_rn(v.z, v.w);
    float lx = v.x - __bfloat162float(__low2bfloat16(h0));
    float ly = v.y - __bfloat162float(__high2bfloat16(h0));
    float lz = v.z - __bfloat162float(__low2bfloat16(h1));
    float lw = v.w - __bfloat162float(__high2bfloat16(h1));
    __nv_bfloat162 l0 = __floats2bfloat162_rn(lx, ly);
    __nv_bfloat162 l1 = __floats2bfloat162_rn(lz, lw);
    uint2 ho, loo;
    ho.x  = *reinterpret_cast<uint32_t*>(&h0);
    ho.y  = *reinterpret_cast<uint32_t*>(&h1);
    loo.x = *reinterpret_cast<uint32_t*>(&l0);
    loo.y = *reinterpret_cast<uint32_t*>(&l1);
    ((uint2*)hi)[idx] = ho;
    ((uint2*)lo)[idx] = loo;
}

// ============ cg2 GEMM: C[m,n] = sum_k A[m,k]*B[n,k] + bias[n] (+resid), pre-split bf16 ============
// Cluster (2,1,1): pair covers a 256x256 output tile. Per CTA: A 128 rows (its M half),
// B 128 rows (its N half). BK=64, 3-stage decoupled cp.async ring (no __syncthreads in loop).
// grid: (2*(N/256), M/256). rank = blockIdx.x & 1.
#define NSTAGE 3
#define STAGE_BYTES 65536   /* A_hi 16K | A_lo 16K | B_hi 16K | B_lo 16K */
#define GEMM_SMEM (1024 + NSTAGE * STAGE_BYTES)

__global__ void __launch_bounds__(256, 1) __cluster_dims__(2, 1, 1)
mma_gemm_kernel(const __nv_bfloat16* __restrict__ Ah, const __nv_bfloat16* __restrict__ Al,
                const __nv_bfloat16* __restrict__ Bh, const __nv_bfloat16* __restrict__ Bl,
                const float* __restrict__ bias, const float* __restrict__ resid,
                float* __restrict__ C, int M, int N, int K)
{
    extern __shared__ char smem[];
#if HAS_TCGEN05
    const uint32_t sbase = smem_u32(smem);
    const int tid  = threadIdx.x;
    const int wid  = tid >> 5;
    const int lane = tid & 31;
    const int rank = blockIdx.x & 1;
    const int bn   = (blockIdx.x >> 1) * 256;     // pair's N base
    const int bm   = blockIdx.y * 256;            // pair's M base

    const uint32_t tile_abs = (sbase + 128 + 1023) & ~1023u;
    const uint32_t mb_full  = sbase + 8;    // full_local[s], count 256
    const uint32_t mb_f2    = sbase + 32;   // full_cluster[s] (used on rank0), count 2
    const uint32_t mb_empty = sbase + 56;   // empty[s], count 1 (commit-multicast)

    if (wid == 0) {
        asm volatile("tcgen05.alloc.cta_group::2.sync.aligned.shared::cta.b32 [%0], %1;"
                     :: "r"(sbase), "r"(256u) : "memory");
        asm volatile("tcgen05.relinquish_alloc_permit.cta_group::2.sync.aligned;");
    }
    if (tid == 0) {
#pragma unroll
        for (int s = 0; s < NSTAGE; s++) {
            mbar_init(mb_full  + s * 8, 256);
            mbar_init(mb_f2    + s * 8, 2);
            mbar_init(mb_empty + s * 8, 1);
        }
    }
    __syncthreads();
    CLUSTER_SYNC();   // peer mbarriers live before any cluster arrivals / peer smem reads

    uint32_t tmem;
    asm volatile("ld.shared.b32 %0, [%1];" : "=r"(tmem) : "r"(sbase));

    // producer mapping: all four 16KB tiles are 128 rows x 128B SW128.
    // thread t -> row t>>1, 64B half (t&1); 4 x 16B cp.async per tile.
    const int r  = tid >> 1;
    const int hh = tid & 1;
    const uint32_t off = r * 128 + hh * 64;
    const __nv_bfloat16* AgH = Ah + (size_t)(bm + rank * 128 + r) * K + hh * 32;
    const __nv_bfloat16* AgL = Al + (size_t)(bm + rank * 128 + r) * K + hh * 32;
    const __nv_bfloat16* BgH = Bh + (size_t)(bn + rank * 128 + r) * K + hh * 32;
    const __nv_bfloat16* BgL = Bl + (size_t)(bn + rank * 128 + r) * K + hh * 32;

    const int n = K >> 6;

    auto do_mma = [&](int i) {   // rank0, tid0 only
        const int si = i % NSTAGE;
        mbar_wait(mb_f2 + si * 8, (i / NSTAGE) & 1);
        asm volatile("fence.proxy.async.shared::cta;" ::: "memory");
        const uint32_t sbi = tile_abs + si * STAGE_BYTES;
        const uint64_t ah = mkdesc(sbi);
        const uint64_t al = mkdesc(sbi + 16384);
        const uint64_t bh = mkdesc(sbi + 32768);
        const uint64_t bl = mkdesc(sbi + 49152);
#pragma unroll
        for (int k = 0; k < 4; k++)
            mma_bf16_ss_cg2(tmem, ah + k * 2, bh + k * 2, (i > 0 || k > 0) ? 1u : 0u);
#pragma unroll
        for (int k = 0; k < 4; k++)
            mma_bf16_ss_cg2(tmem, ah + k * 2, bl + k * 2, 1u);
#pragma unroll
        for (int k = 0; k < 4; k++)
            mma_bf16_ss_cg2(tmem, al + k * 2, bh + k * 2, 1u);
        tc_commit_mc2(mb_empty + si * 8);
    };

    for (int c = 0; c < n; c++) {
        const int s = c % NSTAGE;
        const int use = c / NSTAGE;
        if (c >= NSTAGE) mbar_wait(mb_empty + s * 8, (use - 1) & 1);

        const uint32_t sb = tile_abs + s * STAGE_BYTES;
        const size_t kof = (size_t)c * 64;
#pragma unroll
        for (int j = 0; j < 4; j++) {
            const uint32_t o = SW128(off + j * 16);
            cpasync16(sb + o,         AgH + kof + j * 8);
            cpasync16(sb + 16384 + o, AgL + kof + j * 8);
            cpasync16(sb + 32768 + o, BgH + kof + j * 8);
            cpasync16(sb + 49152 + o, BgL + kof + j * 8);
        }
        cp_arrive(mb_full + s * 8);

        if (tid == 0 && c >= 1) {
            const int i = c - 1, si = i % NSTAGE;
            // relay: local data landed -> arrive leader's cluster barrier
            mbar_wait(mb_full + si * 8, (i / NSTAGE) & 1);
            mbar_arrive_rank0(mb_f2 + si * 8);
            if (rank == 0) do_mma(i);
        }
    }

    if (tid == 0) {   // tail chunk
        const int i = n - 1, si = i % NSTAGE;
        mbar_wait(mb_full + si * 8, (i / NSTAGE) & 1);
        mbar_arrive_rank0(mb_f2 + si * 8);
        if (rank == 0) do_mma(i);
    }

    // all threads wait for the final chunk's MMA completion (multicast commit)
    {
        const int i = n - 1, si = i % NSTAGE;
        mbar_wait(mb_empty + si * 8, (i / NSTAGE) & 1);
    }
    asm volatile("tcgen05.fence::after_thread_sync;" ::: "memory");

    // epilogue: this CTA's TMEM holds its 128 M-rows x 256 cols.
    // warp w -> rows (w&3)*32..+31, col half (w>>2)*128; 2 x 32-col groups per half.
    const int sub  = wid & 3;
    const int half = wid >> 2;
    const int row  = bm + rank * 128 + sub * 32 + lane;
    const float* rrow = resid ? resid + (size_t)row * N : nullptr;
    float* crow = C + (size_t)row * N;
#pragma unroll 1
    for (int c32 = 0; c32 < 2; c32++) {
        uint32_t d[32];
        ldtm32(d, tmem + half * 64 + c32 * 32);
        asm volatile("tcgen05.wait::ld.sync.aligned;" ::: "memory");
        const int col0 = bn + half * 64 + c32 * 32;
        if (rrow) {
#pragma unroll
            for (int j = 0; j < 32; j++)
                crow[col0 + j] = __uint_as_float(d[j]) + bias[col0 + j] + rrow[col0 + j];
        } else {
#pragma unroll
            for (int j = 0; j < 32; j++)
                crow[col0 + j] = __uint_as_float(d[j]) + bias[col0 + j];
        }
    }
#pragma unroll 1
    for (int c32 = 0; c32 < 2; c32++) {
        uint32_t d[32];
        ldtm32(d, tmem + 128 + half * 64 + c32 * 32);
        asm volatile("tcgen05.wait::ld.sync.aligned;" ::: "memory");
        const int col0 = bn + 128 + half * 64 + c32 * 32;
        if (rrow) {
#pragma unroll
            for (int j = 0; j < 32; j++)
                crow[col0 + j] = __uint_as_float(d[j]) + bias[col0 + j] + rrow[col0 + j];
        } else {
#pragma unroll
            for (int j = 0; j < 32; j++)
                crow[col0 + j] = __uint_as_float(d[j]) + bias[col0 + j];
        }
    }
    __syncthreads();
    if (wid == 0) {
        asm volatile("tcgen05.dealloc.cta_group::2.sync.aligned.b32 %0, %1;"
                     :: "r"(tmem), "r"(256u));
    }
    CLUSTER_SYNC();   // no CTA exits while peer smem may still be referenced
#else
    // ---------- baseline-PTX fallback: SIMT, reconstruct fp32 = hi + lo ----------
    float* As = (float*)smem;            // [8][128]
    float* Bs = As + 8 * 128;            // [8][128]
    const int tid = threadIdx.x;
    const int rank = blockIdx.x & 1;
    const int bm = blockIdx.y * 256 + rank * 128;
    const int bn0 = (blockIdx.x >> 1) * 256;
    const int lr  = tid >> 1;
    const int lcc = (tid & 1) * 4;
    const int tx = tid & 15, ty = tid >> 4;

    for (int h = 0; h < 2; h++) {
        const int bn = bn0 + h * 128;
        float acc[8][8];
#pragma unroll
        for (int i = 0; i < 8; i++)
#pragma unroll
            for (int j = 0; j < 8; j++) acc[i][j] = 0.f;

        for (int k0 = 0; k0 < K; k0 += 8) {
            const __nv_bfloat16* aph = Ah + (size_t)(bm + lr) * K + k0 + lcc;
            const __nv_bfloat16* apl = Al + (size_t)(bm + lr) * K + k0 + lcc;
            const __nv_bfloat16* bph = Bh + (size_t)(bn + lr) * K + k0 + lcc;
            const __nv_bfloat16* bpl = Bl + (size_t)(bn + lr) * K + k0 + lcc;
#pragma unroll
            for (int j = 0; j < 4; j++) {
                As[(lcc + j) * 128 + lr] = __bfloat162float(aph[j]) + __bfloat162float(apl[j]);
                Bs[(lcc + j) * 128 + lr] = __bfloat162float(bph[j]) + __bfloat162float(bpl[j]);
            }
            __syncthreads();
#pragma unroll
            for (int kk = 0; kk < 8; kk++) {
                float a[8], bb[8];
#pragma unroll
                for (int i = 0; i < 8; i++)
                    a[i] = As[kk * 128 + ((i & 4) << 4) + ty * 4 + (i & 3)];
#pragma unroll
                for (int j = 0; j < 8; j++)
                    bb[j] = Bs[kk * 128 + ((j & 4) << 4) + tx * 4 + (j & 3)];
#pragma unroll
                for (int i = 0; i < 8; i++)
#pragma unroll
                    for (int j = 0; j < 8; j++)
                        acc[i][j] += a[i] * bb[j];
            }
            __syncthreads();
        }

#pragma unroll
        for (int i = 0; i < 8; i++) {
            const int row = bm + ((i & 4) << 4) + ty * 4 + (i & 3);
#pragma unroll
            for (int j = 0; j < 8; j++) {
                const int col = bn + ((j & 4) << 4) + tx * 4 + (j & 3);
                float vv = acc[i][j] + bias[col];
                if (resid) vv += resid[(size_t)row * N + col];
                C[(size_t)row * N + col] = vv;
            }
        }
    }
#endif
}

// ---------------- LayerNorm ----------------
__global__ void __launch_bounds__(256) ln_kernel(const float* __restrict__ x,
                                                 const float* __restrict__ g,
                                                 const float* __restrict__ b,
                                                 float* __restrict__ out)
{
    const int row = blockIdx.x;
    const int tid = threadIdx.x;
    const float* xr = x + (size_t)row * Dd;
    __shared__ float red[256];

    float s = 0.f;
    for (int i = tid; i < Dd; i += 256) s += xr[i];
    red[tid] = s; __syncthreads();
    for (int off = 128; off > 0; off >>= 1) {
        if (tid < off) red[tid] += red[tid + off];
        __syncthreads();
    }
    const float mean = red[0] * (1.f / Dd);
    __syncthreads();

    float v = 0.f;
    for (int i = tid; i < Dd; i += 256) { float d = xr[i] - mean; v += d * d; }
    red[tid] = v; __syncthreads();
    for (int off = 128; off > 0; off >>= 1) {
        if (tid < off) red[tid] += red[tid + off];
        __syncthreads();
    }
    const float rstd = rsqrtf(red[0] * (1.f / Dd) + 1e-5f);

    float* orow = out + (size_t)row * Dd;
    for (int i = tid; i < Dd; i += 256)
        orow[i] = (xr[i] - mean) * rstd * g[i] + b[i];
}

// ---------------- RoPE (head-indexed freqs, faithful to reference) ----------------
__global__ void rope_kernel(float* __restrict__ q, float* __restrict__ k,
                            const float* __restrict__ fr)
{
    const int idx = blockIdx.x * blockDim.x + threadIdx.x;
    const int j  = idx & 63;
    const int h  = (idx >> 6) & 15;
    const int bt = idx >> 10;
    const size_t base = (size_t)bt * Dd + h * HDd + 2 * j;
    const float cr = fr[h * 128 + 2 * j];
    const float ci = fr[h * 128 + 2 * j + 1];
    float a = q[base], b2 = q[base + 1];
    q[base]     = a * cr - b2 * ci;
    q[base + 1] = a * ci + b2 * cr;
    a = k[base]; b2 = k[base + 1];
    k[base]     = a * cr - b2 * ci;
    k[base + 1] = a * ci + b2 * cr;
}

// ---------------- Flash attention, causal, fp32, HD=128 ----------------
__global__ void __launch_bounds__(256) flash_kernel(const float* __restrict__ Q,
                                                    const float* __restrict__ K,
                                                    const float* __restrict__ V,
                                                    float* __restrict__ Out)
{
    extern __shared__ float sm[];
    float* sQ = sm;
    float* sK = sm + 64 * 128;
    float* sV = sm + 2 * 64 * 128;
    float* sP = sm + 3 * 64 * 128;

    const int tid = threadIdx.x;
    const int qb = blockIdx.x, h = blockIdx.y, b = blockIdx.z;
    const int q0 = qb * 64;
    const size_t qbase = ((size_t)(b * Tt + q0)) * Dd + h * HDd;

#pragma unroll
    for (int it = 0; it < 8; it++) {
        int f = tid + it * 256;
        int r = f >> 5, c = f & 31;
        *(float4*)(sQ + r * 128 + c * 4) =
            *(const float4*)(Q + qbase + (size_t)r * Dd + c * 4);
    }

    const int qi = tid >> 2;
    const int lc = tid & 3;
    const int rp = ((tid >> 2) + 2 * lc) & 7;
    const int dbase = lc * 32;
    const float scale = 0.088388347648318447f;

    float4 O[8];
#pragma unroll
    for (int i = 0; i < 8; i++) O[i] = make_float4(0.f, 0.f, 0.f, 0.f);
    float mrow = -1e30f, lrow = 0.f;

    for (int kb = 0; kb <= qb; kb++) {
        const int j0 = kb * 64;
        const size_t kbase = ((size_t)(b * Tt + j0)) * Dd + h * HDd;
#pragma unroll
        for (int it = 0; it < 8; it++) {
            int f = tid + it * 256;
            int r = f >> 5, c = f & 31;
            *(float4*)(sK + r * 128 + c * 4) =
                *(const float4*)(K + kbase + (size_t)r * Dd + c * 4);
            *(float4*)(sV + r * 128 + c * 4) =
                *(const float4*)(V + kbase + (size_t)r * Dd + c * 4);
        }
        __syncthreads();

        float acc[16];
#pragma unroll
        for (int kk = 0; kk < 16; kk++) acc[kk] = 0.f;

#pragma unroll
        for (int ch = 0; ch < 4; ch++) {
            float4 qreg[8];
#pragma unroll
            for (int i = 0; i < 8; i++) {
                int g = (i + rp) & 7;
                qreg[i] = *(const float4*)(sQ + qi * 128 + ch * 32 + g * 4);
            }
#pragma unroll
            for (int kk = 0; kk < 16; kk++) {
                const float* kr = sK + (lc * 16 + kk) * 128 + ch * 32;
                float s = 0.f;
#pragma unroll
                for (int i = 0; i < 8; i++) {
                    int g = (i + rp) & 7;
                    float4 kv = *(const float4*)(kr + g * 4);
                    s += qreg[i].x * kv.x + qreg[i].y * kv.y
                       + qreg[i].z * kv.z + qreg[i].w * kv.w;
                }
                acc[kk] += s;
            }
        }

        float tmax = -1e30f;
#pragma unroll
        for (int kk = 0; kk < 16; kk++) {
            float s = acc[kk] * scale;
            if (j0 + lc * 16 + kk > q0 + qi) s = -1e30f;
            acc[kk] = s;
            tmax = fmaxf(tmax, s);
        }
        tmax = fmaxf(tmax, __shfl_xor_sync(0xffffffffu, tmax, 1));
        tmax = fmaxf(tmax, __shfl_xor_sync(0xffffffffu, tmax, 2));
        const float mnew = fmaxf(mrow, tmax);
        const float alpha = __expf(mrow - mnew);
        mrow = mnew;

        float psum = 0.f;
#pragma unroll
        for (int kk = 0; kk < 16; kk++) {
            float p = __expf(acc[kk] - mnew);
            psum += p;
            sP[qi * 68 + lc * 16 + kk] = p;
        }
        psum += __shfl_xor_sync(0xffffffffu, psum, 1);
        psum += __shfl_xor_sync(0xffffffffu, psum, 2);
        lrow = lrow * alpha + psum;
#pragma unroll
        for (int i = 0; i < 8; i++) {
            O[i].x *= alpha; O[i].y *= alpha; O[i].z *= alpha; O[i].w *= alpha;
        }
        __syncthreads();

#pragma unroll 4
        for (int k2 = 0; k2 < 64; k2++) {
            const float pv = sP[qi * 68 + k2];
            const float* vr = sV + k2 * 128 + dbase;
#pragma unroll
            for (int i = 0; i < 8; i++) {
                int g = (i + rp) & 7;
                float4 vv = *(const float4*)(vr + g * 4);
                O[i].x += pv * vv.x; O[i].y += pv * vv.y;
                O[i].z += pv * vv.z; O[i].w += pv * vv.w;
            }
        }
        __syncthreads();
    }

    const float inv = 1.f / lrow;
    const size_t obase = ((size_t)(b * Tt + q0 + qi)) * Dd + h * HDd + dbase;
#pragma unroll
    for (int i = 0; i < 8; i++) {
        int g = (i + rp) & 7;
        float4 o = O[i];
        o.x *= inv; o.y *= inv; o.z *= inv; o.w *= inv;
        *(float4*)(Out + obase + g * 4) = o;
    }
}

// ---------------- fused SiLU(gate)*up ----------------
__global__ void silu_mul_kernel(float* __restrict__ gbuf, const float* __restrict__ ubuf)
{
    const int idx = blockIdx.x * blockDim.x + threadIdx.x;
    const float gt = gbuf[idx];
    const float s = gt / (1.f + __expf(-gt));
    gbuf[idx] = s * ubuf[idx];
}

// ---------------- launch ----------------
extern "C" void kernel_launch(void* const* d_in, const int* in_sizes, int n_in,
                              void* d_out, int out_size)
{
    const float* x   = (const float*)d_in[0];
    const float* fr  = (const float*)d_in[1];
    const float* Wq  = (const float*)d_in[2];
    const float* bq  = (const float*)d_in[3];
    const float* Wk  = (const float*)d_in[4];
    const float* bk  = (const float*)d_in[5];
    const float* Wv  = (const float*)d_in[6];
    const float* bv  = (const float*)d_in[7];
    const float* Wo  = (const float*)d_in[8];
    const float* bo  = (const float*)d_in[9];
    const float* g1  = (const float*)d_in[10];
    const float* be1 = (const float*)d_in[11];
    const float* g2  = (const float*)d_in[12];
    const float* be2 = (const float*)d_in[13];
    const float* Wg  = (const float*)d_in[14];
    const float* bg  = (const float*)d_in[15];
    const float* Wu  = (const float*)d_in[16];
    const float* bu  = (const float*)d_in[17];
    const float* Wd  = (const float*)d_in[18];
    const float* bd  = (const float*)d_in[19];
    float* out = (float*)d_out;

    float *xn, *q, *k, *v, *attn, *ff1, *ff2;
    __nv_bfloat16 *Ahi, *Alo, *Bhi, *Blo;
    cudaGetSymbolAddress((void**)&xn,   g_xn);
    cudaGetSymbolAddress((void**)&q,    g_q);
    cudaGetSymbolAddress((void**)&k,    g_k);
    cudaGetSymbolAddress((void**)&v,    g_v);
    cudaGetSymbolAddress((void**)&attn, g_attn);
    cudaGetSymbolAddress((void**)&ff1,  g_ff1);
    cudaGetSymbolAddress((void**)&ff2,  g_ff2);
    cudaGetSymbolAddress((void**)&Ahi,  g_Ahi);
    cudaGetSymbolAddress((void**)&Alo,  g_Alo);
    cudaGetSymbolAddress((void**)&Bhi,  g_Bhi);
    cudaGetSymbolAddress((void**)&Blo,  g_Blo);

    const int smemF = (3 * 64 * 128 + 64 * 68) * (int)sizeof(float);   // 113 KB
    cudaFuncSetAttribute(flash_kernel, cudaFuncAttributeMaxDynamicSharedMemorySize, smemF);
    cudaFuncSetAttribute(mma_gemm_kernel, cudaFuncAttributeMaxDynamicSharedMemorySize, GEMM_SMEM);

    const int DD  = ROWS * Dd;   // 8M
    const int DW  = Dd * Dd;     // 4M
    const int FW  = FFd * Dd;    // 16M
    const int DF  = ROWS * FFd;  // 32M

#define SPLIT(src, hi, lo, n) split_kernel<<<((n)/4 + 255)/256, 256>>>(src, hi, lo, (n)/4)

    // 1) LN1
    ln_kernel<<<ROWS, 256>>>(x, g1, be1, xn);

    // 2) Q,K,V projections
    SPLIT(xn, Ahi, Alo, DD);
    dim3 gD(2 * (Dd / 256), ROWS / 256);    // (16,16) cg2 pairs
    SPLIT(Wq, Bhi, Blo, DW);
    mma_gemm_kernel<<<gD, 256, GEMM_SMEM>>>(Ahi, Alo, Bhi, Blo, bq, nullptr, q, ROWS, Dd, Dd);
    SPLIT(Wk, Bhi, Blo, DW);
    mma_gemm_kernel<<<gD, 256, GEMM_SMEM>>>(Ahi, Alo, Bhi, Blo, bk, nullptr, k, ROWS, Dd, Dd);
    SPLIT(Wv, Bhi, Blo, DW);
    mma_gemm_kernel<<<gD, 256, GEMM_SMEM>>>(Ahi, Alo, Bhi, Blo, bv, nullptr, v, ROWS, Dd, Dd);

    // 3) RoPE
    rope_kernel<<<(Bb * Tt * Hh * (HDd / 2)) / 256, 256>>>(q, k, fr);

    // 4) causal flash attention
    flash_kernel<<<dim3(Tt / 64, Hh, Bb), 256, smemF>>>(q, k, v, attn);

    // 5) output projection + residual(x) -> out
    SPLIT(attn, Ahi, Alo, DD);
    SPLIT(Wo, Bhi, Blo, DW);
    mma_gemm_kernel<<<gD, 256, GEMM_SMEM>>>(Ahi, Alo, Bhi, Blo, bo, x, out, ROWS, Dd, Dd);

    // 6) LN2
    ln_kernel<<<ROWS, 256>>>(out, g2, be2, xn);

    // 7) gate / up
    SPLIT(xn, Ahi, Alo, DD);
    dim3 gF(2 * (FFd / 256), ROWS / 256);   // (64,16)
    SPLIT(Wg, Bhi, Blo, FW);
    mma_gemm_kernel<<<gF, 256, GEMM_SMEM>>>(Ahi, Alo, Bhi, Blo, bg, nullptr, ff1, ROWS, FFd, Dd);
    SPLIT(Wu, Bhi, Blo, FW);
    mma_gemm_kernel<<<gF, 256, GEMM_SMEM>>>(Ahi, Alo, Bhi, Blo, bu, nullptr, ff2, ROWS, FFd, Dd);

    // 8) SiLU(gate)*up
    silu_mul_kernel<<<(ROWS * FFd) / 256, 256>>>(ff1, ff2);

    // 9) down projection + residual(out) -> out
    SPLIT(ff1, Ahi, Alo, DF);
    SPLIT(Wd, Bhi, Blo, FW);
    mma_gemm_kernel<<<gD, 256, GEMM_SMEM>>>(Ahi, Alo, Bhi, Blo, bd, out, out, ROWS, Dd, FFd);
}

// round 9
// speedup vs baseline: 5.6142x; 1.7592x over previous
#include <cuda_runtime.h>
#include <cuda_bf16.h>
#include <cstdint>
#include <math.h>

#define Bb 2
#define Tt 2048
#define Dd 2048
#define Hh 16
#define HDd 128
#define FFd 8192
#define ROWS (Bb*Tt)   /* 4096 */

// tcgen05 only exists in arch-specific (sm_10xa) compilation phases.
#if defined(__CUDA_ARCH_FEAT_SM103_ALL) || defined(__CUDA_ARCH_FEAT_SM100_ALL) || \
    defined(__CUDA_ARCH_FEAT_SM101_ALL) || \
    (defined(__CUDA_ARCH_SPECIFIC__) && (__CUDA_ARCH_SPECIFIC__ >= 1000)) || \
    (defined(__CUDA_ARCH_FAMILY_SPECIFIC__) && (__CUDA_ARCH_FAMILY_SPECIFIC__ >= 1000))
#define HAS_TCGEN05 1
#else
#define HAS_TCGEN05 0
#endif

// ---------------- scratch (no allocations allowed -> device globals) ----------------
__device__ float g_xn  [ROWS*Dd];
__device__ float g_q   [ROWS*Dd];
__device__ float g_k   [ROWS*Dd];
__device__ float g_v   [ROWS*Dd];
__device__ float g_attn[ROWS*Dd];
__device__ float g_ff1 [ROWS*FFd];
__device__ float g_ff2 [ROWS*FFd];
// bf16 split buffers (GEMM)
__device__ __nv_bfloat16 g_Ahi[ROWS*FFd];
__device__ __nv_bfloat16 g_Alo[ROWS*FFd];
__device__ __nv_bfloat16 g_Bhi[FFd*Dd];
__device__ __nv_bfloat16 g_Blo[FFd*Dd];
// bf16 split buffers (flash): Q/K in [b,t,h*hd]; Vt in [b,h,hd,t]
__device__ __nv_bfloat16 g_fQh[ROWS*Dd];
__device__ __nv_bfloat16 g_fQl[ROWS*Dd];
__device__ __nv_bfloat16 g_fKh[ROWS*Dd];
__device__ __nv_bfloat16 g_fKl[ROWS*Dd];
__device__ __nv_bfloat16 g_fVh[ROWS*Dd];
__device__ __nv_bfloat16 g_fVl[ROWS*Dd];

// ================= helpers =================
__device__ __forceinline__ uint32_t smem_u32(const void* p) {
    uint32_t a;
    asm("{ .reg .u64 t; cvta.to.shared.u64 t, %1; cvt.u32.u64 %0, t; }"
        : "=r"(a) : "l"(p));
    return a;
}

#define SW128(o) ((o) ^ (((o) >> 3) & 0x70))

static constexpr uint64_t DESC_BASE_SW128 =
    (uint64_t(2)  << 61) | (uint64_t(1) << 46) | (uint64_t(64) << 32) | (uint64_t(1) << 16);

// idescs (kind::f16): dtype=F32(1<<4), atype/btype=BF16
#define MMA_IDESC_CG2 0x10400490u   /* M=256, N=256 */
#define MMA_IDESC_QK  0x08100490u   /* M=128, N=64  */
#define MMA_IDESC_PV  0x08200490u   /* M=128, N=128 */

#if HAS_TCGEN05
__device__ __forceinline__ uint64_t mkdesc(uint32_t addr) {
    return DESC_BASE_SW128 | ((uint64_t)(addr >> 4) & 0x3FFF);
}
__device__ __forceinline__ void mma_bf16_ss_cg2(uint32_t d, uint64_t ad, uint64_t bd, uint32_t en) {
    asm volatile(
        "{\n\t.reg .pred p;\n\tsetp.ne.u32 p, %4, 0;\n\t"
        "tcgen05.mma.cta_group::2.kind::f16 [%0], %1, %2, %3, {%5,%5,%5,%5,%5,%5,%5,%5}, p;\n\t}"
        :: "r"(d), "l"(ad), "l"(bd), "r"(MMA_IDESC_CG2), "r"(en), "r"(0u) : "memory");
}
__device__ __forceinline__ void mma_ss_cg1(uint32_t d, uint64_t ad, uint64_t bd,
                                           uint32_t idesc, uint32_t en) {
    asm volatile(
        "{\n\t.reg .pred p;\n\tsetp.ne.u32 p, %4, 0;\n\t"
        "tcgen05.mma.cta_group::1.kind::f16 [%0], %1, %2, %3, {%5,%5,%5,%5}, p;\n\t}"
        :: "r"(d), "l"(ad), "l"(bd), "r"(idesc), "r"(en), "r"(0u) : "memory");
}
__device__ __forceinline__ void mbar_init(uint32_t m, uint32_t cnt) {
    asm volatile("mbarrier.init.shared.b64 [%0], %1;" :: "r"(m), "r"(cnt) : "memory");
}
__device__ __forceinline__ void mbar_wait(uint32_t m, uint32_t parity) {
    asm volatile(
        "{\n\t.reg .pred P1;\n"
        "W%=:\n\t"
        "mbarrier.try_wait.parity.acquire.cta.shared::cta.b64 P1, [%0], %1, 0x989680;\n\t"
        "@P1 bra.uni D%=;\n\t"
        "bra.uni W%=;\n"
        "D%=:\n\t}"
        :: "r"(m), "r"(parity) : "memory");
}
__device__ __forceinline__ void tc_commit_cg1(uint32_t m) {
    asm volatile("tcgen05.commit.cta_group::1.mbarrier::arrive::one.shared::cluster.b64 [%0];"
                 :: "r"(m) : "memory");
}
__device__ __forceinline__ void tc_commit_mc2(uint32_t m) {
    asm volatile(
        "tcgen05.commit.cta_group::2.mbarrier::arrive::one.shared::cluster.multicast::cluster.b64 [%0], %1;"
        :: "r"(m), "h"((uint16_t)0x3) : "memory");
}
__device__ __forceinline__ void mbar_arrive_rank0(uint32_t local_addr) {
    asm volatile(
        "{\n\t.reg .b32 ra;\n\t"
        "mapa.shared::cluster.u32 ra, %0, %1;\n\t"
        "mbarrier.arrive.shared::cluster.b64 _, [ra];\n\t}"
        :: "r"(local_addr), "r"(0) : "memory");
}
__device__ __forceinline__ void ldtm32(uint32_t* r, uint32_t a) {
    asm volatile(
        "tcgen05.ld.sync.aligned.32x32b.x32.b32 "
        "{%0,%1,%2,%3,%4,%5,%6,%7,%8,%9,%10,%11,%12,%13,%14,%15,"
        "%16,%17,%18,%19,%20,%21,%22,%23,%24,%25,%26,%27,%28,%29,%30,%31}, [%32];"
        : "=r"(r[0]),"=r"(r[1]),"=r"(r[2]),"=r"(r[3]),"=r"(r[4]),"=r"(r[5]),"=r"(r[6]),"=r"(r[7]),
          "=r"(r[8]),"=r"(r[9]),"=r"(r[10]),"=r"(r[11]),"=r"(r[12]),"=r"(r[13]),"=r"(r[14]),"=r"(r[15]),
          "=r"(r[16]),"=r"(r[17]),"=r"(r[18]),"=r"(r[19]),"=r"(r[20]),"=r"(r[21]),"=r"(r[22]),"=r"(r[23]),
          "=r"(r[24]),"=r"(r[25]),"=r"(r[26]),"=r"(r[27]),"=r"(r[28]),"=r"(r[29]),"=r"(r[30]),"=r"(r[31])
        : "r"(a));
}
__device__ __forceinline__ void sttm32(uint32_t a, const uint32_t* r) {
    asm volatile(
        "tcgen05.st.sync.aligned.32x32b.x32.b32 [%32], "
        "{%0,%1,%2,%3,%4,%5,%6,%7,%8,%9,%10,%11,%12,%13,%14,%15,"
        "%16,%17,%18,%19,%20,%21,%22,%23,%24,%25,%26,%27,%28,%29,%30,%31};"
        :: "r"(r[0]),"r"(r[1]),"r"(r[2]),"r"(r[3]),"r"(r[4]),"r"(r[5]),"r"(r[6]),"r"(r[7]),
           "r"(r[8]),"r"(r[9]),"r"(r[10]),"r"(r[11]),"r"(r[12]),"r"(r[13]),"r"(r[14]),"r"(r[15]),
           "r"(r[16]),"r"(r[17]),"r"(r[18]),"r"(r[19]),"r"(r[20]),"r"(r[21]),"r"(r[22]),"r"(r[23]),
           "r"(r[24]),"r"(r[25]),"r"(r[26]),"r"(r[27]),"r"(r[28]),"r"(r[29]),"r"(r[30]),"r"(r[31]),
           "r"(a)
        : "memory");
}
__device__ __forceinline__ void cpasync16(uint32_t dst, const void* src) {
    asm volatile("cp.async.cg.shared.global [%0], [%1], 16;" :: "r"(dst), "l"(src) : "memory");
}
__device__ __forceinline__ void cp_arrive(uint32_t m) {
    asm volatile("cp.async.mbarrier.arrive.noinc.shared.b64 [%0];" :: "r"(m) : "memory");
}
#define CP_COMMIT() asm volatile("cp.async.commit_group;" ::: "memory")
#define CP_WAIT0()  asm volatile("cp.async.wait_group 0;" ::: "memory")
#define TC_WAIT_LD() asm volatile("tcgen05.wait::ld.sync.aligned;" ::: "memory")
#define TC_WAIT_ST() asm volatile("tcgen05.wait::st.sync.aligned;" ::: "memory")
#define TC_FENCE_BEFORE() asm volatile("tcgen05.fence::before_thread_sync;" ::: "memory")
#define TC_FENCE_AFTER()  asm volatile("tcgen05.fence::after_thread_sync;" ::: "memory")
#define CLUSTER_SYNC() do { \
    asm volatile("barrier.cluster.arrive.aligned;" ::: "memory"); \
    asm volatile("barrier.cluster.wait.aligned;" ::: "memory"); \
} while (0)
#endif  // HAS_TCGEN05

// ---------------- split fp32 -> bf16 hi/lo ----------------
__global__ void __launch_bounds__(256) split_kernel(const float* __restrict__ src,
                                                    __nv_bfloat16* __restrict__ hi,
                                                    __nv_bfloat16* __restrict__ lo,
                                                    int n4)
{
    int idx = blockIdx.x * blockDim.x + threadIdx.x;
    if (idx >= n4) return;
    float4 v = ((const float4*)src)[idx];
    __nv_bfloat162 h0 = __floats2bfloat162_rn(v.x, v.y);
    __nv_bfloat162 h1 = __floats2bfloat162_rn(v.z, v.w);
    float lx = v.x - __bfloat162float(__low2bfloat16(h0));
    float ly = v.y - __bfloat162float(__high2bfloat16(h0));
    float lz = v.z - __bfloat162float(__low2bfloat16(h1));
    float lw = v.w - __bfloat162float(__high2bfloat16(h1));
    __nv_bfloat162 l0 = __floats2bfloat162_rn(lx, ly);
    __nv_bfloat162 l1 = __floats2bfloat162_rn(lz, lw);
    uint2 ho, loo;
    ho.x  = *reinterpret_cast<uint32_t*>(&h0);
    ho.y  = *reinterpret_cast<uint32_t*>(&h1);
    loo.x = *reinterpret_cast<uint32_t*>(&l0);
    loo.y = *reinterpret_cast<uint32_t*>(&l1);
    ((uint2*)hi)[idx] = ho;
    ((uint2*)lo)[idx] = loo;
}

// ---------------- V transpose+split: v[b,t,h*hd] -> Vt[b,h,hd,t] bf16 hi/lo ----------------
__global__ void __launch_bounds__(256) vtrans_kernel(const float* __restrict__ v,
                                                     __nv_bfloat16* __restrict__ Vth,
                                                     __nv_bfloat16* __restrict__ Vtl)
{
    __shared__ float tile[32][33];
    const int bh = blockIdx.z;
    const int b  = bh >> 4, h = bh & 15;
    const int t0 = blockIdx.x * 32;
    const int d0 = blockIdx.y * 32;
    const int x = threadIdx.x, y = threadIdx.y;  // (32,8)
#pragma unroll
    for (int i = 0; i < 4; i++) {
        int t = t0 + y + i * 8;
        tile[y + i * 8][x] = v[(size_t)(b * Tt + t) * Dd + h * HDd + d0 + x];
    }
    __syncthreads();
#pragma unroll
    for (int i = 0; i < 4; i++) {
        int hd = d0 + y + i * 8;
        float val = tile[x][y + i * 8];
        __nv_bfloat16 hi = __float2bfloat16(val);
        __nv_bfloat16 lo = __float2bfloat16(val - __bfloat162float(hi));
        size_t idx = (size_t)(bh * HDd + hd) * Tt + t0 + x;
        Vth[idx] = hi;
        Vtl[idx] = lo;
    }
}

// ============ cg2 GEMM (unchanged from R8, passing) ============
#define NSTAGE 3
#define STAGE_BYTES 65536
#define GEMM_SMEM (1024 + NSTAGE * STAGE_BYTES)

__global__ void __launch_bounds__(256, 1) __cluster_dims__(2, 1, 1)
mma_gemm_kernel(const __nv_bfloat16* __restrict__ Ah, const __nv_bfloat16* __restrict__ Al,
                const __nv_bfloat16* __restrict__ Bh, const __nv_bfloat16* __restrict__ Bl,
                const float* __restrict__ bias, const float* __restrict__ resid,
                float* __restrict__ C, int M, int N, int K)
{
    extern __shared__ char smem[];
#if HAS_TCGEN05
    const uint32_t sbase = smem_u32(smem);
    const int tid  = threadIdx.x;
    const int wid  = tid >> 5;
    const int lane = tid & 31;
    const int rank = blockIdx.x & 1;
    const int bn   = (blockIdx.x >> 1) * 256;
    const int bm   = blockIdx.y * 256;

    const uint32_t tile_abs = (sbase + 128 + 1023) & ~1023u;
    const uint32_t mb_full  = sbase + 8;
    const uint32_t mb_f2    = sbase + 32;
    const uint32_t mb_empty = sbase + 56;

    if (wid == 0) {
        asm volatile("tcgen05.alloc.cta_group::2.sync.aligned.shared::cta.b32 [%0], %1;"
                     :: "r"(sbase), "r"(256u) : "memory");
        asm volatile("tcgen05.relinquish_alloc_permit.cta_group::2.sync.aligned;");
    }
    if (tid == 0) {
#pragma unroll
        for (int s = 0; s < NSTAGE; s++) {
            mbar_init(mb_full  + s * 8, 256);
            mbar_init(mb_f2    + s * 8, 2);
            mbar_init(mb_empty + s * 8, 1);
        }
    }
    __syncthreads();
    CLUSTER_SYNC();

    uint32_t tmem;
    asm volatile("ld.shared.b32 %0, [%1];" : "=r"(tmem) : "r"(sbase));

    const int r  = tid >> 1;
    const int hh = tid & 1;
    const uint32_t off = r * 128 + hh * 64;
    const __nv_bfloat16* AgH = Ah + (size_t)(bm + rank * 128 + r) * K + hh * 32;
    const __nv_bfloat16* AgL = Al + (size_t)(bm + rank * 128 + r) * K + hh * 32;
    const __nv_bfloat16* BgH = Bh + (size_t)(bn + rank * 128 + r) * K + hh * 32;
    const __nv_bfloat16* BgL = Bl + (size_t)(bn + rank * 128 + r) * K + hh * 32;

    const int n = K >> 6;

    auto do_mma = [&](int i) {
        const int si = i % NSTAGE;
        mbar_wait(mb_f2 + si * 8, (i / NSTAGE) & 1);
        asm volatile("fence.proxy.async.shared::cta;" ::: "memory");
        const uint32_t sbi = tile_abs + si * STAGE_BYTES;
        const uint64_t ah = mkdesc(sbi);
        const uint64_t al = mkdesc(sbi + 16384);
        const uint64_t bh = mkdesc(sbi + 32768);
        const uint64_t bl = mkdesc(sbi + 49152);
#pragma unroll
        for (int k = 0; k < 4; k++)
            mma_bf16_ss_cg2(tmem, ah + k * 2, bh + k * 2, (i > 0 || k > 0) ? 1u : 0u);
#pragma unroll
        for (int k = 0; k < 4; k++)
            mma_bf16_ss_cg2(tmem, ah + k * 2, bl + k * 2, 1u);
#pragma unroll
        for (int k = 0; k < 4; k++)
            mma_bf16_ss_cg2(tmem, al + k * 2, bh + k * 2, 1u);
        tc_commit_mc2(mb_empty + si * 8);
    };

    for (int c = 0; c < n; c++) {
        const int s = c % NSTAGE;
        const int use = c / NSTAGE;
        if (c >= NSTAGE) mbar_wait(mb_empty + s * 8, (use - 1) & 1);

        const uint32_t sb = tile_abs + s * STAGE_BYTES;
        const size_t kof = (size_t)c * 64;
#pragma unroll
        for (int j = 0; j < 4; j++) {
            const uint32_t o = SW128(off + j * 16);
            cpasync16(sb + o,         AgH + kof + j * 8);
            cpasync16(sb + 16384 + o, AgL + kof + j * 8);
            cpasync16(sb + 32768 + o, BgH + kof + j * 8);
            cpasync16(sb + 49152 + o, BgL + kof + j * 8);
        }
        cp_arrive(mb_full + s * 8);

        if (tid == 0 && c >= 1) {
            const int i = c - 1, si = i % NSTAGE;
            mbar_wait(mb_full + si * 8, (i / NSTAGE) & 1);
            mbar_arrive_rank0(mb_f2 + si * 8);
            if (rank == 0) do_mma(i);
        }
    }

    if (tid == 0) {
        const int i = n - 1, si = i % NSTAGE;
        mbar_wait(mb_full + si * 8, (i / NSTAGE) & 1);
        mbar_arrive_rank0(mb_f2 + si * 8);
        if (rank == 0) do_mma(i);
    }

    {
        const int i = n - 1, si = i % NSTAGE;
        mbar_wait(mb_empty + si * 8, (i / NSTAGE) & 1);
    }
    TC_FENCE_AFTER();

    const int sub  = wid & 3;
    const int half = wid >> 2;
    const int row  = bm + rank * 128 + sub * 32 + lane;
    const float* rrow = resid ? resid + (size_t)row * N : nullptr;
    float* crow = C + (size_t)row * N;
#pragma unroll 1
    for (int half2 = 0; half2 < 2; half2++) {
#pragma unroll 1
        for (int c32 = 0; c32 < 2; c32++) {
            uint32_t d[32];
            ldtm32(d, tmem + half2 * 128 + half * 64 + c32 * 32);
            TC_WAIT_LD();
            const int col0 = bn + half2 * 128 + half * 64 + c32 * 32;
            if (rrow) {
#pragma unroll
                for (int j = 0; j < 32; j++)
                    crow[col0 + j] = __uint_as_float(d[j]) + bias[col0 + j] + rrow[col0 + j];
            } else {
#pragma unroll
                for (int j = 0; j < 32; j++)
                    crow[col0 + j] = __uint_as_float(d[j]) + bias[col0 + j];
            }
        }
    }
    __syncthreads();
    if (wid == 0) {
        asm volatile("tcgen05.dealloc.cta_group::2.sync.aligned.b32 %0, %1;"
                     :: "r"(tmem), "r"(256u));
    }
    CLUSTER_SYNC();
#else
    float* As = (float*)smem;
    float* Bs = As + 8 * 128;
    const int tid = threadIdx.x;
    const int rank = blockIdx.x & 1;
    const int bm = blockIdx.y * 256 + rank * 128;
    const int bn0 = (blockIdx.x >> 1) * 256;
    const int lr  = tid >> 1;
    const int lcc = (tid & 1) * 4;
    const int tx = tid & 15, ty = tid >> 4;

    for (int h = 0; h < 2; h++) {
        const int bn = bn0 + h * 128;
        float acc[8][8];
#pragma unroll
        for (int i = 0; i < 8; i++)
#pragma unroll
            for (int j = 0; j < 8; j++) acc[i][j] = 0.f;

        for (int k0 = 0; k0 < K; k0 += 8) {
            const __nv_bfloat16* aph = Ah + (size_t)(bm + lr) * K + k0 + lcc;
            const __nv_bfloat16* apl = Al + (size_t)(bm + lr) * K + k0 + lcc;
            const __nv_bfloat16* bph = Bh + (size_t)(bn + lr) * K + k0 + lcc;
            const __nv_bfloat16* bpl = Bl + (size_t)(bn + lr) * K + k0 + lcc;
#pragma unroll
            for (int j = 0; j < 4; j++) {
                As[(lcc + j) * 128 + lr] = __bfloat162float(aph[j]) + __bfloat162float(apl[j]);
                Bs[(lcc + j) * 128 + lr] = __bfloat162float(bph[j]) + __bfloat162float(bpl[j]);
            }
            __syncthreads();
#pragma unroll
            for (int kk = 0; kk < 8; kk++) {
                float a[8], bb[8];
#pragma unroll
                for (int i = 0; i < 8; i++)
                    a[i] = As[kk * 128 + ((i & 4) << 4) + ty * 4 + (i & 3)];
#pragma unroll
                for (int j = 0; j < 8; j++)
                    bb[j] = Bs[kk * 128 + ((j & 4) << 4) + tx * 4 + (j & 3)];
#pragma unroll
                for (int i = 0; i < 8; i++)
#pragma unroll
                    for (int j = 0; j < 8; j++)
                        acc[i][j] += a[i] * bb[j];
            }
            __syncthreads();
        }

#pragma unroll
        for (int i = 0; i < 8; i++) {
            const int row = bm + ((i & 4) << 4) + ty * 4 + (i & 3);
#pragma unroll
            for (int j = 0; j < 8; j++) {
                const int col = bn + ((j & 4) << 4) + tx * 4 + (j & 3);
                float vv = acc[i][j] + bias[col];
                if (resid) vv += resid[(size_t)row * N + col];
                C[(size_t)row * N + col] = vv;
            }
        }
    }
#endif
}

// ============ tcgen05 flash attention: 128q x 64k tiles, bf16x3 QK and PV ============
// smem layout from tile_abs:
//   Q:  hiA 0, hiB 16K, loA 32K, loB 48K            (4 x 16KB, 128 rows x 128B)
//   K:  64K + buf*16K + half*8K                      (4 x  8KB,  64 rows x 128B)
//   Vt: 96K + buf*16K                                (2 x 16KB, 128 rows x 128B)
//   P:  128K + buf*16K                               (2 x 16KB, 128 rows x 128B)
#define FLASH_SMEM (1024 + 160 * 1024 + 1024)

__global__ void __launch_bounds__(256, 1) flash_mma_kernel(
    const __nv_bfloat16* __restrict__ Qh, const __nv_bfloat16* __restrict__ Ql,
    const __nv_bfloat16* __restrict__ Kh, const __nv_bfloat16* __restrict__ Kl,
    const __nv_bfloat16* __restrict__ Vh, const __nv_bfloat16* __restrict__ Vl,
    float* __restrict__ Out)
{
    extern __shared__ char smem[];
#if HAS_TCGEN05
    const uint32_t sbase = smem_u32(smem);
    const int tid  = threadIdx.x;
    const int wid  = tid >> 5;
    const int lane = tid & 31;
    const int qb = blockIdx.x, h = blockIdx.y, b = blockIdx.z;
    const int q0 = qb * 128;

    const uint32_t mb_qk = sbase + 8;
    const uint32_t mb_pv = sbase + 16;
    int*   flags  = (int*)(smem + 24);        // [4]
    float* redbuf = (float*)(smem + 64);      // [128] alpha / linv
    const uint32_t tile_abs = (sbase + 576 + 1023) & ~1023u;
    const uint32_t tile_off = tile_abs - sbase;

    if (wid == 0) {
        asm volatile("tcgen05.alloc.cta_group::1.sync.aligned.shared::cta.b32 [%0], %1;"
                     :: "r"(sbase), "r"(256u) : "memory");
        asm volatile("tcgen05.relinquish_alloc_permit.cta_group::1.sync.aligned;");
    }
    if (tid == 0) { mbar_init(mb_qk, 1); mbar_init(mb_pv, 1); }
    __syncthreads();
    uint32_t tmem;
    asm volatile("ld.shared.b32 %0, [%1];" : "=r"(tmem) : "r"(sbase));
    const uint32_t tm_S = tmem;        // 64 cols fp32
    const uint32_t tm_O = tmem + 64;   // 128 cols fp32

    // ---- load Q tiles (once): 512 units of 128B, 2 per thread ----
#pragma unroll
    for (int i = 0; i < 2; i++) {
        int u = tid * 2 + i;
        int buf = u >> 8, rem = u & 255, half = rem >> 7, row = rem & 127;
        const __nv_bfloat16* src = (buf ? Ql : Qh)
            + (size_t)(b * Tt + q0 + row) * Dd + h * HDd + half * 64;
        uint32_t dst = tile_abs + buf * 32768 + half * 16384;
        uint32_t off = row * 128;
#pragma unroll
        for (int j = 0; j < 8; j++)
            cpasync16(dst + SW128(off + j * 16), src + j * 8);
    }
    CP_COMMIT();

    const int sw   = wid & 3;          // row group / subpartition
    const int colh = wid >> 2;         // column half for O
    const int row  = sw * 32 + lane;   // handled S/O row (0..127)
    const float scale = 0.088388347648318447f;

    float m = -1e30f, l = 0.f;
    const int nt = 2 * qb + 2;

    for (int t = 0; t < nt; t++) {
        const int j0 = t * 64;
        if (t > 0) mbar_wait(mb_pv, (t - 1) & 1);

        // ---- load K/V tile: 512 units of 128B, 2 per thread ----
#pragma unroll
        for (int i = 0; i < 2; i++) {
            int u = tid * 2 + i;
            const __nv_bfloat16* src;
            uint32_t dst, off;
            if (u < 256) {   // K: 64 rows x 2 half x 2 buf
                int kr = u & 63, half = (u >> 6) & 1, buf = u >> 7;
                src = (buf ? Kl : Kh) + (size_t)(b * Tt + j0 + kr) * Dd + h * HDd + half * 64;
                dst = tile_abs + 65536 + buf * 16384 + half * 8192;
                off = kr * 128;
            } else {         // Vt: 128 rows x 2 buf
                int u2 = u - 256;
                int vr = u2 & 127, buf = u2 >> 7;
                src = (buf ? Vl : Vh) + (size_t)((b * Hh + h) * HDd + vr) * Tt + j0;
                dst = tile_abs + 98304 + buf * 16384;
                off = vr * 128;
            }
#pragma unroll
            for (int j = 0; j < 8; j++)
                cpasync16(dst + SW128(off + j * 16), src + j * 8);
        }
        CP_COMMIT();
        CP_WAIT0();
        __syncthreads();

        // ---- QK^T: S = Qhi@Khi + Qhi@Klo + Qlo@Khi ----
        if (tid == 0) {
            asm volatile("fence.proxy.async.shared::cta;" ::: "memory");
            uint64_t qd[2][2], kd[2][2];
            qd[0][0] = mkdesc(tile_abs);          qd[0][1] = mkdesc(tile_abs + 16384);
            qd[1][0] = mkdesc(tile_abs + 32768);  qd[1][1] = mkdesc(tile_abs + 49152);
            kd[0][0] = mkdesc(tile_abs + 65536);  kd[0][1] = mkdesc(tile_abs + 73728);
            kd[1][0] = mkdesc(tile_abs + 81920);  kd[1][1] = mkdesc(tile_abs + 90112);
            int first = 1;
#pragma unroll
            for (int c3 = 0; c3 < 3; c3++) {
                const int ab = (c3 == 2) ? 1 : 0;
                const int bb = (c3 == 1) ? 1 : 0;
#pragma unroll
                for (int ks = 0; ks < 8; ks++) {
                    const int half = ks >> 2;
                    const uint64_t o = (uint64_t)((ks & 3) * 2);
                    mma_ss_cg1(tm_S, qd[ab][half] + o, kd[bb][half] + o,
                               MMA_IDESC_QK, first ? 0u : 1u);
                    first = 0;
                }
            }
            tc_commit_cg1(mb_qk);
        }
        mbar_wait(mb_qk, t & 1);
        TC_FENCE_AFTER();

        // ---- softmax (warps 0-3) ----
        if (wid < 4) {
            uint32_t sr[64];
            ldtm32(sr,      tm_S);
            ldtm32(sr + 32, tm_S + 32);
            TC_WAIT_LD();
            float sv[64];
            float tmax = -1e30f;
#pragma unroll
            for (int c = 0; c < 64; c++) {
                float x = __uint_as_float(sr[c]) * scale;
                if (j0 + c > q0 + row) x = -1e30f;
                sv[c] = x;
                tmax = fmaxf(tmax, x);
            }
            const float mnew = fmaxf(m, tmax);
            const float alpha = __expf(m - mnew);
            m = mnew;
            float psum = 0.f;
#pragma unroll
            for (int c = 0; c < 64; c++) {
                float p = __expf(sv[c] - mnew);
                sv[c] = p;
                psum += p;
            }
            l = l * alpha + psum;
            // P hi/lo -> smem
            const uint32_t prow = row * 128;
#pragma unroll
            for (int g = 0; g < 16; g++) {
                const int c = g * 4;
                __nv_bfloat162 h0 = __floats2bfloat162_rn(sv[c], sv[c + 1]);
                __nv_bfloat162 h1 = __floats2bfloat162_rn(sv[c + 2], sv[c + 3]);
                float l0a = sv[c]     - __bfloat162float(__low2bfloat16(h0));
                float l1a = sv[c + 1] - __bfloat162float(__high2bfloat16(h0));
                float l2a = sv[c + 2] - __bfloat162float(__low2bfloat16(h1));
                float l3a = sv[c + 3] - __bfloat162float(__high2bfloat16(h1));
                __nv_bfloat162 g0 = __floats2bfloat162_rn(l0a, l1a);
                __nv_bfloat162 g1 = __floats2bfloat162_rn(l2a, l3a);
                uint2 hv, lv;
                hv.x = *reinterpret_cast<uint32_t*>(&h0);
                hv.y = *reinterpret_cast<uint32_t*>(&h1);
                lv.x = *reinterpret_cast<uint32_t*>(&g0);
                lv.y = *reinterpret_cast<uint32_t*>(&g1);
                const uint32_t o = SW128(prow + c * 2);
                *(uint2*)(smem + tile_off + 131072 + o) = hv;
                *(uint2*)(smem + tile_off + 147456 + o) = lv;
            }
            asm volatile("fence.proxy.async.shared::cta;" ::: "memory");
            redbuf[row] = alpha;
            unsigned bal = __ballot_sync(0xffffffffu, alpha < 0.999999f);
            if (lane == 0) flags[wid] = (bal != 0) ? 1 : 0;
        }
        __syncthreads();

        // ---- O rescale (all 8 warps; skip if no row in group changed max) ----
        if (t > 0 && ((volatile int*)flags)[sw]) {
            const float av = ((volatile float*)redbuf)[row];
            uint32_t o0[32], o1[32];
            ldtm32(o0, tm_O + colh * 64);
            ldtm32(o1, tm_O + colh * 64 + 32);
            TC_WAIT_LD();
#pragma unroll
            for (int j = 0; j < 32; j++) {
                o0[j] = __float_as_uint(__uint_as_float(o0[j]) * av);
                o1[j] = __float_as_uint(__uint_as_float(o1[j]) * av);
            }
            sttm32(tm_O + colh * 64,      o0);
            sttm32(tm_O + colh * 64 + 32, o1);
            TC_WAIT_ST();
        }
        TC_FENCE_BEFORE();
        __syncthreads();

        // ---- PV: O += Phi@Vhi + Plo@Vhi + Phi@Vlo ----
        if (tid == 0) {
            TC_FENCE_AFTER();
            asm volatile("fence.proxy.async.shared::cta;" ::: "memory");
            uint64_t pd[2], vd[2];
            pd[0] = mkdesc(tile_abs + 131072); pd[1] = mkdesc(tile_abs + 147456);
            vd[0] = mkdesc(tile_abs + 98304);  vd[1] = mkdesc(tile_abs + 114688);
            int first = (t == 0) ? 1 : 0;
#pragma unroll
            for (int c3 = 0; c3 < 3; c3++) {
                const int ab = (c3 == 1) ? 1 : 0;
                const int bb = (c3 == 2) ? 1 : 0;
#pragma unroll
                for (int ks = 0; ks < 4; ks++) {
                    const uint64_t o = (uint64_t)(ks * 2);
                    mma_ss_cg1(tm_O, pd[ab] + o, vd[bb] + o,
                               MMA_IDESC_PV, first ? 0u : 1u);
                    first = 0;
                }
            }
            tc_commit_cg1(mb_pv);
        }
    }

    mbar_wait(mb_pv, (nt - 1) & 1);
    TC_FENCE_AFTER();
    if (wid < 4) redbuf[row] = 1.f / l;
    __syncthreads();

    // ---- epilogue ----
    {
        const float linv = ((volatile float*)redbuf)[row];
        uint32_t o0[32], o1[32];
        ldtm32(o0, tm_O + colh * 64);
        ldtm32(o1, tm_O + colh * 64 + 32);
        TC_WAIT_LD();
        float* orow = Out + (size_t)(b * Tt + q0 + row) * Dd + h * HDd + colh * 64;
#pragma unroll
        for (int j4 = 0; j4 < 8; j4++) {
            float4 v0;
            v0.x = __uint_as_float(o0[j4 * 4 + 0]) * linv;
            v0.y = __uint_as_float(o0[j4 * 4 + 1]) * linv;
            v0.z = __uint_as_float(o0[j4 * 4 + 2]) * linv;
            v0.w = __uint_as_float(o0[j4 * 4 + 3]) * linv;
            *(float4*)(orow + j4 * 4) = v0;
            float4 v1;
            v1.x = __uint_as_float(o1[j4 * 4 + 0]) * linv;
            v1.y = __uint_as_float(o1[j4 * 4 + 1]) * linv;
            v1.z = __uint_as_float(o1[j4 * 4 + 2]) * linv;
            v1.w = __uint_as_float(o1[j4 * 4 + 3]) * linv;
            *(float4*)(orow + 32 + j4 * 4) = v1;
        }
    }
    __syncthreads();
    if (wid == 0) {
        asm volatile("tcgen05.dealloc.cta_group::1.sync.aligned.b32 %0, %1;"
                     :: "r"(tmem), "r"(256u));
    }
#else
    // ---------- correctness-only fallback (slow; never runs on sm_103a) ----------
    const int tid = threadIdx.x;
    const int qb = blockIdx.x, h = blockIdx.y, b = blockIdx.z;
    const int q0 = qb * 128;
    if (tid < 128) {
        const int rq = q0 + tid;
        float m = -1e30f, l = 0.f, o[128];
        for (int d = 0; d < 128; d++) o[d] = 0.f;
        for (int j = 0; j <= rq; j++) {
            float s = 0.f;
            const size_t qo = (size_t)(b * Tt + rq) * Dd + h * HDd;
            const size_t ko = (size_t)(b * Tt + j) * Dd + h * HDd;
            for (int d = 0; d < 128; d++) {
                float qv = __bfloat162float(Qh[qo + d]) + __bfloat162float(Ql[qo + d]);
                float kv = __bfloat162float(Kh[ko + d]) + __bfloat162float(Kl[ko + d]);
                s += qv * kv;
            }
            s *= 0.088388347648318447f;
            float mn = fmaxf(m, s);
            float al = __expf(m - mn), p = __expf(s - mn);
            m = mn;
            l = l * al + p;
            const size_t vo = (size_t)(b * Hh + h) * HDd;
            for (int d = 0; d < 128; d++) {
                float vv = __bfloat162float(Vh[(vo + d) * Tt + j]) +
                           __bfloat162float(Vl[(vo + d) * Tt + j]);
                o[d] = o[d] * al + p * vv;
            }
        }
        float* orow = Out + (size_t)(b * Tt + rq) * Dd + h * HDd;
        for (int d = 0; d < 128; d++) orow[d] = o[d] / l;
    }
#endif
}

// ---------------- LayerNorm ----------------
__global__ void __launch_bounds__(256) ln_kernel(const float* __restrict__ x,
                                                 const float* __restrict__ g,
                                                 const float* __restrict__ b,
                                                 float* __restrict__ out)
{
    const int row = blockIdx.x;
    const int tid = threadIdx.x;
    const float* xr = x + (size_t)row * Dd;
    __shared__ float red[256];

    float s = 0.f;
    for (int i = tid; i < Dd; i += 256) s += xr[i];
    red[tid] = s; __syncthreads();
    for (int off = 128; off > 0; off >>= 1) {
        if (tid < off) red[tid] += red[tid + off];
        __syncthreads();
    }
    const float mean = red[0] * (1.f / Dd);
    __syncthreads();

    float v = 0.f;
    for (int i = tid; i < Dd; i += 256) { float d = xr[i] - mean; v += d * d; }
    red[tid] = v; __syncthreads();
    for (int off = 128; off > 0; off >>= 1) {
        if (tid < off) red[tid] += red[tid + off];
        __syncthreads();
    }
    const float rstd = rsqrtf(red[0] * (1.f / Dd) + 1e-5f);

    float* orow = out + (size_t)row * Dd;
    for (int i = tid; i < Dd; i += 256)
        orow[i] = (xr[i] - mean) * rstd * g[i] + b[i];
}

// ---------------- RoPE (head-indexed freqs, faithful to reference) ----------------
__global__ void rope_kernel(float* __restrict__ q, float* __restrict__ k,
                            const float* __restrict__ fr)
{
    const int idx = blockIdx.x * blockDim.x + threadIdx.x;
    const int j  = idx & 63;
    const int h  = (idx >> 6) & 15;
    const int bt = idx >> 10;
    const size_t base = (size_t)bt * Dd + h * HDd + 2 * j;
    const float cr = fr[h * 128 + 2 * j];
    const float ci = fr[h * 128 + 2 * j + 1];
    float a = q[base], b2 = q[base + 1];
    q[base]     = a * cr - b2 * ci;
    q[base + 1] = a * ci + b2 * cr;
    a = k[base]; b2 = k[base + 1];
    k[base]     = a * cr - b2 * ci;
    k[base + 1] = a * ci + b2 * cr;
}

// ---------------- fused SiLU(gate)*up ----------------
__global__ void silu_mul_kernel(float* __restrict__ gbuf, const float* __restrict__ ubuf)
{
    const int idx = blockIdx.x * blockDim.x + threadIdx.x;
    const float gt = gbuf[idx];
    const float s = gt / (1.f + __expf(-gt));
    gbuf[idx] = s * ubuf[idx];
}

// ---------------- launch ----------------
extern "C" void kernel_launch(void* const* d_in, const int* in_sizes, int n_in,
                              void* d_out, int out_size)
{
    const float* x   = (const float*)d_in[0];
    const float* fr  = (const float*)d_in[1];
    const float* Wq  = (const float*)d_in[2];
    const float* bq  = (const float*)d_in[3];
    const float* Wk  = (const float*)d_in[4];
    const float* bk  = (const float*)d_in[5];
    const float* Wv  = (const float*)d_in[6];
    const float* bv  = (const float*)d_in[7];
    const float* Wo  = (const float*)d_in[8];
    const float* bo  = (const float*)d_in[9];
    const float* g1  = (const float*)d_in[10];
    const float* be1 = (const float*)d_in[11];
    const float* g2  = (const float*)d_in[12];
    const float* be2 = (const float*)d_in[13];
    const float* Wg  = (const float*)d_in[14];
    const float* bg  = (const float*)d_in[15];
    const float* Wu  = (const float*)d_in[16];
    const float* bu  = (const float*)d_in[17];
    const float* Wd  = (const float*)d_in[18];
    const float* bd  = (const float*)d_in[19];
    float* out = (float*)d_out;

    float *xn, *q, *k, *v, *attn, *ff1, *ff2;
    __nv_bfloat16 *Ahi, *Alo, *Bhi, *Blo, *fQh, *fQl, *fKh, *fKl, *fVh, *fVl;
    cudaGetSymbolAddress((void**)&xn,   g_xn);
    cudaGetSymbolAddress((void**)&q,    g_q);
    cudaGetSymbolAddress((void**)&k,    g_k);
    cudaGetSymbolAddress((void**)&v,    g_v);
    cudaGetSymbolAddress((void**)&attn, g_attn);
    cudaGetSymbolAddress((void**)&ff1,  g_ff1);
    cudaGetSymbolAddress((void**)&ff2,  g_ff2);
    cudaGetSymbolAddress((void**)&Ahi,  g_Ahi);
    cudaGetSymbolAddress((void**)&Alo,  g_Alo);
    cudaGetSymbolAddress((void**)&Bhi,  g_Bhi);
    cudaGetSymbolAddress((void**)&Blo,  g_Blo);
    cudaGetSymbolAddress((void**)&fQh,  g_fQh);
    cudaGetSymbolAddress((void**)&fQl,  g_fQl);
    cudaGetSymbolAddress((void**)&fKh,  g_fKh);
    cudaGetSymbolAddress((void**)&fKl,  g_fKl);
    cudaGetSymbolAddress((void**)&fVh,  g_fVh);
    cudaGetSymbolAddress((void**)&fVl,  g_fVl);

    cudaFuncSetAttribute(mma_gemm_kernel, cudaFuncAttributeMaxDynamicSharedMemorySize, GEMM_SMEM);
    cudaFuncSetAttribute(flash_mma_kernel, cudaFuncAttributeMaxDynamicSharedMemorySize, FLASH_SMEM);

    const int DD  = ROWS * Dd;   // 8M
    const int DW  = Dd * Dd;     // 4M
    const int FW  = FFd * Dd;    // 16M
    const int DF  = ROWS * FFd;  // 32M

#define SPLIT(src, hi, lo, n) split_kernel<<<((n)/4 + 255)/256, 256>>>(src, hi, lo, (n)/4)

    // 1) LN1
    ln_kernel<<<ROWS, 256>>>(x, g1, be1, xn);

    // 2) Q,K,V projections
    SPLIT(xn, Ahi, Alo, DD);
    dim3 gD(2 * (Dd / 256), ROWS / 256);
    SPLIT(Wq, Bhi, Blo, DW);
    mma_gemm_kernel<<<gD, 256, GEMM_SMEM>>>(Ahi, Alo, Bhi, Blo, bq, nullptr, q, ROWS, Dd, Dd);
    SPLIT(Wk, Bhi, Blo, DW);
    mma_gemm_kernel<<<gD, 256, GEMM_SMEM>>>(Ahi, Alo, Bhi, Blo, bk, nullptr, k, ROWS, Dd, Dd);
    SPLIT(Wv, Bhi, Blo, DW);
    mma_gemm_kernel<<<gD, 256, GEMM_SMEM>>>(Ahi, Alo, Bhi, Blo, bv, nullptr, v, ROWS, Dd, Dd);

    // 3) RoPE, then split q/k and transpose+split v for the MMA flash
    rope_kernel<<<(Bb * Tt * Hh * (HDd / 2)) / 256, 256>>>(q, k, fr);
    SPLIT(q, fQh, fQl, DD);
    SPLIT(k, fKh, fKl, DD);
    vtrans_kernel<<<dim3(Tt / 32, HDd / 32, Bb * Hh), dim3(32, 8)>>>(v, fVh, fVl);

    // 4) causal flash attention (tcgen05)
    flash_mma_kernel<<<dim3(Tt / 128, Hh, Bb), 256, FLASH_SMEM>>>(
        fQh, fQl, fKh, fKl, fVh, fVl, attn);

    // 5) output projection + residual(x) -> out
    SPLIT(attn, Ahi, Alo, DD);
    SPLIT(Wo, Bhi, Blo, DW);
    mma_gemm_kernel<<<gD, 256, GEMM_SMEM>>>(Ahi, Alo, Bhi, Blo, bo, x, out, ROWS, Dd, Dd);

    // 6) LN2
    ln_kernel<<<ROWS, 256>>>(out, g2, be2, xn);

    // 7) gate / up
    SPLIT(xn, Ahi, Alo, DD);
    dim3 gF(2 * (FFd / 256), ROWS / 256);
    SPLIT(Wg, Bhi, Blo, FW);
    mma_gemm_kernel<<<gF, 256, GEMM_SMEM>>>(Ahi, Alo, Bhi, Blo, bg, nullptr, ff1, ROWS, FFd, Dd);
    SPLIT(Wu, Bhi, Blo, FW);
    mma_gemm_kernel<<<gF, 256, GEMM_SMEM>>>(Ahi, Alo, Bhi, Blo, bu, nullptr, ff2, ROWS, FFd, Dd);

    // 8) SiLU(gate)*up
    silu_mul_kernel<<<(ROWS * FFd) / 256, 256>>>(ff1, ff2);

    // 9) down projection + residual(out) -> out
    SPLIT(ff1, Ahi, Alo, DF);
    SPLIT(Wd, Bhi, Blo, FW);
    mma_gemm_kernel<<<gD, 256, GEMM_SMEM>>>(Ahi, Alo, Bhi, Blo, bd, out, out, ROWS, Dd, FFd);
}

// round 10
// speedup vs baseline: 6.2547x; 1.1141x over previous
#include <cuda_runtime.h>
#include <cuda_bf16.h>
#include <cstdint>
#include <math.h>

#define Bb 2
#define Tt 2048
#define Dd 2048
#define Hh 16
#define HDd 128
#define FFd 8192
#define ROWS (Bb*Tt)   /* 4096 */

// tcgen05 only exists in arch-specific (sm_10xa) compilation phases.
#if defined(__CUDA_ARCH_FEAT_SM103_ALL) || defined(__CUDA_ARCH_FEAT_SM100_ALL) || \
    defined(__CUDA_ARCH_FEAT_SM101_ALL) || \
    (defined(__CUDA_ARCH_SPECIFIC__) && (__CUDA_ARCH_SPECIFIC__ >= 1000)) || \
    (defined(__CUDA_ARCH_FAMILY_SPECIFIC__) && (__CUDA_ARCH_FAMILY_SPECIFIC__ >= 1000))
#define HAS_TCGEN05 1
#else
#define HAS_TCGEN05 0
#endif

// ---------------- scratch (no allocations allowed -> device globals) ----------------
__device__ float g_xn  [ROWS*Dd];
__device__ float g_q   [ROWS*Dd];
__device__ float g_k   [ROWS*Dd];
__device__ float g_v   [ROWS*Dd];
__device__ float g_attn[ROWS*Dd];
__device__ float g_ff1 [ROWS*FFd];
__device__ float g_ff2 [ROWS*FFd];
// bf16 split buffers (GEMM)
__device__ __nv_bfloat16 g_Ahi[ROWS*FFd];
__device__ __nv_bfloat16 g_Alo[ROWS*FFd];
__device__ __nv_bfloat16 g_Bhi[FFd*Dd];
__device__ __nv_bfloat16 g_Blo[FFd*Dd];
// bf16 split buffers (flash): Q/K in [b,t,h*hd]; Vt in [b,h,hd,t]
__device__ __nv_bfloat16 g_fQh[ROWS*Dd];
__device__ __nv_bfloat16 g_fQl[ROWS*Dd];
__device__ __nv_bfloat16 g_fKh[ROWS*Dd];
__device__ __nv_bfloat16 g_fKl[ROWS*Dd];
__device__ __nv_bfloat16 g_fVh[ROWS*Dd];
__device__ __nv_bfloat16 g_fVl[ROWS*Dd];

// ================= helpers =================
__device__ __forceinline__ uint32_t smem_u32(const void* p) {
    uint32_t a;
    asm("{ .reg .u64 t; cvta.to.shared.u64 t, %1; cvt.u32.u64 %0, t; }"
        : "=r"(a) : "l"(p));
    return a;
}

#define SW128(o) ((o) ^ (((o) >> 3) & 0x70))

static constexpr uint64_t DESC_BASE_SW128 =
    (uint64_t(2)  << 61) | (uint64_t(1) << 46) | (uint64_t(64) << 32) | (uint64_t(1) << 16);

// idescs (kind::f16): dtype=F32(1<<4), atype/btype=BF16
#define MMA_IDESC_CG2 0x10400490u   /* M=256, N=256 */
#define MMA_IDESC_QK  0x08100490u   /* M=128, N=64  */
#define MMA_IDESC_PV  0x08200490u   /* M=128, N=128 */

#if HAS_TCGEN05
__device__ __forceinline__ uint64_t mkdesc(uint32_t addr) {
    return DESC_BASE_SW128 | ((uint64_t)(addr >> 4) & 0x3FFF);
}
__device__ __forceinline__ void mma_bf16_ss_cg2(uint32_t d, uint64_t ad, uint64_t bd, uint32_t en) {
    asm volatile(
        "{\n\t.reg .pred p;\n\tsetp.ne.u32 p, %4, 0;\n\t"
        "tcgen05.mma.cta_group::2.kind::f16 [%0], %1, %2, %3, {%5,%5,%5,%5,%5,%5,%5,%5}, p;\n\t}"
        :: "r"(d), "l"(ad), "l"(bd), "r"(MMA_IDESC_CG2), "r"(en), "r"(0u) : "memory");
}
__device__ __forceinline__ void mma_ss_cg1(uint32_t d, uint64_t ad, uint64_t bd,
                                           uint32_t idesc, uint32_t en) {
    asm volatile(
        "{\n\t.reg .pred p;\n\tsetp.ne.u32 p, %4, 0;\n\t"
        "tcgen05.mma.cta_group::1.kind::f16 [%0], %1, %2, %3, {%5,%5,%5,%5}, p;\n\t}"
        :: "r"(d), "l"(ad), "l"(bd), "r"(idesc), "r"(en), "r"(0u) : "memory");
}
__device__ __forceinline__ void mbar_init(uint32_t m, uint32_t cnt) {
    asm volatile("mbarrier.init.shared.b64 [%0], %1;" :: "r"(m), "r"(cnt) : "memory");
}
__device__ __forceinline__ void mbar_wait(uint32_t m, uint32_t parity) {
    asm volatile(
        "{\n\t.reg .pred P1;\n"
        "W%=:\n\t"
        "mbarrier.try_wait.parity.acquire.cta.shared::cta.b64 P1, [%0], %1, 0x989680;\n\t"
        "@P1 bra.uni D%=;\n\t"
        "bra.uni W%=;\n"
        "D%=:\n\t}"
        :: "r"(m), "r"(parity) : "memory");
}
__device__ __forceinline__ void tc_commit_cg1(uint32_t m) {
    asm volatile("tcgen05.commit.cta_group::1.mbarrier::arrive::one.shared::cluster.b64 [%0];"
                 :: "r"(m) : "memory");
}
__device__ __forceinline__ void tc_commit_mc2(uint32_t m) {
    asm volatile(
        "tcgen05.commit.cta_group::2.mbarrier::arrive::one.shared::cluster.multicast::cluster.b64 [%0], %1;"
        :: "r"(m), "h"((uint16_t)0x3) : "memory");
}
__device__ __forceinline__ void mbar_arrive_rank0(uint32_t local_addr) {
    asm volatile(
        "{\n\t.reg .b32 ra;\n\t"
        "mapa.shared::cluster.u32 ra, %0, %1;\n\t"
        "mbarrier.arrive.shared::cluster.b64 _, [ra];\n\t}"
        :: "r"(local_addr), "r"(0) : "memory");
}
__device__ __forceinline__ void ldtm32(uint32_t* r, uint32_t a) {
    asm volatile(
        "tcgen05.ld.sync.aligned.32x32b.x32.b32 "
        "{%0,%1,%2,%3,%4,%5,%6,%7,%8,%9,%10,%11,%12,%13,%14,%15,"
        "%16,%17,%18,%19,%20,%21,%22,%23,%24,%25,%26,%27,%28,%29,%30,%31}, [%32];"
        : "=r"(r[0]),"=r"(r[1]),"=r"(r[2]),"=r"(r[3]),"=r"(r[4]),"=r"(r[5]),"=r"(r[6]),"=r"(r[7]),
          "=r"(r[8]),"=r"(r[9]),"=r"(r[10]),"=r"(r[11]),"=r"(r[12]),"=r"(r[13]),"=r"(r[14]),"=r"(r[15]),
          "=r"(r[16]),"=r"(r[17]),"=r"(r[18]),"=r"(r[19]),"=r"(r[20]),"=r"(r[21]),"=r"(r[22]),"=r"(r[23]),
          "=r"(r[24]),"=r"(r[25]),"=r"(r[26]),"=r"(r[27]),"=r"(r[28]),"=r"(r[29]),"=r"(r[30]),"=r"(r[31])
        : "r"(a));
}
__device__ __forceinline__ void sttm32(uint32_t a, const uint32_t* r) {
    asm volatile(
        "tcgen05.st.sync.aligned.32x32b.x32.b32 [%32], "
        "{%0,%1,%2,%3,%4,%5,%6,%7,%8,%9,%10,%11,%12,%13,%14,%15,"
        "%16,%17,%18,%19,%20,%21,%22,%23,%24,%25,%26,%27,%28,%29,%30,%31};"
        :: "r"(r[0]),"r"(r[1]),"r"(r[2]),"r"(r[3]),"r"(r[4]),"r"(r[5]),"r"(r[6]),"r"(r[7]),
           "r"(r[8]),"r"(r[9]),"r"(r[10]),"r"(r[11]),"r"(r[12]),"r"(r[13]),"r"(r[14]),"r"(r[15]),
           "r"(r[16]),"r"(r[17]),"r"(r[18]),"r"(r[19]),"r"(r[20]),"r"(r[21]),"r"(r[22]),"r"(r[23]),
           "r"(r[24]),"r"(r[25]),"r"(r[26]),"r"(r[27]),"r"(r[28]),"r"(r[29]),"r"(r[30]),"r"(r[31]),
           "r"(a)
        : "memory");
}
__device__ __forceinline__ void cpasync16(uint32_t dst, const void* src) {
    asm volatile("cp.async.cg.shared.global [%0], [%1], 16;" :: "r"(dst), "l"(src) : "memory");
}
__device__ __forceinline__ void cp_arrive(uint32_t m) {
    asm volatile("cp.async.mbarrier.arrive.noinc.shared.b64 [%0];" :: "r"(m) : "memory");
}
#define CP_COMMIT() asm volatile("cp.async.commit_group;" ::: "memory")
#define CP_WAIT0()  asm volatile("cp.async.wait_group 0;" ::: "memory")
#define TC_WAIT_LD() asm volatile("tcgen05.wait::ld.sync.aligned;" ::: "memory")
#define TC_WAIT_ST() asm volatile("tcgen05.wait::st.sync.aligned;" ::: "memory")
#define TC_FENCE_BEFORE() asm volatile("tcgen05.fence::before_thread_sync;" ::: "memory")
#define TC_FENCE_AFTER()  asm volatile("tcgen05.fence::after_thread_sync;" ::: "memory")
#define CLUSTER_SYNC() do { \
    asm volatile("barrier.cluster.arrive.aligned;" ::: "memory"); \
    asm volatile("barrier.cluster.wait.aligned;" ::: "memory"); \
} while (0)
#endif  // HAS_TCGEN05

// ---------------- split fp32 -> bf16 hi/lo ----------------
__global__ void __launch_bounds__(256) split_kernel(const float* __restrict__ src,
                                                    __nv_bfloat16* __restrict__ hi,
                                                    __nv_bfloat16* __restrict__ lo,
                                                    int n4)
{
    int idx = blockIdx.x * blockDim.x + threadIdx.x;
    if (idx >= n4) return;
    float4 v = ((const float4*)src)[idx];
    __nv_bfloat162 h0 = __floats2bfloat162_rn(v.x, v.y);
    __nv_bfloat162 h1 = __floats2bfloat162_rn(v.z, v.w);
    float lx = v.x - __bfloat162float(__low2bfloat16(h0));
    float ly = v.y - __bfloat162float(__high2bfloat16(h0));
    float lz = v.z - __bfloat162float(__low2bfloat16(h1));
    float lw = v.w - __bfloat162float(__high2bfloat16(h1));
    __nv_bfloat162 l0 = __floats2bfloat162_rn(lx, ly);
    __nv_bfloat162 l1 = __floats2bfloat162_rn(lz, lw);
    uint2 ho, loo;
    ho.x  = *reinterpret_cast<uint32_t*>(&h0);
    ho.y  = *reinterpret_cast<uint32_t*>(&h1);
    loo.x = *reinterpret_cast<uint32_t*>(&l0);
    loo.y = *reinterpret_cast<uint32_t*>(&l1);
    ((uint2*)hi)[idx] = ho;
    ((uint2*)lo)[idx] = loo;
}

// ---------------- V transpose+split: v[b,t,h*hd] -> Vt[b,h,hd,t] bf16 hi/lo ----------------
__global__ void __launch_bounds__(256) vtrans_kernel(const float* __restrict__ v,
                                                     __nv_bfloat16* __restrict__ Vth,
                                                     __nv_bfloat16* __restrict__ Vtl)
{
    __shared__ float tile[32][33];
    const int bh = blockIdx.z;
    const int b  = bh >> 4, h = bh & 15;
    const int t0 = blockIdx.x * 32;
    const int d0 = blockIdx.y * 32;
    const int x = threadIdx.x, y = threadIdx.y;  // (32,8)
#pragma unroll
    for (int i = 0; i < 4; i++) {
        int t = t0 + y + i * 8;
        tile[y + i * 8][x] = v[(size_t)(b * Tt + t) * Dd + h * HDd + d0 + x];
    }
    __syncthreads();
#pragma unroll
    for (int i = 0; i < 4; i++) {
        int hd = d0 + y + i * 8;
        float val = tile[x][y + i * 8];
        __nv_bfloat16 hi = __float2bfloat16(val);
        __nv_bfloat16 lo = __float2bfloat16(val - __bfloat162float(hi));
        size_t idx = (size_t)(bh * HDd + hd) * Tt + t0 + x;
        Vth[idx] = hi;
        Vtl[idx] = lo;
    }
}

// ============ cg2 GEMM, warp-specialized: warps 0-7 produce, warp 8 relays/issues MMA ============
#define NSTAGE 3
#define STAGE_BYTES 65536
#define GEMM_SMEM (1024 + NSTAGE * STAGE_BYTES)
#define GEMM_THREADS 288

__global__ void __launch_bounds__(GEMM_THREADS, 1) __cluster_dims__(2, 1, 1)
mma_gemm_kernel(const __nv_bfloat16* __restrict__ Ah, const __nv_bfloat16* __restrict__ Al,
                const __nv_bfloat16* __restrict__ Bh, const __nv_bfloat16* __restrict__ Bl,
                const float* __restrict__ bias, const float* __restrict__ resid,
                float* __restrict__ C, int M, int N, int K)
{
    extern __shared__ char smem[];
#if HAS_TCGEN05
    const uint32_t sbase = smem_u32(smem);
    const int tid  = threadIdx.x;
    const int wid  = tid >> 5;
    const int lane = tid & 31;
    const int rank = blockIdx.x & 1;
    const int bn   = (blockIdx.x >> 1) * 256;
    const int bm   = blockIdx.y * 256;

    const uint32_t tile_abs = (sbase + 128 + 1023) & ~1023u;
    const uint32_t mb_full  = sbase + 8;    // count 256 (producers' cp_arrive)
    const uint32_t mb_f2    = sbase + 32;   // count 2 (both CTAs' relays)
    const uint32_t mb_empty = sbase + 56;   // count 1 (commit-multicast)

    if (wid == 0) {
        asm volatile("tcgen05.alloc.cta_group::2.sync.aligned.shared::cta.b32 [%0], %1;"
                     :: "r"(sbase), "r"(256u) : "memory");
        asm volatile("tcgen05.relinquish_alloc_permit.cta_group::2.sync.aligned;");
    }
    if (tid == 0) {
#pragma unroll
        for (int s = 0; s < NSTAGE; s++) {
            mbar_init(mb_full  + s * 8, 256);
            mbar_init(mb_f2    + s * 8, 2);
            mbar_init(mb_empty + s * 8, 1);
        }
    }
    __syncthreads();
    CLUSTER_SYNC();

    uint32_t tmem;
    asm volatile("ld.shared.b32 %0, [%1];" : "=r"(tmem) : "r"(sbase));

    const int n = K >> 6;

    if (tid < 256) {
        // ---------------- producers ----------------
        const int r  = tid >> 1;
        const int hh = tid & 1;
        const uint32_t off = r * 128 + hh * 64;
        const __nv_bfloat16* AgH = Ah + (size_t)(bm + rank * 128 + r) * K + hh * 32;
        const __nv_bfloat16* AgL = Al + (size_t)(bm + rank * 128 + r) * K + hh * 32;
        const __nv_bfloat16* BgH = Bh + (size_t)(bn + rank * 128 + r) * K + hh * 32;
        const __nv_bfloat16* BgL = Bl + (size_t)(bn + rank * 128 + r) * K + hh * 32;

        for (int c = 0; c < n; c++) {
            const int s = c % NSTAGE;
            const int use = c / NSTAGE;
            if (c >= NSTAGE) mbar_wait(mb_empty + s * 8, (use - 1) & 1);

            const uint32_t sb = tile_abs + s * STAGE_BYTES;
            const size_t kof = (size_t)c * 64;
#pragma unroll
            for (int j = 0; j < 4; j++) {
                const uint32_t o = SW128(off + j * 16);
                cpasync16(sb + o,         AgH + kof + j * 8);
                cpasync16(sb + 16384 + o, AgL + kof + j * 8);
                cpasync16(sb + 32768 + o, BgH + kof + j * 8);
                cpasync16(sb + 49152 + o, BgL + kof + j * 8);
            }
            cp_arrive(mb_full + s * 8);
        }
    } else if (tid == 256) {
        // ---------------- relay + MMA consumer (never touches LSU loads) ----------------
        for (int i = 0; i < n; i++) {
            const int si = i % NSTAGE;
            mbar_wait(mb_full + si * 8, (i / NSTAGE) & 1);
            mbar_arrive_rank0(mb_f2 + si * 8);
            if (rank == 0) {
                mbar_wait(mb_f2 + si * 8, (i / NSTAGE) & 1);
                asm volatile("fence.proxy.async.shared::cta;" ::: "memory");
                const uint32_t sbi = tile_abs + si * STAGE_BYTES;
                const uint64_t ah = mkdesc(sbi);
                const uint64_t al = mkdesc(sbi + 16384);
                const uint64_t bh = mkdesc(sbi + 32768);
                const uint64_t bl = mkdesc(sbi + 49152);
#pragma unroll
                for (int k = 0; k < 4; k++)
                    mma_bf16_ss_cg2(tmem, ah + k * 2, bh + k * 2, (i > 0 || k > 0) ? 1u : 0u);
#pragma unroll
                for (int k = 0; k < 4; k++)
                    mma_bf16_ss_cg2(tmem, ah + k * 2, bl + k * 2, 1u);
#pragma unroll
                for (int k = 0; k < 4; k++)
                    mma_bf16_ss_cg2(tmem, al + k * 2, bh + k * 2, 1u);
                tc_commit_mc2(mb_empty + si * 8);
            }
        }
    }

    // all threads wait for the final chunk's MMA completion (multicast commit)
    {
        const int i = n - 1, si = i % NSTAGE;
        mbar_wait(mb_empty + si * 8, (i / NSTAGE) & 1);
    }
    TC_FENCE_AFTER();

    if (wid < 8) {
        const int sub  = wid & 3;
        const int half = wid >> 2;
        const int row  = bm + rank * 128 + sub * 32 + lane;
        const float* rrow = resid ? resid + (size_t)row * N : nullptr;
        float* crow = C + (size_t)row * N;
#pragma unroll 1
        for (int half2 = 0; half2 < 2; half2++) {
#pragma unroll 1
            for (int c32 = 0; c32 < 2; c32++) {
                uint32_t d[32];
                ldtm32(d, tmem + half2 * 128 + half * 64 + c32 * 32);
                TC_WAIT_LD();
                const int col0 = bn + half2 * 128 + half * 64 + c32 * 32;
                if (rrow) {
#pragma unroll
                    for (int j = 0; j < 32; j++)
                        crow[col0 + j] = __uint_as_float(d[j]) + bias[col0 + j] + rrow[col0 + j];
                } else {
#pragma unroll
                    for (int j = 0; j < 32; j++)
                        crow[col0 + j] = __uint_as_float(d[j]) + bias[col0 + j];
                }
            }
        }
    }
    __syncthreads();
    if (wid == 0) {
        asm volatile("tcgen05.dealloc.cta_group::2.sync.aligned.b32 %0, %1;"
                     :: "r"(tmem), "r"(256u));
    }
    CLUSTER_SYNC();
#else
    float* As = (float*)smem;
    float* Bs = As + 8 * 128;
    const int tid = threadIdx.x;
    const int rank = blockIdx.x & 1;
    const int bm = blockIdx.y * 256 + rank * 128;
    const int bn0 = (blockIdx.x >> 1) * 256;
    const int lr  = tid >> 1;
    const int lcc = (tid & 1) * 4;
    const int tx = tid & 15, ty = tid >> 4;

    for (int h = 0; h < 2; h++) {
        const int bn = bn0 + h * 128;
        float acc[8][8];
#pragma unroll
        for (int i = 0; i < 8; i++)
#pragma unroll
            for (int j = 0; j < 8; j++) acc[i][j] = 0.f;

        for (int k0 = 0; k0 < K; k0 += 8) {
            if (tid < 256) {
                const __nv_bfloat16* aph = Ah + (size_t)(bm + lr) * K + k0 + lcc;
                const __nv_bfloat16* apl = Al + (size_t)(bm + lr) * K + k0 + lcc;
                const __nv_bfloat16* bph = Bh + (size_t)(bn + lr) * K + k0 + lcc;
                const __nv_bfloat16* bpl = Bl + (size_t)(bn + lr) * K + k0 + lcc;
#pragma unroll
                for (int j = 0; j < 4; j++) {
                    As[(lcc + j) * 128 + lr] = __bfloat162float(aph[j]) + __bfloat162float(apl[j]);
                    Bs[(lcc + j) * 128 + lr] = __bfloat162float(bph[j]) + __bfloat162float(bpl[j]);
                }
            }
            __syncthreads();
            if (tid < 256) {
#pragma unroll
                for (int kk = 0; kk < 8; kk++) {
                    float a[8], bb[8];
#pragma unroll
                    for (int i = 0; i < 8; i++)
                        a[i] = As[kk * 128 + ((i & 4) << 4) + ty * 4 + (i & 3)];
#pragma unroll
                    for (int j = 0; j < 8; j++)
                        bb[j] = Bs[kk * 128 + ((j & 4) << 4) + tx * 4 + (j & 3)];
#pragma unroll
                    for (int i = 0; i < 8; i++)
#pragma unroll
                        for (int j = 0; j < 8; j++)
                            acc[i][j] += a[i] * bb[j];
                }
            }
            __syncthreads();
        }

        if (tid < 256) {
#pragma unroll
            for (int i = 0; i < 8; i++) {
                const int row = bm + ((i & 4) << 4) + ty * 4 + (i & 3);
#pragma unroll
                for (int j = 0; j < 8; j++) {
                    const int col = bn + ((j & 4) << 4) + tx * 4 + (j & 3);
                    float vv = acc[i][j] + bias[col];
                    if (resid) vv += resid[(size_t)row * N + col];
                    C[(size_t)row * N + col] = vv;
                }
            }
        }
    }
#endif
}

// ============ tcgen05 flash attention (unchanged from R9, passing) ============
#define FLASH_SMEM (1024 + 160 * 1024 + 1024)

__global__ void __launch_bounds__(256, 1) flash_mma_kernel(
    const __nv_bfloat16* __restrict__ Qh, const __nv_bfloat16* __restrict__ Ql,
    const __nv_bfloat16* __restrict__ Kh, const __nv_bfloat16* __restrict__ Kl,
    const __nv_bfloat16* __restrict__ Vh, const __nv_bfloat16* __restrict__ Vl,
    float* __restrict__ Out)
{
    extern __shared__ char smem[];
#if HAS_TCGEN05
    const uint32_t sbase = smem_u32(smem);
    const int tid  = threadIdx.x;
    const int wid  = tid >> 5;
    const int lane = tid & 31;
    const int qb = blockIdx.x, h = blockIdx.y, b = blockIdx.z;
    const int q0 = qb * 128;

    const uint32_t mb_qk = sbase + 8;
    const uint32_t mb_pv = sbase + 16;
    int*   flags  = (int*)(smem + 24);
    float* redbuf = (float*)(smem + 64);
    const uint32_t tile_abs = (sbase + 576 + 1023) & ~1023u;
    const uint32_t tile_off = tile_abs - sbase;

    if (wid == 0) {
        asm volatile("tcgen05.alloc.cta_group::1.sync.aligned.shared::cta.b32 [%0], %1;"
                     :: "r"(sbase), "r"(256u) : "memory");
        asm volatile("tcgen05.relinquish_alloc_permit.cta_group::1.sync.aligned;");
    }
    if (tid == 0) { mbar_init(mb_qk, 1); mbar_init(mb_pv, 1); }
    __syncthreads();
    uint32_t tmem;
    asm volatile("ld.shared.b32 %0, [%1];" : "=r"(tmem) : "r"(sbase));
    const uint32_t tm_S = tmem;
    const uint32_t tm_O = tmem + 64;

#pragma unroll
    for (int i = 0; i < 2; i++) {
        int u = tid * 2 + i;
        int buf = u >> 8, rem = u & 255, half = rem >> 7, row = rem & 127;
        const __nv_bfloat16* src = (buf ? Ql : Qh)
            + (size_t)(b * Tt + q0 + row) * Dd + h * HDd + half * 64;
        uint32_t dst = tile_abs + buf * 32768 + half * 16384;
        uint32_t off = row * 128;
#pragma unroll
        for (int j = 0; j < 8; j++)
            cpasync16(dst + SW128(off + j * 16), src + j * 8);
    }
    CP_COMMIT();

    const int sw   = wid & 3;
    const int colh = wid >> 2;
    const int row  = sw * 32 + lane;
    const float scale = 0.088388347648318447f;

    float m = -1e30f, l = 0.f;
    const int nt = 2 * qb + 2;

    for (int t = 0; t < nt; t++) {
        const int j0 = t * 64;
        if (t > 0) mbar_wait(mb_pv, (t - 1) & 1);

#pragma unroll
        for (int i = 0; i < 2; i++) {
            int u = tid * 2 + i;
            const __nv_bfloat16* src;
            uint32_t dst, off;
            if (u < 256) {
                int kr = u & 63, half = (u >> 6) & 1, buf = u >> 7;
                src = (buf ? Kl : Kh) + (size_t)(b * Tt + j0 + kr) * Dd + h * HDd + half * 64;
                dst = tile_abs + 65536 + buf * 16384 + half * 8192;
                off = kr * 128;
            } else {
                int u2 = u - 256;
                int vr = u2 & 127, buf = u2 >> 7;
                src = (buf ? Vl : Vh) + (size_t)((b * Hh + h) * HDd + vr) * Tt + j0;
                dst = tile_abs + 98304 + buf * 16384;
                off = vr * 128;
            }
#pragma unroll
            for (int j = 0; j < 8; j++)
                cpasync16(dst + SW128(off + j * 16), src + j * 8);
        }
        CP_COMMIT();
        CP_WAIT0();
        __syncthreads();

        if (tid == 0) {
            asm volatile("fence.proxy.async.shared::cta;" ::: "memory");
            uint64_t qd[2][2], kd[2][2];
            qd[0][0] = mkdesc(tile_abs);          qd[0][1] = mkdesc(tile_abs + 16384);
            qd[1][0] = mkdesc(tile_abs + 32768);  qd[1][1] = mkdesc(tile_abs + 49152);
            kd[0][0] = mkdesc(tile_abs + 65536);  kd[0][1] = mkdesc(tile_abs + 73728);
            kd[1][0] = mkdesc(tile_abs + 81920);  kd[1][1] = mkdesc(tile_abs + 90112);
            int first = 1;
#pragma unroll
            for (int c3 = 0; c3 < 3; c3++) {
                const int ab = (c3 == 2) ? 1 : 0;
                const int bb = (c3 == 1) ? 1 : 0;
#pragma unroll
                for (int ks = 0; ks < 8; ks++) {
                    const int half = ks >> 2;
                    const uint64_t o = (uint64_t)((ks & 3) * 2);
                    mma_ss_cg1(tm_S, qd[ab][half] + o, kd[bb][half] + o,
                               MMA_IDESC_QK, first ? 0u : 1u);
                    first = 0;
                }
            }
            tc_commit_cg1(mb_qk);
        }
        mbar_wait(mb_qk, t & 1);
        TC_FENCE_AFTER();

        if (wid < 4) {
            uint32_t sr[64];
            ldtm32(sr,      tm_S);
            ldtm32(sr + 32, tm_S + 32);
            TC_WAIT_LD();
            float sv[64];
            float tmax = -1e30f;
#pragma unroll
            for (int c = 0; c < 64; c++) {
                float x = __uint_as_float(sr[c]) * scale;
                if (j0 + c > q0 + row) x = -1e30f;
                sv[c] = x;
                tmax = fmaxf(tmax, x);
            }
            const float mnew = fmaxf(m, tmax);
            const float alpha = __expf(m - mnew);
            m = mnew;
            float psum = 0.f;
#pragma unroll
            for (int c = 0; c < 64; c++) {
                float p = __expf(sv[c] - mnew);
                sv[c] = p;
                psum += p;
            }
            l = l * alpha + psum;
            const uint32_t prow = row * 128;
#pragma unroll
            for (int g = 0; g < 16; g++) {
                const int c = g * 4;
                __nv_bfloat162 h0 = __floats2bfloat162_rn(sv[c], sv[c + 1]);
                __nv_bfloat162 h1 = __floats2bfloat162_rn(sv[c + 2], sv[c + 3]);
                float l0a = sv[c]     - __bfloat162float(__low2bfloat16(h0));
                float l1a = sv[c + 1] - __bfloat162float(__high2bfloat16(h0));
                float l2a = sv[c + 2] - __bfloat162float(__low2bfloat16(h1));
                float l3a = sv[c + 3] - __bfloat162float(__high2bfloat16(h1));
                __nv_bfloat162 g0 = __floats2bfloat162_rn(l0a, l1a);
                __nv_bfloat162 g1 = __floats2bfloat162_rn(l2a, l3a);
                uint2 hv, lv;
                hv.x = *reinterpret_cast<uint32_t*>(&h0);
                hv.y = *reinterpret_cast<uint32_t*>(&h1);
                lv.x = *reinterpret_cast<uint32_t*>(&g0);
                lv.y = *reinterpret_cast<uint32_t*>(&g1);
                const uint32_t o = SW128(prow + c * 2);
                *(uint2*)(smem + tile_off + 131072 + o) = hv;
                *(uint2*)(smem + tile_off + 147456 + o) = lv;
            }
            asm volatile("fence.proxy.async.shared::cta;" ::: "memory");
            redbuf[row] = alpha;
            unsigned bal = __ballot_sync(0xffffffffu, alpha < 0.999999f);
            if (lane == 0) flags[wid] = (bal != 0) ? 1 : 0;
        }
        __syncthreads();

        if (t > 0 && ((volatile int*)flags)[sw]) {
            const float av = ((volatile float*)redbuf)[row];
            uint32_t o0[32], o1[32];
            ldtm32(o0, tm_O + colh * 64);
            ldtm32(o1, tm_O + colh * 64 + 32);
            TC_WAIT_LD();
#pragma unroll
            for (int j = 0; j < 32; j++) {
                o0[j] = __float_as_uint(__uint_as_float(o0[j]) * av);
                o1[j] = __float_as_uint(__uint_as_float(o1[j]) * av);
            }
            sttm32(tm_O + colh * 64,      o0);
            sttm32(tm_O + colh * 64 + 32, o1);
            TC_WAIT_ST();
        }
        TC_FENCE_BEFORE();
        __syncthreads();

        if (tid == 0) {
            TC_FENCE_AFTER();
            asm volatile("fence.proxy.async.shared::cta;" ::: "memory");
            uint64_t pd[2], vd[2];
            pd[0] = mkdesc(tile_abs + 131072); pd[1] = mkdesc(tile_abs + 147456);
            vd[0] = mkdesc(tile_abs + 98304);  vd[1] = mkdesc(tile_abs + 114688);
            int first = (t == 0) ? 1 : 0;
#pragma unroll
            for (int c3 = 0; c3 < 3; c3++) {
                const int ab = (c3 == 1) ? 1 : 0;
                const int bb = (c3 == 2) ? 1 : 0;
#pragma unroll
                for (int ks = 0; ks < 4; ks++) {
                    const uint64_t o = (uint64_t)(ks * 2);
                    mma_ss_cg1(tm_O, pd[ab] + o, vd[bb] + o,
                               MMA_IDESC_PV, first ? 0u : 1u);
                    first = 0;
                }
            }
            tc_commit_cg1(mb_pv);
        }
    }

    mbar_wait(mb_pv, (nt - 1) & 1);
    TC_FENCE_AFTER();
    if (wid < 4) redbuf[row] = 1.f / l;
    __syncthreads();

    {
        const float linv = ((volatile float*)redbuf)[row];
        uint32_t o0[32], o1[32];
        ldtm32(o0, tm_O + colh * 64);
        ldtm32(o1, tm_O + colh * 64 + 32);
        TC_WAIT_LD();
        float* orow = Out + (size_t)(b * Tt + q0 + row) * Dd + h * HDd + colh * 64;
#pragma unroll
        for (int j4 = 0; j4 < 8; j4++) {
            float4 v0;
            v0.x = __uint_as_float(o0[j4 * 4 + 0]) * linv;
            v0.y = __uint_as_float(o0[j4 * 4 + 1]) * linv;
            v0.z = __uint_as_float(o0[j4 * 4 + 2]) * linv;
            v0.w = __uint_as_float(o0[j4 * 4 + 3]) * linv;
            *(float4*)(orow + j4 * 4) = v0;
            float4 v1;
            v1.x = __uint_as_float(o1[j4 * 4 + 0]) * linv;
            v1.y = __uint_as_float(o1[j4 * 4 + 1]) * linv;
            v1.z = __uint_as_float(o1[j4 * 4 + 2]) * linv;
            v1.w = __uint_as_float(o1[j4 * 4 + 3]) * linv;
            *(float4*)(orow + 32 + j4 * 4) = v1;
        }
    }
    __syncthreads();
    if (wid == 0) {
        asm volatile("tcgen05.dealloc.cta_group::1.sync.aligned.b32 %0, %1;"
                     :: "r"(tmem), "r"(256u));
    }
#else
    const int tid = threadIdx.x;
    const int qb = blockIdx.x, h = blockIdx.y, b = blockIdx.z;
    const int q0 = qb * 128;
    if (tid < 128) {
        const int rq = q0 + tid;
        float m = -1e30f, l = 0.f, o[128];
        for (int d = 0; d < 128; d++) o[d] = 0.f;
        for (int j = 0; j <= rq; j++) {
            float s = 0.f;
            const size_t qo = (size_t)(b * Tt + rq) * Dd + h * HDd;
            const size_t ko = (size_t)(b * Tt + j) * Dd + h * HDd;
            for (int d = 0; d < 128; d++) {
                float qv = __bfloat162float(Qh[qo + d]) + __bfloat162float(Ql[qo + d]);
                float kv = __bfloat162float(Kh[ko + d]) + __bfloat162float(Kl[ko + d]);
                s += qv * kv;
            }
            s *= 0.088388347648318447f;
            float mn = fmaxf(m, s);
            float al = __expf(m - mn), p = __expf(s - mn);
            m = mn;
            l = l * al + p;
            const size_t vo = (size_t)(b * Hh + h) * HDd;
            for (int d = 0; d < 128; d++) {
                float vv = __bfloat162float(Vh[(vo + d) * Tt + j]) +
                           __bfloat162float(Vl[(vo + d) * Tt + j]);
                o[d] = o[d] * al + p * vv;
            }
        }
        float* orow = Out + (size_t)(b * Tt + rq) * Dd + h * HDd;
        for (int d = 0; d < 128; d++) orow[d] = o[d] / l;
    }
#endif
}

// ---------------- LayerNorm ----------------
__global__ void __launch_bounds__(256) ln_kernel(const float* __restrict__ x,
                                                 const float* __restrict__ g,
                                                 const float* __restrict__ b,
                                                 float* __restrict__ out)
{
    const int row = blockIdx.x;
    const int tid = threadIdx.x;
    const float* xr = x + (size_t)row * Dd;
    __shared__ float red[256];

    float s = 0.f;
    for (int i = tid; i < Dd; i += 256) s += xr[i];
    red[tid] = s; __syncthreads();
    for (int off = 128; off > 0; off >>= 1) {
        if (tid < off) red[tid] += red[tid + off];
        __syncthreads();
    }
    const float mean = red[0] * (1.f / Dd);
    __syncthreads();

    float v = 0.f;
    for (int i = tid; i < Dd; i += 256) { float d = xr[i] - mean; v += d * d; }
    red[tid] = v; __syncthreads();
    for (int off = 128; off > 0; off >>= 1) {
        if (tid < off) red[tid] += red[tid + off];
        __syncthreads();
    }
    const float rstd = rsqrtf(red[0] * (1.f / Dd) + 1e-5f);

    float* orow = out + (size_t)row * Dd;
    for (int i = tid; i < Dd; i += 256)
        orow[i] = (xr[i] - mean) * rstd * g[i] + b[i];
}

// ---------------- RoPE (head-indexed freqs, faithful to reference) ----------------
__global__ void rope_kernel(float* __restrict__ q, float* __restrict__ k,
                            const float* __restrict__ fr)
{
    const int idx = blockIdx.x * blockDim.x + threadIdx.x;
    const int j  = idx & 63;
    const int h  = (idx >> 6) & 15;
    const int bt = idx >> 10;
    const size_t base = (size_t)bt * Dd + h * HDd + 2 * j;
    const float cr = fr[h * 128 + 2 * j];
    const float ci = fr[h * 128 + 2 * j + 1];
    float a = q[base], b2 = q[base + 1];
    q[base]     = a * cr - b2 * ci;
    q[base + 1] = a * ci + b2 * cr;
    a = k[base]; b2 = k[base + 1];
    k[base]     = a * cr - b2 * ci;
    k[base + 1] = a * ci + b2 * cr;
}

// ---------------- fused SiLU(gate)*up ----------------
__global__ void silu_mul_kernel(float* __restrict__ gbuf, const float* __restrict__ ubuf)
{
    const int idx = blockIdx.x * blockDim.x + threadIdx.x;
    const float gt = gbuf[idx];
    const float s = gt / (1.f + __expf(-gt));
    gbuf[idx] = s * ubuf[idx];
}

// ---------------- launch ----------------
extern "C" void kernel_launch(void* const* d_in, const int* in_sizes, int n_in,
                              void* d_out, int out_size)
{
    const float* x   = (const float*)d_in[0];
    const float* fr  = (const float*)d_in[1];
    const float* Wq  = (const float*)d_in[2];
    const float* bq  = (const float*)d_in[3];
    const float* Wk  = (const float*)d_in[4];
    const float* bk  = (const float*)d_in[5];
    const float* Wv  = (const float*)d_in[6];
    const float* bv  = (const float*)d_in[7];
    const float* Wo  = (const float*)d_in[8];
    const float* bo  = (const float*)d_in[9];
    const float* g1  = (const float*)d_in[10];
    const float* be1 = (const float*)d_in[11];
    const float* g2  = (const float*)d_in[12];
    const float* be2 = (const float*)d_in[13];
    const float* Wg  = (const float*)d_in[14];
    const float* bg  = (const float*)d_in[15];
    const float* Wu  = (const float*)d_in[16];
    const float* bu  = (const float*)d_in[17];
    const float* Wd  = (const float*)d_in[18];
    const float* bd  = (const float*)d_in[19];
    float* out = (float*)d_out;

    float *xn, *q, *k, *v, *attn, *ff1, *ff2;
    __nv_bfloat16 *Ahi, *Alo, *Bhi, *Blo, *fQh, *fQl, *fKh, *fKl, *fVh, *fVl;
    cudaGetSymbolAddress((void**)&xn,   g_xn);
    cudaGetSymbolAddress((void**)&q,    g_q);
    cudaGetSymbolAddress((void**)&k,    g_k);
    cudaGetSymbolAddress((void**)&v,    g_v);
    cudaGetSymbolAddress((void**)&attn, g_attn);
    cudaGetSymbolAddress((void**)&ff1,  g_ff1);
    cudaGetSymbolAddress((void**)&ff2,  g_ff2);
    cudaGetSymbolAddress((void**)&Ahi,  g_Ahi);
    cudaGetSymbolAddress((void**)&Alo,  g_Alo);
    cudaGetSymbolAddress((void**)&Bhi,  g_Bhi);
    cudaGetSymbolAddress((void**)&Blo,  g_Blo);
    cudaGetSymbolAddress((void**)&fQh,  g_fQh);
    cudaGetSymbolAddress((void**)&fQl,  g_fQl);
    cudaGetSymbolAddress((void**)&fKh,  g_fKh);
    cudaGetSymbolAddress((void**)&fKl,  g_fKl);
    cudaGetSymbolAddress((void**)&fVh,  g_fVh);
    cudaGetSymbolAddress((void**)&fVl,  g_fVl);

    cudaFuncSetAttribute(mma_gemm_kernel, cudaFuncAttributeMaxDynamicSharedMemorySize, GEMM_SMEM);
    cudaFuncSetAttribute(flash_mma_kernel, cudaFuncAttributeMaxDynamicSharedMemorySize, FLASH_SMEM);

    const int DD  = ROWS * Dd;   // 8M
    const int DW  = Dd * Dd;     // 4M
    const int FW  = FFd * Dd;    // 16M
    const int DF  = ROWS * FFd;  // 32M

#define SPLIT(src, hi, lo, n) split_kernel<<<((n)/4 + 255)/256, 256>>>(src, hi, lo, (n)/4)

    // 1) LN1
    ln_kernel<<<ROWS, 256>>>(x, g1, be1, xn);

    // 2) Q,K,V projections
    SPLIT(xn, Ahi, Alo, DD);
    dim3 gD(2 * (Dd / 256), ROWS / 256);
    SPLIT(Wq, Bhi, Blo, DW);
    mma_gemm_kernel<<<gD, GEMM_THREADS, GEMM_SMEM>>>(Ahi, Alo, Bhi, Blo, bq, nullptr, q, ROWS, Dd, Dd);
    SPLIT(Wk, Bhi, Blo, DW);
    mma_gemm_kernel<<<gD, GEMM_THREADS, GEMM_SMEM>>>(Ahi, Alo, Bhi, Blo, bk, nullptr, k, ROWS, Dd, Dd);
    SPLIT(Wv, Bhi, Blo, DW);
    mma_gemm_kernel<<<gD, GEMM_THREADS, GEMM_SMEM>>>(Ahi, Alo, Bhi, Blo, bv, nullptr, v, ROWS, Dd, Dd);

    // 3) RoPE, then split q/k and transpose+split v for the MMA flash
    rope_kernel<<<(Bb * Tt * Hh * (HDd / 2)) / 256, 256>>>(q, k, fr);
    SPLIT(q, fQh, fQl, DD);
    SPLIT(k, fKh, fKl, DD);
    vtrans_kernel<<<dim3(Tt / 32, HDd / 32, Bb * Hh), dim3(32, 8)>>>(v, fVh, fVl);

    // 4) causal flash attention (tcgen05)
    flash_mma_kernel<<<dim3(Tt / 128, Hh, Bb), 256, FLASH_SMEM>>>(
        fQh, fQl, fKh, fKl, fVh, fVl, attn);

    // 5) output projection + residual(x) -> out
    SPLIT(attn, Ahi, Alo, DD);
    SPLIT(Wo, Bhi, Blo, DW);
    mma_gemm_kernel<<<gD, GEMM_THREADS, GEMM_SMEM>>>(Ahi, Alo, Bhi, Blo, bo, x, out, ROWS, Dd, Dd);

    // 6) LN2
    ln_kernel<<<ROWS, 256>>>(out, g2, be2, xn);

    // 7) gate / up
    SPLIT(xn, Ahi, Alo, DD);
    dim3 gF(2 * (FFd / 256), ROWS / 256);
    SPLIT(Wg, Bhi, Blo, FW);
    mma_gemm_kernel<<<gF, GEMM_THREADS, GEMM_SMEM>>>(Ahi, Alo, Bhi, Blo, bg, nullptr, ff1, ROWS, FFd, Dd);
    SPLIT(Wu, Bhi, Blo, FW);
    mma_gemm_kernel<<<gF, GEMM_THREADS, GEMM_SMEM>>>(Ahi, Alo, Bhi, Blo, bu, nullptr, ff2, ROWS, FFd, Dd);

    // 8) SiLU(gate)*up
    silu_mul_kernel<<<(ROWS * FFd) / 256, 256>>>(ff1, ff2);

    // 9) down projection + residual(out) -> out
    SPLIT(ff1, Ahi, Alo, DF);
    SPLIT(Wd, Bhi, Blo, FW);
    mma_gemm_kernel<<<gD, GEMM_THREADS, GEMM_SMEM>>>(Ahi, Alo, Bhi, Blo, bd, out, out, ROWS, Dd, FFd);
}

// round 12
// speedup vs baseline: 6.6457x; 1.0625x over previous
#include <cuda_runtime.h>
#include <cuda_bf16.h>
#include <cstdint>
#include <math.h>

#define Bb 2
#define Tt 2048
#define Dd 2048
#define Hh 16
#define HDd 128
#define FFd 8192
#define ROWS (Bb*Tt)   /* 4096 */

// tcgen05 only exists in arch-specific (sm_10xa) compilation phases.
#if defined(__CUDA_ARCH_FEAT_SM103_ALL) || defined(__CUDA_ARCH_FEAT_SM100_ALL) || \
    defined(__CUDA_ARCH_FEAT_SM101_ALL) || \
    (defined(__CUDA_ARCH_SPECIFIC__) && (__CUDA_ARCH_SPECIFIC__ >= 1000)) || \
    (defined(__CUDA_ARCH_FAMILY_SPECIFIC__) && (__CUDA_ARCH_FAMILY_SPECIFIC__ >= 1000))
#define HAS_TCGEN05 1
#else
#define HAS_TCGEN05 0
#endif

// ---------------- scratch (no allocations allowed -> device globals) ----------------
__device__ float g_q   [ROWS*Dd];
__device__ float g_k   [ROWS*Dd];
__device__ float g_v   [ROWS*Dd];
__device__ float g_ff1 [ROWS*FFd];
__device__ float g_ff2 [ROWS*FFd];
// bf16 split buffers (GEMM)
__device__ __nv_bfloat16 g_Ahi[ROWS*FFd];
__device__ __nv_bfloat16 g_Alo[ROWS*FFd];
__device__ __nv_bfloat16 g_Bhi[FFd*Dd];
__device__ __nv_bfloat16 g_Blo[FFd*Dd];
// bf16 split buffers (flash): Q/K in [b,t,h*hd]; Vt in [b,h,hd,t]
__device__ __nv_bfloat16 g_fQh[ROWS*Dd];
__device__ __nv_bfloat16 g_fQl[ROWS*Dd];
__device__ __nv_bfloat16 g_fKh[ROWS*Dd];
__device__ __nv_bfloat16 g_fKl[ROWS*Dd];
__device__ __nv_bfloat16 g_fVh[ROWS*Dd];
__device__ __nv_bfloat16 g_fVl[ROWS*Dd];

// ================= helpers =================
__device__ __forceinline__ uint32_t smem_u32(const void* p) {
    uint32_t a;
    asm("{ .reg .u64 t; cvta.to.shared.u64 t, %1; cvt.u32.u64 %0, t; }"
        : "=r"(a) : "l"(p));
    return a;
}

#define SW128(o) ((o) ^ (((o) >> 3) & 0x70))

static constexpr uint64_t DESC_BASE_SW128 =
    (uint64_t(2)  << 61) | (uint64_t(1) << 46) | (uint64_t(64) << 32) | (uint64_t(1) << 16);

// idescs (kind::f16): dtype=F32(1<<4), atype/btype=BF16
#define MMA_IDESC_CG2 0x10400490u   /* M=256, N=256 */
#define MMA_IDESC_QK  0x08100490u   /* M=128, N=64  */
#define MMA_IDESC_PV  0x08200490u   /* M=128, N=128 */

// split one fp32 into bf16 hi/lo
__device__ __forceinline__ void split1(float v, __nv_bfloat16& h, __nv_bfloat16& l) {
    h = __float2bfloat16(v);
    l = __float2bfloat16(v - __bfloat162float(h));
}
// pack two fp32 into bf16x2 hi and lo words
__device__ __forceinline__ void split2(float a, float b, uint32_t& hw, uint32_t& lw) {
    __nv_bfloat162 h = __floats2bfloat162_rn(a, b);
    float la = a - __bfloat162float(__low2bfloat16(h));
    float lb = b - __bfloat162float(__high2bfloat16(h));
    __nv_bfloat162 l = __floats2bfloat162_rn(la, lb);
    hw = *reinterpret_cast<uint32_t*>(&h);
    lw = *reinterpret_cast<uint32_t*>(&l);
}

#if HAS_TCGEN05
__device__ __forceinline__ uint64_t mkdesc(uint32_t addr) {
    return DESC_BASE_SW128 | ((uint64_t)(addr >> 4) & 0x3FFF);
}
__device__ __forceinline__ void mma_bf16_ss_cg2(uint32_t d, uint64_t ad, uint64_t bd, uint32_t en) {
    asm volatile(
        "{\n\t.reg .pred p;\n\tsetp.ne.u32 p, %4, 0;\n\t"
        "tcgen05.mma.cta_group::2.kind::f16 [%0], %1, %2, %3, {%5,%5,%5,%5,%5,%5,%5,%5}, p;\n\t}"
        :: "r"(d), "l"(ad), "l"(bd), "r"(MMA_IDESC_CG2), "r"(en), "r"(0u) : "memory");
}
__device__ __forceinline__ void mma_ss_cg1(uint32_t d, uint64_t ad, uint64_t bd,
                                           uint32_t idesc, uint32_t en) {
    asm volatile(
        "{\n\t.reg .pred p;\n\tsetp.ne.u32 p, %4, 0;\n\t"
        "tcgen05.mma.cta_group::1.kind::f16 [%0], %1, %2, %3, {%5,%5,%5,%5}, p;\n\t}"
        :: "r"(d), "l"(ad), "l"(bd), "r"(idesc), "r"(en), "r"(0u) : "memory");
}
__device__ __forceinline__ void mbar_init(uint32_t m, uint32_t cnt) {
    asm volatile("mbarrier.init.shared.b64 [%0], %1;" :: "r"(m), "r"(cnt) : "memory");
}
__device__ __forceinline__ void mbar_wait(uint32_t m, uint32_t parity) {
    asm volatile(
        "{\n\t.reg .pred P1;\n"
        "W%=:\n\t"
        "mbarrier.try_wait.parity.acquire.cta.shared::cta.b64 P1, [%0], %1, 0x989680;\n\t"
        "@P1 bra.uni D%=;\n\t"
        "bra.uni W%=;\n"
        "D%=:\n\t}"
        :: "r"(m), "r"(parity) : "memory");
}
__device__ __forceinline__ void tc_commit_cg1(uint32_t m) {
    asm volatile("tcgen05.commit.cta_group::1.mbarrier::arrive::one.shared::cluster.b64 [%0];"
                 :: "r"(m) : "memory");
}
__device__ __forceinline__ void tc_commit_mc2(uint32_t m) {
    asm volatile(
        "tcgen05.commit.cta_group::2.mbarrier::arrive::one.shared::cluster.multicast::cluster.b64 [%0], %1;"
        :: "r"(m), "h"((uint16_t)0x3) : "memory");
}
__device__ __forceinline__ void mbar_arrive_rank0(uint32_t local_addr) {
    asm volatile(
        "{\n\t.reg .b32 ra;\n\t"
        "mapa.shared::cluster.u32 ra, %0, %1;\n\t"
        "mbarrier.arrive.shared::cluster.b64 _, [ra];\n\t}"
        :: "r"(local_addr), "r"(0) : "memory");
}
__device__ __forceinline__ void ldtm32(uint32_t* r, uint32_t a) {
    asm volatile(
        "tcgen05.ld.sync.aligned.32x32b.x32.b32 "
        "{%0,%1,%2,%3,%4,%5,%6,%7,%8,%9,%10,%11,%12,%13,%14,%15,"
        "%16,%17,%18,%19,%20,%21,%22,%23,%24,%25,%26,%27,%28,%29,%30,%31}, [%32];"
        : "=r"(r[0]),"=r"(r[1]),"=r"(r[2]),"=r"(r[3]),"=r"(r[4]),"=r"(r[5]),"=r"(r[6]),"=r"(r[7]),
          "=r"(r[8]),"=r"(r[9]),"=r"(r[10]),"=r"(r[11]),"=r"(r[12]),"=r"(r[13]),"=r"(r[14]),"=r"(r[15]),
          "=r"(r[16]),"=r"(r[17]),"=r"(r[18]),"=r"(r[19]),"=r"(r[20]),"=r"(r[21]),"=r"(r[22]),"=r"(r[23]),
          "=r"(r[24]),"=r"(r[25]),"=r"(r[26]),"=r"(r[27]),"=r"(r[28]),"=r"(r[29]),"=r"(r[30]),"=r"(r[31])
        : "r"(a));
}
__device__ __forceinline__ void sttm32(uint32_t a, const uint32_t* r) {
    asm volatile(
        "tcgen05.st.sync.aligned.32x32b.x32.b32 [%32], "
        "{%0,%1,%2,%3,%4,%5,%6,%7,%8,%9,%10,%11,%12,%13,%14,%15,"
        "%16,%17,%18,%19,%20,%21,%22,%23,%24,%25,%26,%27,%28,%29,%30,%31};"
        :: "r"(r[0]),"r"(r[1]),"r"(r[2]),"r"(r[3]),"r"(r[4]),"r"(r[5]),"r"(r[6]),"r"(r[7]),
           "r"(r[8]),"r"(r[9]),"r"(r[10]),"r"(r[11]),"r"(r[12]),"r"(r[13]),"r"(r[14]),"r"(r[15]),
           "r"(r[16]),"r"(r[17]),"r"(r[18]),"r"(r[19]),"r"(r[20]),"r"(r[21]),"r"(r[22]),"r"(r[23]),
           "r"(r[24]),"r"(r[25]),"r"(r[26]),"r"(r[27]),"r"(r[28]),"r"(r[29]),"r"(r[30]),"r"(r[31]),
           "r"(a)
        : "memory");
}
__device__ __forceinline__ void cpasync16(uint32_t dst, const void* src) {
    asm volatile("cp.async.cg.shared.global [%0], [%1], 16;" :: "r"(dst), "l"(src) : "memory");
}
__device__ __forceinline__ void cp_arrive(uint32_t m) {
    asm volatile("cp.async.mbarrier.arrive.noinc.shared.b64 [%0];" :: "r"(m) : "memory");
}
#define CP_COMMIT() asm volatile("cp.async.commit_group;" ::: "memory")
#define CP_WAIT0()  asm volatile("cp.async.wait_group 0;" ::: "memory")
#define TC_WAIT_LD() asm volatile("tcgen05.wait::ld.sync.aligned;" ::: "memory")
#define TC_WAIT_ST() asm volatile("tcgen05.wait::st.sync.aligned;" ::: "memory")
#define TC_FENCE_BEFORE() asm volatile("tcgen05.fence::before_thread_sync;" ::: "memory")
#define TC_FENCE_AFTER()  asm volatile("tcgen05.fence::after_thread_sync;" ::: "memory")
#define CLUSTER_SYNC() do { \
    asm volatile("barrier.cluster.arrive.aligned;" ::: "memory"); \
    asm volatile("barrier.cluster.wait.aligned;" ::: "memory"); \
} while (0)
#endif  // HAS_TCGEN05

// ---------------- split fp32 -> bf16 hi/lo (weights etc.) ----------------
__global__ void __launch_bounds__(256) split_kernel(const float* __restrict__ src,
                                                    __nv_bfloat16* __restrict__ hi,
                                                    __nv_bfloat16* __restrict__ lo,
                                                    int n4)
{
    int idx = blockIdx.x * blockDim.x + threadIdx.x;
    if (idx >= n4) return;
    float4 v = ((const float4*)src)[idx];
    uint2 ho, loo;
    split2(v.x, v.y, ho.x, loo.x);
    split2(v.z, v.w, ho.y, loo.y);
    ((uint2*)hi)[idx] = ho;
    ((uint2*)lo)[idx] = loo;
}

// ---------------- LayerNorm emitting bf16 hi/lo directly ----------------
__global__ void __launch_bounds__(256) ln_split_kernel(const float* __restrict__ x,
                                                       const float* __restrict__ g,
                                                       const float* __restrict__ b,
                                                       __nv_bfloat16* __restrict__ hi,
                                                       __nv_bfloat16* __restrict__ lo)
{
    const int row = blockIdx.x;
    const int tid = threadIdx.x;
    const float* xr = x + (size_t)row * Dd;
    __shared__ float red[256];

    float s = 0.f;
    for (int i = tid; i < Dd; i += 256) s += xr[i];
    red[tid] = s; __syncthreads();
    for (int off = 128; off > 0; off >>= 1) {
        if (tid < off) red[tid] += red[tid + off];
        __syncthreads();
    }
    const float mean = red[0] * (1.f / Dd);
    __syncthreads();

    float v = 0.f;
    for (int i = tid; i < Dd; i += 256) { float d = xr[i] - mean; v += d * d; }
    red[tid] = v; __syncthreads();
    for (int off = 128; off > 0; off >>= 1) {
        if (tid < off) red[tid] += red[tid + off];
        __syncthreads();
    }
    const float rstd = rsqrtf(red[0] * (1.f / Dd) + 1e-5f);

    uint2* hrow = (uint2*)(hi + (size_t)row * Dd);
    uint2* lrow = (uint2*)(lo + (size_t)row * Dd);
    for (int i4 = tid; i4 < Dd / 4; i4 += 256) {
        const int i = i4 * 4;
        float v0 = (xr[i + 0] - mean) * rstd * g[i + 0] + b[i + 0];
        float v1 = (xr[i + 1] - mean) * rstd * g[i + 1] + b[i + 1];
        float v2 = (xr[i + 2] - mean) * rstd * g[i + 2] + b[i + 2];
        float v3 = (xr[i + 3] - mean) * rstd * g[i + 3] + b[i + 3];
        uint2 ho, loo;
        split2(v0, v1, ho.x, loo.x);
        split2(v2, v3, ho.y, loo.y);
        hrow[i4] = ho;
        lrow[i4] = loo;
    }
}

// ---------------- RoPE reading fp32 q/k, writing rotated bf16 hi/lo ----------------
__global__ void rope_split_kernel(const float* __restrict__ q, const float* __restrict__ k,
                                  const float* __restrict__ fr,
                                  __nv_bfloat16* __restrict__ Qh, __nv_bfloat16* __restrict__ Ql,
                                  __nv_bfloat16* __restrict__ Kh, __nv_bfloat16* __restrict__ Kl)
{
    const int idx = blockIdx.x * blockDim.x + threadIdx.x;   // < B*T*H*(HD/2)
    const int j  = idx & 63;
    const int h  = (idx >> 6) & 15;
    const int bt = idx >> 10;
    const size_t base = (size_t)bt * Dd + h * HDd + 2 * j;
    const float cr = fr[h * 128 + 2 * j];
    const float ci = fr[h * 128 + 2 * j + 1];

    float a = q[base], b2 = q[base + 1];
    float r0 = a * cr - b2 * ci;
    float r1 = a * ci + b2 * cr;
    uint32_t hw, lw;
    split2(r0, r1, hw, lw);
    *(uint32_t*)(Qh + base) = hw;
    *(uint32_t*)(Ql + base) = lw;

    a = k[base]; b2 = k[base + 1];
    r0 = a * cr - b2 * ci;
    r1 = a * ci + b2 * cr;
    split2(r0, r1, hw, lw);
    *(uint32_t*)(Kh + base) = hw;
    *(uint32_t*)(Kl + base) = lw;
}

// ---------------- V transpose+split: v[b,t,h*hd] -> Vt[b,h,hd,t] bf16 hi/lo ----------------
__global__ void __launch_bounds__(256) vtrans_kernel(const float* __restrict__ v,
                                                     __nv_bfloat16* __restrict__ Vth,
                                                     __nv_bfloat16* __restrict__ Vtl)
{
    __shared__ float tile[32][33];
    const int bh = blockIdx.z;
    const int b  = bh >> 4, h = bh & 15;
    const int t0 = blockIdx.x * 32;
    const int d0 = blockIdx.y * 32;
    const int x = threadIdx.x, y = threadIdx.y;  // (32,8)
#pragma unroll
    for (int i = 0; i < 4; i++) {
        int t = t0 + y + i * 8;
        tile[y + i * 8][x] = v[(size_t)(b * Tt + t) * Dd + h * HDd + d0 + x];
    }
    __syncthreads();
#pragma unroll
    for (int i = 0; i < 4; i++) {
        int hd = d0 + y + i * 8;
        float val = tile[x][y + i * 8];
        __nv_bfloat16 hi, lo;
        split1(val, hi, lo);
        size_t idx = (size_t)(bh * HDd + hd) * Tt + t0 + x;
        Vth[idx] = hi;
        Vtl[idx] = lo;
    }
}

// ---------------- fused SiLU(gate)*up -> bf16 hi/lo ----------------
__global__ void __launch_bounds__(256) silu_split_kernel(const float* __restrict__ gbuf,
                                                         const float* __restrict__ ubuf,
                                                         __nv_bfloat16* __restrict__ hi,
                                                         __nv_bfloat16* __restrict__ lo)
{
    const int idx = blockIdx.x * blockDim.x + threadIdx.x;  // over float4
    float4 gv = ((const float4*)gbuf)[idx];
    float4 uv = ((const float4*)ubuf)[idx];
    float v0 = gv.x / (1.f + __expf(-gv.x)) * uv.x;
    float v1 = gv.y / (1.f + __expf(-gv.y)) * uv.y;
    float v2 = gv.z / (1.f + __expf(-gv.z)) * uv.z;
    float v3 = gv.w / (1.f + __expf(-gv.w)) * uv.w;
    uint2 ho, loo;
    split2(v0, v1, ho.x, loo.x);
    split2(v2, v3, ho.y, loo.y);
    ((uint2*)hi)[idx] = ho;
    ((uint2*)lo)[idx] = loo;
}

// ============ cg2 GEMM, warp-specialized (unchanged core from R10, passing) ============
#define NSTAGE 3
#define STAGE_BYTES 65536
#define GEMM_SMEM (1024 + NSTAGE * STAGE_BYTES)
#define GEMM_THREADS 288

__global__ void __launch_bounds__(GEMM_THREADS, 1) __cluster_dims__(2, 1, 1)
mma_gemm_kernel(const __nv_bfloat16* __restrict__ Ah, const __nv_bfloat16* __restrict__ Al,
                const __nv_bfloat16* __restrict__ Bh, const __nv_bfloat16* __restrict__ Bl,
                const float* __restrict__ bias, const float* __restrict__ resid,
                float* __restrict__ C, int M, int N, int K)
{
    extern __shared__ char smem[];
#if HAS_TCGEN05
    const uint32_t sbase = smem_u32(smem);
    const int tid  = threadIdx.x;
    const int wid  = tid >> 5;
    const int lane = tid & 31;
    const int rank = blockIdx.x & 1;
    const int bn   = (blockIdx.x >> 1) * 256;
    const int bm   = blockIdx.y * 256;

    const uint32_t tile_abs = (sbase + 128 + 1023) & ~1023u;
    const uint32_t mb_full  = sbase + 8;
    const uint32_t mb_f2    = sbase + 32;
    const uint32_t mb_empty = sbase + 56;

    if (wid == 0) {
        asm volatile("tcgen05.alloc.cta_group::2.sync.aligned.shared::cta.b32 [%0], %1;"
                     :: "r"(sbase), "r"(256u) : "memory");
        asm volatile("tcgen05.relinquish_alloc_permit.cta_group::2.sync.aligned;");
    }
    if (tid == 0) {
#pragma unroll
        for (int s = 0; s < NSTAGE; s++) {
            mbar_init(mb_full  + s * 8, 256);
            mbar_init(mb_f2    + s * 8, 2);
            mbar_init(mb_empty + s * 8, 1);
        }
    }
    __syncthreads();
    CLUSTER_SYNC();

    uint32_t tmem;
    asm volatile("ld.shared.b32 %0, [%1];" : "=r"(tmem) : "r"(sbase));

    const int n = K >> 6;

    if (tid < 256) {
        const int r  = tid >> 1;
        const int hh = tid & 1;
        const uint32_t off = r * 128 + hh * 64;
        const __nv_bfloat16* AgH = Ah + (size_t)(bm + rank * 128 + r) * K + hh * 32;
        const __nv_bfloat16* AgL = Al + (size_t)(bm + rank * 128 + r) * K + hh * 32;
        const __nv_bfloat16* BgH = Bh + (size_t)(bn + rank * 128 + r) * K + hh * 32;
        const __nv_bfloat16* BgL = Bl + (size_t)(bn + rank * 128 + r) * K + hh * 32;

        for (int c = 0; c < n; c++) {
            const int s = c % NSTAGE;
            const int use = c / NSTAGE;
            if (c >= NSTAGE) mbar_wait(mb_empty + s * 8, (use - 1) & 1);

            const uint32_t sb = tile_abs + s * STAGE_BYTES;
            const size_t kof = (size_t)c * 64;
#pragma unroll
            for (int j = 0; j < 4; j++) {
                const uint32_t o = SW128(off + j * 16);
                cpasync16(sb + o,         AgH + kof + j * 8);
                cpasync16(sb + 16384 + o, AgL + kof + j * 8);
                cpasync16(sb + 32768 + o, BgH + kof + j * 8);
                cpasync16(sb + 49152 + o, BgL + kof + j * 8);
            }
            cp_arrive(mb_full + s * 8);
        }
    } else if (tid == 256) {
        for (int i = 0; i < n; i++) {
            const int si = i % NSTAGE;
            mbar_wait(mb_full + si * 8, (i / NSTAGE) & 1);
            mbar_arrive_rank0(mb_f2 + si * 8);
            if (rank == 0) {
                mbar_wait(mb_f2 + si * 8, (i / NSTAGE) & 1);
                asm volatile("fence.proxy.async.shared::cta;" ::: "memory");
                const uint32_t sbi = tile_abs + si * STAGE_BYTES;
                const uint64_t ah = mkdesc(sbi);
                const uint64_t al = mkdesc(sbi + 16384);
                const uint64_t bh = mkdesc(sbi + 32768);
                const uint64_t bl = mkdesc(sbi + 49152);
#pragma unroll
                for (int k = 0; k < 4; k++)
                    mma_bf16_ss_cg2(tmem, ah + k * 2, bh + k * 2, (i > 0 || k > 0) ? 1u : 0u);
#pragma unroll
                for (int k = 0; k < 4; k++)
                    mma_bf16_ss_cg2(tmem, ah + k * 2, bl + k * 2, 1u);
#pragma unroll
                for (int k = 0; k < 4; k++)
                    mma_bf16_ss_cg2(tmem, al + k * 2, bh + k * 2, 1u);
                tc_commit_mc2(mb_empty + si * 8);
            }
        }
    }

    {
        const int i = n - 1, si = i % NSTAGE;
        mbar_wait(mb_empty + si * 8, (i / NSTAGE) & 1);
    }
    TC_FENCE_AFTER();

    if (wid < 8) {
        const int sub  = wid & 3;
        const int half = wid >> 2;
        const int row  = bm + rank * 128 + sub * 32 + lane;
        const float* rrow = resid ? resid + (size_t)row * N : nullptr;
        float* crow = C + (size_t)row * N;
#pragma unroll 1
        for (int half2 = 0; half2 < 2; half2++) {
#pragma unroll 1
            for (int c32 = 0; c32 < 2; c32++) {
                uint32_t d[32];
                ldtm32(d, tmem + half2 * 128 + half * 64 + c32 * 32);
                TC_WAIT_LD();
                const int col0 = bn + half2 * 128 + half * 64 + c32 * 32;
                if (rrow) {
#pragma unroll
                    for (int j = 0; j < 32; j++)
                        crow[col0 + j] = __uint_as_float(d[j]) + bias[col0 + j] + rrow[col0 + j];
                } else {
#pragma unroll
                    for (int j = 0; j < 32; j++)
                        crow[col0 + j] = __uint_as_float(d[j]) + bias[col0 + j];
                }
            }
        }
    }
    __syncthreads();
    if (wid == 0) {
        asm volatile("tcgen05.dealloc.cta_group::2.sync.aligned.b32 %0, %1;"
                     :: "r"(tmem), "r"(256u));
    }
    CLUSTER_SYNC();
#else
    float* As = (float*)smem;
    float* Bs = As + 8 * 128;
    const int tid = threadIdx.x;
    const int rank = blockIdx.x & 1;
    const int bm = blockIdx.y * 256 + rank * 128;
    const int bn0 = (blockIdx.x >> 1) * 256;
    const int lr  = tid >> 1;
    const int lcc = (tid & 1) * 4;
    const int tx = tid & 15, ty = tid >> 4;

    for (int h = 0; h < 2; h++) {
        const int bn = bn0 + h * 128;
        float acc[8][8];
#pragma unroll
        for (int i = 0; i < 8; i++)
#pragma unroll
            for (int j = 0; j < 8; j++) acc[i][j] = 0.f;

        for (int k0 = 0; k0 < K; k0 += 8) {
            if (tid < 256) {
                const __nv_bfloat16* aph = Ah + (size_t)(bm + lr) * K + k0 + lcc;
                const __nv_bfloat16* apl = Al + (size_t)(bm + lr) * K + k0 + lcc;
                const __nv_bfloat16* bph = Bh + (size_t)(bn + lr) * K + k0 + lcc;
                const __nv_bfloat16* bpl = Bl + (size_t)(bn + lr) * K + k0 + lcc;
#pragma unroll
                for (int j = 0; j < 4; j++) {
                    As[(lcc + j) * 128 + lr] = __bfloat162float(aph[j]) + __bfloat162float(apl[j]);
                    Bs[(lcc + j) * 128 + lr] = __bfloat162float(bph[j]) + __bfloat162float(bpl[j]);
                }
            }
            __syncthreads();
            if (tid < 256) {
#pragma unroll
                for (int kk = 0; kk < 8; kk++) {
                    float a[8], bb[8];
#pragma unroll
                    for (int i = 0; i < 8; i++)
                        a[i] = As[kk * 128 + ((i & 4) << 4) + ty * 4 + (i & 3)];
#pragma unroll
                    for (int j = 0; j < 8; j++)
                        bb[j] = Bs[kk * 128 + ((j & 4) << 4) + tx * 4 + (j & 3)];
#pragma unroll
                    for (int i = 0; i < 8; i++)
#pragma unroll
                        for (int j = 0; j < 8; j++)
                            acc[i][j] += a[i] * bb[j];
                }
            }
            __syncthreads();
        }

        if (tid < 256) {
#pragma unroll
            for (int i = 0; i < 8; i++) {
                const int row = bm + ((i & 4) << 4) + ty * 4 + (i & 3);
#pragma unroll
                for (int j = 0; j < 8; j++) {
                    const int col = bn + ((j & 4) << 4) + tx * 4 + (j & 3);
                    float vv = acc[i][j] + bias[col];
                    if (resid) vv += resid[(size_t)row * N + col];
                    C[(size_t)row * N + col] = vv;
                }
            }
        }
    }
#endif
}

// ============ tcgen05 flash attention; epilogue writes bf16 hi/lo (Wo's A operand) ============
#define FLASH_SMEM (1024 + 160 * 1024 + 1024)

__global__ void __launch_bounds__(256, 1) flash_mma_kernel(
    const __nv_bfloat16* __restrict__ Qh, const __nv_bfloat16* __restrict__ Ql,
    const __nv_bfloat16* __restrict__ Kh, const __nv_bfloat16* __restrict__ Kl,
    const __nv_bfloat16* __restrict__ Vh, const __nv_bfloat16* __restrict__ Vl,
    __nv_bfloat16* __restrict__ Ohi, __nv_bfloat16* __restrict__ Olo)
{
    extern __shared__ char smem[];
#if HAS_TCGEN05
    const uint32_t sbase = smem_u32(smem);
    const int tid  = threadIdx.x;
    const int wid  = tid >> 5;
    const int lane = tid & 31;
    const int qb = blockIdx.x, h = blockIdx.y, b = blockIdx.z;
    const int q0 = qb * 128;

    const uint32_t mb_qk = sbase + 8;
    const uint32_t mb_pv = sbase + 16;
    int*   flags  = (int*)(smem + 24);
    float* redbuf = (float*)(smem + 64);
    const uint32_t tile_abs = (sbase + 576 + 1023) & ~1023u;
    const uint32_t tile_off = tile_abs - sbase;

    if (wid == 0) {
        asm volatile("tcgen05.alloc.cta_group::1.sync.aligned.shared::cta.b32 [%0], %1;"
                     :: "r"(sbase), "r"(256u) : "memory");
        asm volatile("tcgen05.relinquish_alloc_permit.cta_group::1.sync.aligned;");
    }
    if (tid == 0) { mbar_init(mb_qk, 1); mbar_init(mb_pv, 1); }
    __syncthreads();
    uint32_t tmem;
    asm volatile("ld.shared.b32 %0, [%1];" : "=r"(tmem) : "r"(sbase));
    const uint32_t tm_S = tmem;
    const uint32_t tm_O = tmem + 64;

#pragma unroll
    for (int i = 0; i < 2; i++) {
        int u = tid * 2 + i;
        int buf = u >> 8, rem = u & 255, half = rem >> 7, row = rem & 127;
        const __nv_bfloat16* src = (buf ? Ql : Qh)
            + (size_t)(b * Tt + q0 + row) * Dd + h * HDd + half * 64;
        uint32_t dst = tile_abs + buf * 32768 + half * 16384;
        uint32_t off = row * 128;
#pragma unroll
        for (int j = 0; j < 8; j++)
            cpasync16(dst + SW128(off + j * 16), src + j * 8);
    }
    CP_COMMIT();

    const int sw   = wid & 3;
    const int colh = wid >> 2;
    const int row  = sw * 32 + lane;
    const float scale = 0.088388347648318447f;

    float m = -1e30f, l = 0.f;
    const int nt = 2 * qb + 2;

    for (int t = 0; t < nt; t++) {
        const int j0 = t * 64;
        if (t > 0) mbar_wait(mb_pv, (t - 1) & 1);

#pragma unroll
        for (int i = 0; i < 2; i++) {
            int u = tid * 2 + i;
            const __nv_bfloat16* src;
            uint32_t dst, off;
            if (u < 256) {
                int kr = u & 63, half = (u >> 6) & 1, buf = u >> 7;
                src = (buf ? Kl : Kh) + (size_t)(b * Tt + j0 + kr) * Dd + h * HDd + half * 64;
                dst = tile_abs + 65536 + buf * 16384 + half * 8192;
                off = kr * 128;
            } else {
                int u2 = u - 256;
                int vr = u2 & 127, buf = u2 >> 7;
                src = (buf ? Vl : Vh) + (size_t)((b * Hh + h) * HDd + vr) * Tt + j0;
                dst = tile_abs + 98304 + buf * 16384;
                off = vr * 128;
            }
#pragma unroll
            for (int j = 0; j < 8; j++)
                cpasync16(dst + SW128(off + j * 16), src + j * 8);
        }
        CP_COMMIT();
        CP_WAIT0();
        __syncthreads();

        if (tid == 0) {
            asm volatile("fence.proxy.async.shared::cta;" ::: "memory");
            uint64_t qd[2][2], kd[2][2];
            qd[0][0] = mkdesc(tile_abs);          qd[0][1] = mkdesc(tile_abs + 16384);
            qd[1][0] = mkdesc(tile_abs + 32768);  qd[1][1] = mkdesc(tile_abs + 49152);
            kd[0][0] = mkdesc(tile_abs + 65536);  kd[0][1] = mkdesc(tile_abs + 73728);
            kd[1][0] = mkdesc(tile_abs + 81920);  kd[1][1] = mkdesc(tile_abs + 90112);
            int first = 1;
#pragma unroll
            for (int c3 = 0; c3 < 3; c3++) {
                const int ab = (c3 == 2) ? 1 : 0;
                const int bb = (c3 == 1) ? 1 : 0;
#pragma unroll
                for (int ks = 0; ks < 8; ks++) {
                    const int half = ks >> 2;
                    const uint64_t o = (uint64_t)((ks & 3) * 2);
                    mma_ss_cg1(tm_S, qd[ab][half] + o, kd[bb][half] + o,
                               MMA_IDESC_QK, first ? 0u : 1u);
                    first = 0;
                }
            }
            tc_commit_cg1(mb_qk);
        }
        mbar_wait(mb_qk, t & 1);
        TC_FENCE_AFTER();

        if (wid < 4) {
            uint32_t sr[64];
            ldtm32(sr,      tm_S);
            ldtm32(sr + 32, tm_S + 32);
            TC_WAIT_LD();
            float sv[64];
            float tmax = -1e30f;
#pragma unroll
            for (int c = 0; c < 64; c++) {
                float x = __uint_as_float(sr[c]) * scale;
                if (j0 + c > q0 + row) x = -1e30f;
                sv[c] = x;
                tmax = fmaxf(tmax, x);
            }
            const float mnew = fmaxf(m, tmax);
            const float alpha = __expf(m - mnew);
            m = mnew;
            float psum = 0.f;
#pragma unroll
            for (int c = 0; c < 64; c++) {
                float p = __expf(sv[c] - mnew);
                sv[c] = p;
                psum += p;
            }
            l = l * alpha + psum;
            const uint32_t prow = row * 128;
#pragma unroll
            for (int g = 0; g < 16; g++) {
                const int c = g * 4;
                uint2 hv, lv;
                split2(sv[c],     sv[c + 1], hv.x, lv.x);
                split2(sv[c + 2], sv[c + 3], hv.y, lv.y);
                const uint32_t o = SW128(prow + c * 2);
                *(uint2*)(smem + tile_off + 131072 + o) = hv;
                *(uint2*)(smem + tile_off + 147456 + o) = lv;
            }
            asm volatile("fence.proxy.async.shared::cta;" ::: "memory");
            redbuf[row] = alpha;
            unsigned bal = __ballot_sync(0xffffffffu, alpha < 0.999999f);
            if (lane == 0) flags[wid] = (bal != 0) ? 1 : 0;
        }
        __syncthreads();

        if (t > 0 && ((volatile int*)flags)[sw]) {
            const float av = ((volatile float*)redbuf)[row];
            uint32_t o0[32], o1[32];
            ldtm32(o0, tm_O + colh * 64);
            ldtm32(o1, tm_O + colh * 64 + 32);
            TC_WAIT_LD();
#pragma unroll
            for (int j = 0; j < 32; j++) {
                o0[j] = __float_as_uint(__uint_as_float(o0[j]) * av);
                o1[j] = __float_as_uint(__uint_as_float(o1[j]) * av);
            }
            sttm32(tm_O + colh * 64,      o0);
            sttm32(tm_O + colh * 64 + 32, o1);
            TC_WAIT_ST();
        }
        TC_FENCE_BEFORE();
        __syncthreads();

        if (tid == 0) {
            TC_FENCE_AFTER();
            asm volatile("fence.proxy.async.shared::cta;" ::: "memory");
            uint64_t pd[2], vd[2];
            pd[0] = mkdesc(tile_abs + 131072); pd[1] = mkdesc(tile_abs + 147456);
            vd[0] = mkdesc(tile_abs + 98304);  vd[1] = mkdesc(tile_abs + 114688);
            int first = (t == 0) ? 1 : 0;
#pragma unroll
            for (int c3 = 0; c3 < 3; c3++) {
                const int ab = (c3 == 1) ? 1 : 0;
                const int bb = (c3 == 2) ? 1 : 0;
#pragma unroll
                for (int ks = 0; ks < 4; ks++) {
                    const uint64_t o = (uint64_t)(ks * 2);
                    mma_ss_cg1(tm_O, pd[ab] + o, vd[bb] + o,
                               MMA_IDESC_PV, first ? 0u : 1u);
                    first = 0;
                }
            }
            tc_commit_cg1(mb_pv);
        }
    }

    mbar_wait(mb_pv, (nt - 1) & 1);
    TC_FENCE_AFTER();
    if (wid < 4) redbuf[row] = 1.f / l;
    __syncthreads();

    // ---- epilogue: O/l -> bf16 hi/lo directly ----
    {
        const float linv = ((volatile float*)redbuf)[row];
        uint32_t o0[32], o1[32];
        ldtm32(o0, tm_O + colh * 64);
        ldtm32(o1, tm_O + colh * 64 + 32);
        TC_WAIT_LD();
        const size_t obase = (size_t)(b * Tt + q0 + row) * Dd + h * HDd + colh * 64;
        uint32_t* hrow = (uint32_t*)(Ohi + obase);
        uint32_t* lrow = (uint32_t*)(Olo + obase);
#pragma unroll
        for (int j = 0; j < 16; j++) {
            uint32_t hw, lw;
            split2(__uint_as_float(o0[2 * j]) * linv,
                   __uint_as_float(o0[2 * j + 1]) * linv, hw, lw);
            hrow[j] = hw; lrow[j] = lw;
        }
#pragma unroll
        for (int j = 0; j < 16; j++) {
            uint32_t hw, lw;
            split2(__uint_as_float(o1[2 * j]) * linv,
                   __uint_as_float(o1[2 * j + 1]) * linv, hw, lw);
            hrow[16 + j] = hw; lrow[16 + j] = lw;
        }
    }
    __syncthreads();
    if (wid == 0) {
        asm volatile("tcgen05.dealloc.cta_group::1.sync.aligned.b32 %0, %1;"
                     :: "r"(tmem), "r"(256u));
    }
#else
    const int tid = threadIdx.x;
    const int qb = blockIdx.x, h = blockIdx.y, b = blockIdx.z;
    const int q0 = qb * 128;
    if (tid < 128) {
        const int rq = q0 + tid;
        float m = -1e30f, l = 0.f, o[128];
        for (int d = 0; d < 128; d++) o[d] = 0.f;
        for (int j = 0; j <= rq; j++) {
            float s = 0.f;
            const size_t qo = (size_t)(b * Tt + rq) * Dd + h * HDd;
            const size_t ko = (size_t)(b * Tt + j) * Dd + h * HDd;
            for (int d = 0; d < 128; d++) {
                float qv = __bfloat162float(Qh[qo + d]) + __bfloat162float(Ql[qo + d]);
                float kv = __bfloat162float(Kh[ko + d]) + __bfloat162float(Kl[ko + d]);
                s += qv * kv;
            }
            s *= 0.088388347648318447f;
            float mn = fmaxf(m, s);
            float al = __expf(m - mn), p = __expf(s - mn);
            m = mn;
            l = l * al + p;
            const size_t vo = (size_t)(b * Hh + h) * HDd;
            for (int d = 0; d < 128; d++) {
                float vv = __bfloat162float(Vh[(vo + d) * Tt + j]) +
                           __bfloat162float(Vl[(vo + d) * Tt + j]);
                o[d] = o[d] * al + p * vv;
            }
        }
        const size_t obase = (size_t)(b * Tt + rq) * Dd + h * HDd;
        for (int d = 0; d < 128; d++) {
            __nv_bfloat16 hi, lo;
            split1(o[d] / l, hi, lo);
            Ohi[obase + d] = hi;
            Olo[obase + d] = lo;
        }
    }
#endif
}

// ---------------- launch ----------------
extern "C" void kernel_launch(void* const* d_in, const int* in_sizes, int n_in,
                              void* d_out, int out_size)
{
    const float* x   = (const float*)d_in[0];
    const float* fr  = (const float*)d_in[1];
    const float* Wq  = (const float*)d_in[2];
    const float* bq  = (const float*)d_in[3];
    const float* Wk  = (const float*)d_in[4];
    const float* bk  = (const float*)d_in[5];
    const float* Wv  = (const float*)d_in[6];
    const float* bv  = (const float*)d_in[7];
    const float* Wo  = (const float*)d_in[8];
    const float* bo  = (const float*)d_in[9];
    const float* g1  = (const float*)d_in[10];
    const float* be1 = (const float*)d_in[11];
    const float* g2  = (const float*)d_in[12];
    const float* be2 = (const float*)d_in[13];
    const float* Wg  = (const float*)d_in[14];
    const float* bg  = (const float*)d_in[15];
    const float* Wu  = (const float*)d_in[16];
    const float* bu  = (const float*)d_in[17];
    const float* Wd  = (const float*)d_in[18];
    const float* bd  = (const float*)d_in[19];
    float* out = (float*)d_out;

    float *q, *k, *v, *ff1, *ff2;
    __nv_bfloat16 *Ahi, *Alo, *Bhi, *Blo, *fQh, *fQl, *fKh, *fKl, *fVh, *fVl;
    cudaGetSymbolAddress((void**)&q,    g_q);
    cudaGetSymbolAddress((void**)&k,    g_k);
    cudaGetSymbolAddress((void**)&v,    g_v);
    cudaGetSymbolAddress((void**)&ff1,  g_ff1);
    cudaGetSymbolAddress((void**)&ff2,  g_ff2);
    cudaGetSymbolAddress((void**)&Ahi,  g_Ahi);
    cudaGetSymbolAddress((void**)&Alo,  g_Alo);
    cudaGetSymbolAddress((void**)&Bhi,  g_Bhi);
    cudaGetSymbolAddress((void**)&Blo,  g_Blo);
    cudaGetSymbolAddress((void**)&fQh,  g_fQh);
    cudaGetSymbolAddress((void**)&fQl,  g_fQl);
    cudaGetSymbolAddress((void**)&fKh,  g_fKh);
    cudaGetSymbolAddress((void**)&fKl,  g_fKl);
    cudaGetSymbolAddress((void**)&fVh,  g_fVh);
    cudaGetSymbolAddress((void**)&fVl,  g_fVl);

    cudaFuncSetAttribute(mma_gemm_kernel, cudaFuncAttributeMaxDynamicSharedMemorySize, GEMM_SMEM);
    cudaFuncSetAttribute(flash_mma_kernel, cudaFuncAttributeMaxDynamicSharedMemorySize, FLASH_SMEM);

    const int DW  = Dd * Dd;     // 4M
    const int FW  = FFd * Dd;    // 16M
    const int DF  = ROWS * FFd;  // 32M

#define SPLIT(src, hi, lo, n) split_kernel<<<((n)/4 + 255)/256, 256>>>(src, hi, lo, (n)/4)

    // 1) LN1 -> bf16 hi/lo directly (A operand of QKV GEMMs)
    ln_split_kernel<<<ROWS, 256>>>(x, g1, be1, Ahi, Alo);

    // 2) Q,K,V projections
    dim3 gD(2 * (Dd / 256), ROWS / 256);
    SPLIT(Wq, Bhi, Blo, DW);
    mma_gemm_kernel<<<gD, GEMM_THREADS, GEMM_SMEM>>>(Ahi, Alo, Bhi, Blo, bq, nullptr, q, ROWS, Dd, Dd);
    SPLIT(Wk, Bhi, Blo, DW);
    mma_gemm_kernel<<<gD, GEMM_THREADS, GEMM_SMEM>>>(Ahi, Alo, Bhi, Blo, bk, nullptr, k, ROWS, Dd, Dd);
    SPLIT(Wv, Bhi, Blo, DW);
    mma_gemm_kernel<<<gD, GEMM_THREADS, GEMM_SMEM>>>(Ahi, Alo, Bhi, Blo, bv, nullptr, v, ROWS, Dd, Dd);

    // 3) RoPE fused with split; V transpose+split
    rope_split_kernel<<<(Bb * Tt * Hh * (HDd / 2)) / 256, 256>>>(q, k, fr, fQh, fQl, fKh, fKl);
    vtrans_kernel<<<dim3(Tt / 32, HDd / 32, Bb * Hh), dim3(32, 8)>>>(v, fVh, fVl);

    // 4) causal flash attention (tcgen05), writing hi/lo directly (A of Wo)
    flash_mma_kernel<<<dim3(Tt / 128, Hh, Bb), 256, FLASH_SMEM>>>(
        fQh, fQl, fKh, fKl, fVh, fVl, Ahi, Alo);

    // 5) output projection + residual(x) -> out
    SPLIT(Wo, Bhi, Blo, DW);
    mma_gemm_kernel<<<gD, GEMM_THREADS, GEMM_SMEM>>>(Ahi, Alo, Bhi, Blo, bo, x, out, ROWS, Dd, Dd);

    // 6) LN2 -> bf16 hi/lo directly (A operand of gate/up GEMMs)
    ln_split_kernel<<<ROWS, 256>>>(out, g2, be2, Ahi, Alo);

    // 7) gate / up
    dim3 gF(2 * (FFd / 256), ROWS / 256);
    SPLIT(Wg, Bhi, Blo, FW);
    mma_gemm_kernel<<<gF, GEMM_THREADS, GEMM_SMEM>>>(Ahi, Alo, Bhi, Blo, bg, nullptr, ff1, ROWS, FFd, Dd);
    SPLIT(Wu, Bhi, Blo, FW);
    mma_gemm_kernel<<<gF, GEMM_THREADS, GEMM_SMEM>>>(Ahi, Alo, Bhi, Blo, bu, nullptr, ff2, ROWS, FFd, Dd);

    // 8) SiLU(gate)*up fused with split (A operand of down GEMM)
    silu_split_kernel<<<(DF / 4) / 256, 256>>>(ff1, ff2, Ahi, Alo);

    // 9) down projection + residual(out) -> out
    SPLIT(Wd, Bhi, Blo, FW);
    mma_gemm_kernel<<<gD, GEMM_THREADS, GEMM_SMEM>>>(Ahi, Alo, Bhi, Blo, bd, out, out, ROWS, Dd, FFd);
}

// round 13
// speedup vs baseline: 6.7969x; 1.0228x over previous
#include <cuda_runtime.h>
#include <cuda_bf16.h>
#include <cstdint>
#include <math.h>

#define Bb 2
#define Tt 2048
#define Dd 2048
#define Hh 16
#define HDd 128
#define FFd 8192
#define ROWS (Bb*Tt)   /* 4096 */

// tcgen05 only exists in arch-specific (sm_10xa) compilation phases.
#if defined(__CUDA_ARCH_FEAT_SM103_ALL) || defined(__CUDA_ARCH_FEAT_SM100_ALL) || \
    defined(__CUDA_ARCH_FEAT_SM101_ALL) || \
    (defined(__CUDA_ARCH_SPECIFIC__) && (__CUDA_ARCH_SPECIFIC__ >= 1000)) || \
    (defined(__CUDA_ARCH_FAMILY_SPECIFIC__) && (__CUDA_ARCH_FAMILY_SPECIFIC__ >= 1000))
#define HAS_TCGEN05 1
#else
#define HAS_TCGEN05 0
#endif

// ---------------- scratch (no allocations allowed -> device globals) ----------------
__device__ float g_v   [ROWS*Dd];
__device__ float g_ff1 [ROWS*FFd];
__device__ float g_ff2 [ROWS*FFd];
// bf16 split buffers (GEMM)
__device__ __nv_bfloat16 g_Ahi[ROWS*FFd];
__device__ __nv_bfloat16 g_Alo[ROWS*FFd];
__device__ __nv_bfloat16 g_Bhi[FFd*Dd];
__device__ __nv_bfloat16 g_Blo[FFd*Dd];
// bf16 split buffers (flash): Q/K in [b,t,h*hd]; Vt in [b,h,hd,t]
__device__ __nv_bfloat16 g_fQh[ROWS*Dd];
__device__ __nv_bfloat16 g_fQl[ROWS*Dd];
__device__ __nv_bfloat16 g_fKh[ROWS*Dd];
__device__ __nv_bfloat16 g_fKl[ROWS*Dd];
__device__ __nv_bfloat16 g_fVh[ROWS*Dd];
__device__ __nv_bfloat16 g_fVl[ROWS*Dd];

// ================= helpers =================
__device__ __forceinline__ uint32_t smem_u32(const void* p) {
    uint32_t a;
    asm("{ .reg .u64 t; cvta.to.shared.u64 t, %1; cvt.u32.u64 %0, t; }"
        : "=r"(a) : "l"(p));
    return a;
}

#define SW128(o) ((o) ^ (((o) >> 3) & 0x70))

static constexpr uint64_t DESC_BASE_SW128 =
    (uint64_t(2)  << 61) | (uint64_t(1) << 46) | (uint64_t(64) << 32) | (uint64_t(1) << 16);

// idescs (kind::f16): dtype=F32(1<<4), atype/btype=BF16
#define MMA_IDESC_CG2 0x10400490u   /* M=256, N=256 */
#define MMA_IDESC_QK  0x08100490u   /* M=128, N=64  */
#define MMA_IDESC_PV  0x08200490u   /* M=128, N=128 */

// split one fp32 into bf16 hi/lo
__device__ __forceinline__ void split1(float v, __nv_bfloat16& h, __nv_bfloat16& l) {
    h = __float2bfloat16(v);
    l = __float2bfloat16(v - __bfloat162float(h));
}
// pack two fp32 into bf16x2 hi and lo words
__device__ __forceinline__ void split2(float a, float b, uint32_t& hw, uint32_t& lw) {
    __nv_bfloat162 h = __floats2bfloat162_rn(a, b);
    float la = a - __bfloat162float(__low2bfloat16(h));
    float lb = b - __bfloat162float(__high2bfloat16(h));
    __nv_bfloat162 l = __floats2bfloat162_rn(la, lb);
    hw = *reinterpret_cast<uint32_t*>(&h);
    lw = *reinterpret_cast<uint32_t*>(&l);
}

#if HAS_TCGEN05
__device__ __forceinline__ uint64_t mkdesc(uint32_t addr) {
    return DESC_BASE_SW128 | ((uint64_t)(addr >> 4) & 0x3FFF);
}
__device__ __forceinline__ void mma_bf16_ss_cg2(uint32_t d, uint64_t ad, uint64_t bd, uint32_t en) {
    asm volatile(
        "{\n\t.reg .pred p;\n\tsetp.ne.u32 p, %4, 0;\n\t"
        "tcgen05.mma.cta_group::2.kind::f16 [%0], %1, %2, %3, {%5,%5,%5,%5,%5,%5,%5,%5}, p;\n\t}"
        :: "r"(d), "l"(ad), "l"(bd), "r"(MMA_IDESC_CG2), "r"(en), "r"(0u) : "memory");
}
__device__ __forceinline__ void mma_ss_cg1(uint32_t d, uint64_t ad, uint64_t bd,
                                           uint32_t idesc, uint32_t en) {
    asm volatile(
        "{\n\t.reg .pred p;\n\tsetp.ne.u32 p, %4, 0;\n\t"
        "tcgen05.mma.cta_group::1.kind::f16 [%0], %1, %2, %3, {%5,%5,%5,%5}, p;\n\t}"
        :: "r"(d), "l"(ad), "l"(bd), "r"(idesc), "r"(en), "r"(0u) : "memory");
}
__device__ __forceinline__ void mbar_init(uint32_t m, uint32_t cnt) {
    asm volatile("mbarrier.init.shared.b64 [%0], %1;" :: "r"(m), "r"(cnt) : "memory");
}
__device__ __forceinline__ void mbar_wait(uint32_t m, uint32_t parity) {
    asm volatile(
        "{\n\t.reg .pred P1;\n"
        "W%=:\n\t"
        "mbarrier.try_wait.parity.acquire.cta.shared::cta.b64 P1, [%0], %1, 0x989680;\n\t"
        "@P1 bra.uni D%=;\n\t"
        "bra.uni W%=;\n"
        "D%=:\n\t}"
        :: "r"(m), "r"(parity) : "memory");
}
__device__ __forceinline__ void tc_commit_cg1(uint32_t m) {
    asm volatile("tcgen05.commit.cta_group::1.mbarrier::arrive::one.shared::cluster.b64 [%0];"
                 :: "r"(m) : "memory");
}
__device__ __forceinline__ void tc_commit_mc2(uint32_t m) {
    asm volatile(
        "tcgen05.commit.cta_group::2.mbarrier::arrive::one.shared::cluster.multicast::cluster.b64 [%0], %1;"
        :: "r"(m), "h"((uint16_t)0x3) : "memory");
}
__device__ __forceinline__ void mbar_arrive_rank0(uint32_t local_addr) {
    asm volatile(
        "{\n\t.reg .b32 ra;\n\t"
        "mapa.shared::cluster.u32 ra, %0, %1;\n\t"
        "mbarrier.arrive.shared::cluster.b64 _, [ra];\n\t}"
        :: "r"(local_addr), "r"(0) : "memory");
}
__device__ __forceinline__ void ldtm32(uint32_t* r, uint32_t a) {
    asm volatile(
        "tcgen05.ld.sync.aligned.32x32b.x32.b32 "
        "{%0,%1,%2,%3,%4,%5,%6,%7,%8,%9,%10,%11,%12,%13,%14,%15,"
        "%16,%17,%18,%19,%20,%21,%22,%23,%24,%25,%26,%27,%28,%29,%30,%31}, [%32];"
        : "=r"(r[0]),"=r"(r[1]),"=r"(r[2]),"=r"(r[3]),"=r"(r[4]),"=r"(r[5]),"=r"(r[6]),"=r"(r[7]),
          "=r"(r[8]),"=r"(r[9]),"=r"(r[10]),"=r"(r[11]),"=r"(r[12]),"=r"(r[13]),"=r"(r[14]),"=r"(r[15]),
          "=r"(r[16]),"=r"(r[17]),"=r"(r[18]),"=r"(r[19]),"=r"(r[20]),"=r"(r[21]),"=r"(r[22]),"=r"(r[23]),
          "=r"(r[24]),"=r"(r[25]),"=r"(r[26]),"=r"(r[27]),"=r"(r[28]),"=r"(r[29]),"=r"(r[30]),"=r"(r[31])
        : "r"(a));
}
__device__ __forceinline__ void sttm32(uint32_t a, const uint32_t* r) {
    asm volatile(
        "tcgen05.st.sync.aligned.32x32b.x32.b32 [%32], "
        "{%0,%1,%2,%3,%4,%5,%6,%7,%8,%9,%10,%11,%12,%13,%14,%15,"
        "%16,%17,%18,%19,%20,%21,%22,%23,%24,%25,%26,%27,%28,%29,%30,%31};"
        :: "r"(r[0]),"r"(r[1]),"r"(r[2]),"r"(r[3]),"r"(r[4]),"r"(r[5]),"r"(r[6]),"r"(r[7]),
           "r"(r[8]),"r"(r[9]),"r"(r[10]),"r"(r[11]),"r"(r[12]),"r"(r[13]),"r"(r[14]),"r"(r[15]),
           "r"(r[16]),"r"(r[17]),"r"(r[18]),"r"(r[19]),"r"(r[20]),"r"(r[21]),"r"(r[22]),"r"(r[23]),
           "r"(r[24]),"r"(r[25]),"r"(r[26]),"r"(r[27]),"r"(r[28]),"r"(r[29]),"r"(r[30]),"r"(r[31]),
           "r"(a)
        : "memory");
}
__device__ __forceinline__ void cpasync16(uint32_t dst, const void* src) {
    asm volatile("cp.async.cg.shared.global [%0], [%1], 16;" :: "r"(dst), "l"(src) : "memory");
}
__device__ __forceinline__ void cp_arrive(uint32_t m) {
    asm volatile("cp.async.mbarrier.arrive.noinc.shared.b64 [%0];" :: "r"(m) : "memory");
}
#define CP_COMMIT() asm volatile("cp.async.commit_group;" ::: "memory")
#define CP_WAIT0()  asm volatile("cp.async.wait_group 0;" ::: "memory")
#define TC_WAIT_LD() asm volatile("tcgen05.wait::ld.sync.aligned;" ::: "memory")
#define TC_WAIT_ST() asm volatile("tcgen05.wait::st.sync.aligned;" ::: "memory")
#define TC_FENCE_BEFORE() asm volatile("tcgen05.fence::before_thread_sync;" ::: "memory")
#define TC_FENCE_AFTER()  asm volatile("tcgen05.fence::after_thread_sync;" ::: "memory")
#define CLUSTER_SYNC() do { \
    asm volatile("barrier.cluster.arrive.aligned;" ::: "memory"); \
    asm volatile("barrier.cluster.wait.aligned;" ::: "memory"); \
} while (0)
#endif  // HAS_TCGEN05

// ---------------- split fp32 -> bf16 hi/lo (8 elems/thread, 16B ld/st) ----------------
__global__ void __launch_bounds__(256) split_kernel(const float* __restrict__ src,
                                                    __nv_bfloat16* __restrict__ hi,
                                                    __nv_bfloat16* __restrict__ lo,
                                                    int n8)
{
    int idx = blockIdx.x * blockDim.x + threadIdx.x;
    if (idx >= n8) return;
    float4 a = ((const float4*)src)[2 * idx];
    float4 b = ((const float4*)src)[2 * idx + 1];
    uint4 H, L;
    split2(a.x, a.y, H.x, L.x);
    split2(a.z, a.w, H.y, L.y);
    split2(b.x, b.y, H.z, L.z);
    split2(b.z, b.w, H.w, L.w);
    ((uint4*)hi)[idx] = H;
    ((uint4*)lo)[idx] = L;
}

// ---------------- LayerNorm emitting bf16 hi/lo directly ----------------
__global__ void __launch_bounds__(256) ln_split_kernel(const float* __restrict__ x,
                                                       const float* __restrict__ g,
                                                       const float* __restrict__ b,
                                                       __nv_bfloat16* __restrict__ hi,
                                                       __nv_bfloat16* __restrict__ lo)
{
    const int row = blockIdx.x;
    const int tid = threadIdx.x;
    const float* xr = x + (size_t)row * Dd;
    __shared__ float red[256];

    float s = 0.f;
    for (int i = tid; i < Dd; i += 256) s += xr[i];
    red[tid] = s; __syncthreads();
    for (int off = 128; off > 0; off >>= 1) {
        if (tid < off) red[tid] += red[tid + off];
        __syncthreads();
    }
    const float mean = red[0] * (1.f / Dd);
    __syncthreads();

    float v = 0.f;
    for (int i = tid; i < Dd; i += 256) { float d = xr[i] - mean; v += d * d; }
    red[tid] = v; __syncthreads();
    for (int off = 128; off > 0; off >>= 1) {
        if (tid < off) red[tid] += red[tid + off];
        __syncthreads();
    }
    const float rstd = rsqrtf(red[0] * (1.f / Dd) + 1e-5f);

    // 8 elems per thread, Dd/8 == 256
    const int i = tid * 8;
    float4 xa = *(const float4*)(xr + i);
    float4 xb = *(const float4*)(xr + i + 4);
    float4 ga = *(const float4*)(g + i);
    float4 gb = *(const float4*)(g + i + 4);
    float4 ba = *(const float4*)(b + i);
    float4 bb = *(const float4*)(b + i + 4);
    float v0 = (xa.x - mean) * rstd * ga.x + ba.x;
    float v1 = (xa.y - mean) * rstd * ga.y + ba.y;
    float v2 = (xa.z - mean) * rstd * ga.z + ba.z;
    float v3 = (xa.w - mean) * rstd * ga.w + ba.w;
    float v4 = (xb.x - mean) * rstd * gb.x + bb.x;
    float v5 = (xb.y - mean) * rstd * gb.y + bb.y;
    float v6 = (xb.z - mean) * rstd * gb.z + bb.z;
    float v7 = (xb.w - mean) * rstd * gb.w + bb.w;
    uint4 H, L;
    split2(v0, v1, H.x, L.x);
    split2(v2, v3, H.y, L.y);
    split2(v4, v5, H.z, L.z);
    split2(v6, v7, H.w, L.w);
    ((uint4*)(hi + (size_t)row * Dd))[tid] = H;
    ((uint4*)(lo + (size_t)row * Dd))[tid] = L;
}

// ---------------- V transpose+split: v[b,t,h*hd] -> Vt[b,h,hd,t] bf16 hi/lo ----------------
__global__ void __launch_bounds__(256) vtrans_kernel(const float* __restrict__ v,
                                                     __nv_bfloat16* __restrict__ Vth,
                                                     __nv_bfloat16* __restrict__ Vtl)
{
    __shared__ float tile[32][65];   // [hd][t], stride 65 -> conflict-free loads
    const int bh = blockIdx.z;
    const int b  = bh >> 4, h = bh & 15;
    const int t0 = blockIdx.x * 64;
    const int d0 = blockIdx.y * 32;
    const int x = threadIdx.x, y = threadIdx.y;  // (32,8)
#pragma unroll
    for (int i = 0; i < 8; i++) {
        const int tt = y + i * 8;                 // 0..63
        tile[x][tt] = v[(size_t)(b * Tt + t0 + tt) * Dd + h * HDd + d0 + x];
    }
    __syncthreads();
#pragma unroll
    for (int i = 0; i < 4; i++) {
        const int hdl = y + i * 8;                // 0..31
        const float v0 = tile[hdl][x * 2];
        const float v1 = tile[hdl][x * 2 + 1];
        uint32_t hw, lw;
        split2(v0, v1, hw, lw);
        const size_t idx = (size_t)(bh * HDd + d0 + hdl) * Tt + t0 + x * 2;
        *(uint32_t*)(Vth + idx) = hw;
        *(uint32_t*)(Vtl + idx) = lw;
    }
}

// ---------------- fused SiLU(gate)*up -> bf16 hi/lo (8 elems/thread) ----------------
__global__ void __launch_bounds__(256) silu_split_kernel(const float* __restrict__ gbuf,
                                                         const float* __restrict__ ubuf,
                                                         __nv_bfloat16* __restrict__ hi,
                                                         __nv_bfloat16* __restrict__ lo)
{
    const int idx = blockIdx.x * blockDim.x + threadIdx.x;  // over 8-elem groups
    float4 g0 = ((const float4*)gbuf)[2 * idx];
    float4 g1 = ((const float4*)gbuf)[2 * idx + 1];
    float4 u0 = ((const float4*)ubuf)[2 * idx];
    float4 u1 = ((const float4*)ubuf)[2 * idx + 1];
    float v0 = g0.x / (1.f + __expf(-g0.x)) * u0.x;
    float v1 = g0.y / (1.f + __expf(-g0.y)) * u0.y;
    float v2 = g0.z / (1.f + __expf(-g0.z)) * u0.z;
    float v3 = g0.w / (1.f + __expf(-g0.w)) * u0.w;
    float v4 = g1.x / (1.f + __expf(-g1.x)) * u1.x;
    float v5 = g1.y / (1.f + __expf(-g1.y)) * u1.y;
    float v6 = g1.z / (1.f + __expf(-g1.z)) * u1.z;
    float v7 = g1.w / (1.f + __expf(-g1.w)) * u1.w;
    uint4 H, L;
    split2(v0, v1, H.x, L.x);
    split2(v2, v3, H.y, L.y);
    split2(v4, v5, H.z, L.z);
    split2(v6, v7, H.w, L.w);
    ((uint4*)hi)[idx] = H;
    ((uint4*)lo)[idx] = L;
}

// ============ cg2 GEMM, warp-specialized; optional fused RoPE+split epilogue ============
// If rope != nullptr: instead of writing fp32 C, rotate adjacent column pairs with
// (fr[c], fr[c+1]) and write bf16 hi/lo to Chi/Clo. (Head-indexed freqs => index == col.)
#define NSTAGE 3
#define STAGE_BYTES 65536
#define GEMM_SMEM (1024 + NSTAGE * STAGE_BYTES)
#define GEMM_THREADS 288

__global__ void __launch_bounds__(GEMM_THREADS, 1) __cluster_dims__(2, 1, 1)
mma_gemm_kernel(const __nv_bfloat16* __restrict__ Ah, const __nv_bfloat16* __restrict__ Al,
                const __nv_bfloat16* __restrict__ Bh, const __nv_bfloat16* __restrict__ Bl,
                const float* __restrict__ bias, const float* __restrict__ resid,
                float* __restrict__ C,
                const float* __restrict__ rope,
                __nv_bfloat16* __restrict__ Chi, __nv_bfloat16* __restrict__ Clo,
                int M, int N, int K)
{
    extern __shared__ char smem[];
#if HAS_TCGEN05
    const uint32_t sbase = smem_u32(smem);
    const int tid  = threadIdx.x;
    const int wid  = tid >> 5;
    const int lane = tid & 31;
    const int rank = blockIdx.x & 1;
    const int bn   = (blockIdx.x >> 1) * 256;
    const int bm   = blockIdx.y * 256;

    const uint32_t tile_abs = (sbase + 128 + 1023) & ~1023u;
    const uint32_t mb_full  = sbase + 8;
    const uint32_t mb_f2    = sbase + 32;
    const uint32_t mb_empty = sbase + 56;

    if (wid == 0) {
        asm volatile("tcgen05.alloc.cta_group::2.sync.aligned.shared::cta.b32 [%0], %1;"
                     :: "r"(sbase), "r"(256u) : "memory");
        asm volatile("tcgen05.relinquish_alloc_permit.cta_group::2.sync.aligned;");
    }
    if (tid == 0) {
#pragma unroll
        for (int s = 0; s < NSTAGE; s++) {
            mbar_init(mb_full  + s * 8, 256);
            mbar_init(mb_f2    + s * 8, 2);
            mbar_init(mb_empty + s * 8, 1);
        }
    }
    __syncthreads();
    CLUSTER_SYNC();

    uint32_t tmem;
    asm volatile("ld.shared.b32 %0, [%1];" : "=r"(tmem) : "r"(sbase));

    const int n = K >> 6;

    if (tid < 256) {
        const int r  = tid >> 1;
        const int hh = tid & 1;
        const uint32_t off = r * 128 + hh * 64;
        const __nv_bfloat16* AgH = Ah + (size_t)(bm + rank * 128 + r) * K + hh * 32;
        const __nv_bfloat16* AgL = Al + (size_t)(bm + rank * 128 + r) * K + hh * 32;
        const __nv_bfloat16* BgH = Bh + (size_t)(bn + rank * 128 + r) * K + hh * 32;
        const __nv_bfloat16* BgL = Bl + (size_t)(bn + rank * 128 + r) * K + hh * 32;

        for (int c = 0; c < n; c++) {
            const int s = c % NSTAGE;
            const int use = c / NSTAGE;
            if (c >= NSTAGE) mbar_wait(mb_empty + s * 8, (use - 1) & 1);

            const uint32_t sb = tile_abs + s * STAGE_BYTES;
            const size_t kof = (size_t)c * 64;
#pragma unroll
            for (int j = 0; j < 4; j++) {
                const uint32_t o = SW128(off + j * 16);
                cpasync16(sb + o,         AgH + kof + j * 8);
                cpasync16(sb + 16384 + o, AgL + kof + j * 8);
                cpasync16(sb + 32768 + o, BgH + kof + j * 8);
                cpasync16(sb + 49152 + o, BgL + kof + j * 8);
            }
            cp_arrive(mb_full + s * 8);
        }
    } else if (tid == 256) {
        for (int i = 0; i < n; i++) {
            const int si = i % NSTAGE;
            mbar_wait(mb_full + si * 8, (i / NSTAGE) & 1);
            mbar_arrive_rank0(mb_f2 + si * 8);
            if (rank == 0) {
                mbar_wait(mb_f2 + si * 8, (i / NSTAGE) & 1);
                asm volatile("fence.proxy.async.shared::cta;" ::: "memory");
                const uint32_t sbi = tile_abs + si * STAGE_BYTES;
                const uint64_t ah = mkdesc(sbi);
                const uint64_t al = mkdesc(sbi + 16384);
                const uint64_t bh = mkdesc(sbi + 32768);
                const uint64_t bl = mkdesc(sbi + 49152);
#pragma unroll
                for (int k = 0; k < 4; k++)
                    mma_bf16_ss_cg2(tmem, ah + k * 2, bh + k * 2, (i > 0 || k > 0) ? 1u : 0u);
#pragma unroll
                for (int k = 0; k < 4; k++)
                    mma_bf16_ss_cg2(tmem, ah + k * 2, bl + k * 2, 1u);
#pragma unroll
                for (int k = 0; k < 4; k++)
                    mma_bf16_ss_cg2(tmem, al + k * 2, bh + k * 2, 1u);
                tc_commit_mc2(mb_empty + si * 8);
            }
        }
    }

    {
        const int i = n - 1, si = i % NSTAGE;
        mbar_wait(mb_empty + si * 8, (i / NSTAGE) & 1);
    }
    TC_FENCE_AFTER();

    if (wid < 8) {
        const int sub  = wid & 3;
        const int half = wid >> 2;
        const int row  = bm + rank * 128 + sub * 32 + lane;
        const float* rrow = resid ? resid + (size_t)row * N : nullptr;
        float* crow = C ? C + (size_t)row * N : nullptr;
#pragma unroll 1
        for (int half2 = 0; half2 < 2; half2++) {
#pragma unroll 1
            for (int c32 = 0; c32 < 2; c32++) {
                uint32_t d[32];
                ldtm32(d, tmem + half2 * 128 + half * 64 + c32 * 32);
                TC_WAIT_LD();
                const int col0 = bn + half2 * 128 + half * 64 + c32 * 32;
                if (rope) {
                    uint2* hrow = (uint2*)(Chi + (size_t)row * N + col0);
                    uint2* lrow = (uint2*)(Clo + (size_t)row * N + col0);
#pragma unroll
                    for (int t2 = 0; t2 < 8; t2++) {
                        const int c = col0 + t2 * 4;
                        const float a0 = __uint_as_float(d[t2 * 4 + 0]) + bias[c + 0];
                        const float b0 = __uint_as_float(d[t2 * 4 + 1]) + bias[c + 1];
                        const float a1 = __uint_as_float(d[t2 * 4 + 2]) + bias[c + 2];
                        const float b1 = __uint_as_float(d[t2 * 4 + 3]) + bias[c + 3];
                        const float cr0 = rope[c + 0], ci0 = rope[c + 1];
                        const float cr1 = rope[c + 2], ci1 = rope[c + 3];
                        uint2 hv, lv;
                        split2(a0 * cr0 - b0 * ci0, a0 * ci0 + b0 * cr0, hv.x, lv.x);
                        split2(a1 * cr1 - b1 * ci1, a1 * ci1 + b1 * cr1, hv.y, lv.y);
                        hrow[t2] = hv;
                        lrow[t2] = lv;
                    }
                } else if (rrow) {
#pragma unroll
                    for (int j = 0; j < 32; j++)
                        crow[col0 + j] = __uint_as_float(d[j]) + bias[col0 + j] + rrow[col0 + j];
                } else {
#pragma unroll
                    for (int j = 0; j < 32; j++)
                        crow[col0 + j] = __uint_as_float(d[j]) + bias[col0 + j];
                }
            }
        }
    }
    __syncthreads();
    if (wid == 0) {
        asm volatile("tcgen05.dealloc.cta_group::2.sync.aligned.b32 %0, %1;"
                     :: "r"(tmem), "r"(256u));
    }
    CLUSTER_SYNC();
#else
    float* As = (float*)smem;
    float* Bs = As + 8 * 128;
    const int tid = threadIdx.x;
    const int rank = blockIdx.x & 1;
    const int bm = blockIdx.y * 256 + rank * 128;
    const int bn0 = (blockIdx.x >> 1) * 256;
    const int lr  = tid >> 1;
    const int lcc = (tid & 1) * 4;
    const int tx = tid & 15, ty = tid >> 4;

    for (int h = 0; h < 2; h++) {
        const int bn = bn0 + h * 128;
        float acc[8][8];
#pragma unroll
        for (int i = 0; i < 8; i++)
#pragma unroll
            for (int j = 0; j < 8; j++) acc[i][j] = 0.f;

        for (int k0 = 0; k0 < K; k0 += 8) {
            if (tid < 256) {
                const __nv_bfloat16* aph = Ah + (size_t)(bm + lr) * K + k0 + lcc;
                const __nv_bfloat16* apl = Al + (size_t)(bm + lr) * K + k0 + lcc;
                const __nv_bfloat16* bph = Bh + (size_t)(bn + lr) * K + k0 + lcc;
                const __nv_bfloat16* bpl = Bl + (size_t)(bn + lr) * K + k0 + lcc;
#pragma unroll
                for (int j = 0; j < 4; j++) {
                    As[(lcc + j) * 128 + lr] = __bfloat162float(aph[j]) + __bfloat162float(apl[j]);
                    Bs[(lcc + j) * 128 + lr] = __bfloat162float(bph[j]) + __bfloat162float(bpl[j]);
                }
            }
            __syncthreads();
            if (tid < 256) {
#pragma unroll
                for (int kk = 0; kk < 8; kk++) {
                    float a[8], bb[8];
#pragma unroll
                    for (int i = 0; i < 8; i++)
                        a[i] = As[kk * 128 + ((i & 4) << 4) + ty * 4 + (i & 3)];
#pragma unroll
                    for (int j = 0; j < 8; j++)
                        bb[j] = Bs[kk * 128 + ((j & 4) << 4) + tx * 4 + (j & 3)];
#pragma unroll
                    for (int i = 0; i < 8; i++)
#pragma unroll
                        for (int j = 0; j < 8; j++)
                            acc[i][j] += a[i] * bb[j];
                }
            }
            __syncthreads();
        }

        if (tid < 256) {
#pragma unroll
            for (int i = 0; i < 8; i++) {
                const int row = bm + ((i & 4) << 4) + ty * 4 + (i & 3);
                if (rope) {
#pragma unroll
                    for (int j = 0; j < 8; j += 2) {
                        const int c = bn + ((j & 4) << 4) + tx * 4 + (j & 3);
                        float a0 = acc[i][j] + bias[c];
                        float b0 = acc[i][j + 1] + bias[c + 1];
                        float r0 = a0 * rope[c] - b0 * rope[c + 1];
                        float r1 = a0 * rope[c + 1] + b0 * rope[c];
                        __nv_bfloat16 hh, ll;
                        split1(r0, hh, ll);
                        Chi[(size_t)row * N + c] = hh; Clo[(size_t)row * N + c] = ll;
                        split1(r1, hh, ll);
                        Chi[(size_t)row * N + c + 1] = hh; Clo[(size_t)row * N + c + 1] = ll;
                    }
                } else {
#pragma unroll
                    for (int j = 0; j < 8; j++) {
                        const int col = bn + ((j & 4) << 4) + tx * 4 + (j & 3);
                        float vv = acc[i][j] + bias[col];
                        if (resid) vv += resid[(size_t)row * N + col];
                        C[(size_t)row * N + col] = vv;
                    }
                }
            }
        }
    }
#endif
}

// ============ tcgen05 flash attention; LPT order; epilogue writes bf16 hi/lo ============
#define FLASH_SMEM (1024 + 160 * 1024 + 1024)

__global__ void __launch_bounds__(256, 1) flash_mma_kernel(
    const __nv_bfloat16* __restrict__ Qh, const __nv_bfloat16* __restrict__ Ql,
    const __nv_bfloat16* __restrict__ Kh, const __nv_bfloat16* __restrict__ Kl,
    const __nv_bfloat16* __restrict__ Vh, const __nv_bfloat16* __restrict__ Vl,
    __nv_bfloat16* __restrict__ Ohi, __nv_bfloat16* __restrict__ Olo)
{
    extern __shared__ char smem[];
#if HAS_TCGEN05
    const uint32_t sbase = smem_u32(smem);
    const int tid  = threadIdx.x;
    const int wid  = tid >> 5;
    const int lane = tid & 31;
    const int qb = gridDim.x - 1 - blockIdx.x;    // heavy tiles first (LPT)
    const int h = blockIdx.y, b = blockIdx.z;
    const int q0 = qb * 128;

    const uint32_t mb_qk = sbase + 8;
    const uint32_t mb_pv = sbase + 16;
    int*   flags  = (int*)(smem + 24);
    float* redbuf = (float*)(smem + 64);
    const uint32_t tile_abs = (sbase + 576 + 1023) & ~1023u;
    const uint32_t tile_off = tile_abs - sbase;

    if (wid == 0) {
        asm volatile("tcgen05.alloc.cta_group::1.sync.aligned.shared::cta.b32 [%0], %1;"
                     :: "r"(sbase), "r"(256u) : "memory");
        asm volatile("tcgen05.relinquish_alloc_permit.cta_group::1.sync.aligned;");
    }
    if (tid == 0) { mbar_init(mb_qk, 1); mbar_init(mb_pv, 1); }
    __syncthreads();
    uint32_t tmem;
    asm volatile("ld.shared.b32 %0, [%1];" : "=r"(tmem) : "r"(sbase));
    const uint32_t tm_S = tmem;
    const uint32_t tm_O = tmem + 64;

#pragma unroll
    for (int i = 0; i < 2; i++) {
        int u = tid * 2 + i;
        int buf = u >> 8, rem = u & 255, half = rem >> 7, row = rem & 127;
        const __nv_bfloat16* src = (buf ? Ql : Qh)
            + (size_t)(b * Tt + q0 + row) * Dd + h * HDd + half * 64;
        uint32_t dst = tile_abs + buf * 32768 + half * 16384;
        uint32_t off = row * 128;
#pragma unroll
        for (int j = 0; j < 8; j++)
            cpasync16(dst + SW128(off + j * 16), src + j * 8);
    }
    CP_COMMIT();

    const int sw   = wid & 3;
    const int colh = wid >> 2;
    const int row  = sw * 32 + lane;
    const float scale = 0.088388347648318447f;

    float m = -1e30f, l = 0.f;
    const int nt = 2 * qb + 2;

    for (int t = 0; t < nt; t++) {
        const int j0 = t * 64;
        if (t > 0) mbar_wait(mb_pv, (t - 1) & 1);

#pragma unroll
        for (int i = 0; i < 2; i++) {
            int u = tid * 2 + i;
            const __nv_bfloat16* src;
            uint32_t dst, off;
            if (u < 256) {
                int kr = u & 63, half = (u >> 6) & 1, buf = u >> 7;
                src = (buf ? Kl : Kh) + (size_t)(b * Tt + j0 + kr) * Dd + h * HDd + half * 64;
                dst = tile_abs + 65536 + buf * 16384 + half * 8192;
                off = kr * 128;
            } else {
                int u2 = u - 256;
                int vr = u2 & 127, buf = u2 >> 7;
                src = (buf ? Vl : Vh) + (size_t)((b * Hh + h) * HDd + vr) * Tt + j0;
                dst = tile_abs + 98304 + buf * 16384;
                off = vr * 128;
            }
#pragma unroll
            for (int j = 0; j < 8; j++)
                cpasync16(dst + SW128(off + j * 16), src + j * 8);
        }
        CP_COMMIT();
        CP_WAIT0();
        __syncthreads();

        if (tid == 0) {
            asm volatile("fence.proxy.async.shared::cta;" ::: "memory");
            uint64_t qd[2][2], kd[2][2];
            qd[0][0] = mkdesc(tile_abs);          qd[0][1] = mkdesc(tile_abs + 16384);
            qd[1][0] = mkdesc(tile_abs + 32768);  qd[1][1] = mkdesc(tile_abs + 49152);
            kd[0][0] = mkdesc(tile_abs + 65536);  kd[0][1] = mkdesc(tile_abs + 73728);
            kd[1][0] = mkdesc(tile_abs + 81920);  kd[1][1] = mkdesc(tile_abs + 90112);
            int first = 1;
#pragma unroll
            for (int c3 = 0; c3 < 3; c3++) {
                const int ab = (c3 == 2) ? 1 : 0;
                const int bb = (c3 == 1) ? 1 : 0;
#pragma unroll
                for (int ks = 0; ks < 8; ks++) {
                    const int half = ks >> 2;
                    const uint64_t o = (uint64_t)((ks & 3) * 2);
                    mma_ss_cg1(tm_S, qd[ab][half] + o, kd[bb][half] + o,
                               MMA_IDESC_QK, first ? 0u : 1u);
                    first = 0;
                }
            }
            tc_commit_cg1(mb_qk);
        }
        mbar_wait(mb_qk, t & 1);
        TC_FENCE_AFTER();

        if (wid < 4) {
            uint32_t sr[64];
            ldtm32(sr,      tm_S);
            ldtm32(sr + 32, tm_S + 32);
            TC_WAIT_LD();
            float sv[64];
            float tmax = -1e30f;
#pragma unroll
            for (int c = 0; c < 64; c++) {
                float x = __uint_as_float(sr[c]) * scale;
                if (j0 + c > q0 + row) x = -1e30f;
                sv[c] = x;
                tmax = fmaxf(tmax, x);
            }
            const float mnew = fmaxf(m, tmax);
            const float alpha = __expf(m - mnew);
            m = mnew;
            float psum = 0.f;
#pragma unroll
            for (int c = 0; c < 64; c++) {
                float p = __expf(sv[c] - mnew);
                sv[c] = p;
                psum += p;
            }
            l = l * alpha + psum;
            const uint32_t prow = row * 128;
#pragma unroll
            for (int g = 0; g < 16; g++) {
                const int c = g * 4;
                uint2 hv, lv;
                split2(sv[c],     sv[c + 1], hv.x, lv.x);
                split2(sv[c + 2], sv[c + 3], hv.y, lv.y);
                const uint32_t o = SW128(prow + c * 2);
                *(uint2*)(smem + tile_off + 131072 + o) = hv;
                *(uint2*)(smem + tile_off + 147456 + o) = lv;
            }
            asm volatile("fence.proxy.async.shared::cta;" ::: "memory");
            redbuf[row] = alpha;
            unsigned bal = __ballot_sync(0xffffffffu, alpha < 0.999999f);
            if (lane == 0) flags[wid] = (bal != 0) ? 1 : 0;
        }
        __syncthreads();

        if (t > 0 && ((volatile int*)flags)[sw]) {
            const float av = ((volatile float*)redbuf)[row];
            uint32_t o0[32], o1[32];
            ldtm32(o0, tm_O + colh * 64);
            ldtm32(o1, tm_O + colh * 64 + 32);
            TC_WAIT_LD();
#pragma unroll
            for (int j = 0; j < 32; j++) {
                o0[j] = __float_as_uint(__uint_as_float(o0[j]) * av);
                o1[j] = __float_as_uint(__uint_as_float(o1[j]) * av);
            }
            sttm32(tm_O + colh * 64,      o0);
            sttm32(tm_O + colh * 64 + 32, o1);
            TC_WAIT_ST();
        }
        TC_FENCE_BEFORE();
        __syncthreads();

        if (tid == 0) {
            TC_FENCE_AFTER();
            asm volatile("fence.proxy.async.shared::cta;" ::: "memory");
            uint64_t pd[2], vd[2];
            pd[0] = mkdesc(tile_abs + 131072); pd[1] = mkdesc(tile_abs + 147456);
            vd[0] = mkdesc(tile_abs + 98304);  vd[1] = mkdesc(tile_abs + 114688);
            int first = (t == 0) ? 1 : 0;
#pragma unroll
            for (int c3 = 0; c3 < 3; c3++) {
                const int ab = (c3 == 1) ? 1 : 0;
                const int bb = (c3 == 2) ? 1 : 0;
#pragma unroll
                for (int ks = 0; ks < 4; ks++) {
                    const uint64_t o = (uint64_t)(ks * 2);
                    mma_ss_cg1(tm_O, pd[ab] + o, vd[bb] + o,
                               MMA_IDESC_PV, first ? 0u : 1u);
                    first = 0;
                }
            }
            tc_commit_cg1(mb_pv);
        }
    }

    mbar_wait(mb_pv, (nt - 1) & 1);
    TC_FENCE_AFTER();
    if (wid < 4) redbuf[row] = 1.f / l;
    __syncthreads();

    {
        const float linv = ((volatile float*)redbuf)[row];
        uint32_t o0[32], o1[32];
        ldtm32(o0, tm_O + colh * 64);
        ldtm32(o1, tm_O + colh * 64 + 32);
        TC_WAIT_LD();
        const size_t obase = (size_t)(b * Tt + q0 + row) * Dd + h * HDd + colh * 64;
        uint32_t* hrow = (uint32_t*)(Ohi + obase);
        uint32_t* lrow = (uint32_t*)(Olo + obase);
#pragma unroll
        for (int j = 0; j < 16; j++) {
            uint32_t hw, lw;
            split2(__uint_as_float(o0[2 * j]) * linv,
                   __uint_as_float(o0[2 * j + 1]) * linv, hw, lw);
            hrow[j] = hw; lrow[j] = lw;
        }
#pragma unroll
        for (int j = 0; j < 16; j++) {
            uint32_t hw, lw;
            split2(__uint_as_float(o1[2 * j]) * linv,
                   __uint_as_float(o1[2 * j + 1]) * linv, hw, lw);
            hrow[16 + j] = hw; lrow[16 + j] = lw;
        }
    }
    __syncthreads();
    if (wid == 0) {
        asm volatile("tcgen05.dealloc.cta_group::1.sync.aligned.b32 %0, %1;"
                     :: "r"(tmem), "r"(256u));
    }
#else
    const int tid = threadIdx.x;
    const int qb = gridDim.x - 1 - blockIdx.x;
    const int h = blockIdx.y, b = blockIdx.z;
    const int q0 = qb * 128;
    if (tid < 128) {
        const int rq = q0 + tid;
        float m = -1e30f, l = 0.f, o[128];
        for (int d = 0; d < 128; d++) o[d] = 0.f;
        for (int j = 0; j <= rq; j++) {
            float s = 0.f;
            const size_t qo = (size_t)(b * Tt + rq) * Dd + h * HDd;
            const size_t ko = (size_t)(b * Tt + j) * Dd + h * HDd;
            for (int d = 0; d < 128; d++) {
                float qv = __bfloat162float(Qh[qo + d]) + __bfloat162float(Ql[qo + d]);
                float kv = __bfloat162float(Kh[ko + d]) + __bfloat162float(Kl[ko + d]);
                s += qv * kv;
            }
            s *= 0.088388347648318447f;
            float mn = fmaxf(m, s);
            float al = __expf(m - mn), p = __expf(s - mn);
            m = mn;
            l = l * al + p;
            const size_t vo = (size_t)(b * Hh + h) * HDd;
            for (int d = 0; d < 128; d++) {
                float vv = __bfloat162float(Vh[(vo + d) * Tt + j]) +
                           __bfloat162float(Vl[(vo + d) * Tt + j]);
                o[d] = o[d] * al + p * vv;
            }
        }
        const size_t obase = (size_t)(b * Tt + rq) * Dd + h * HDd;
        for (int d = 0; d < 128; d++) {
            __nv_bfloat16 hi, lo;
            split1(o[d] / l, hi, lo);
            Ohi[obase + d] = hi;
            Olo[obase + d] = lo;
        }
    }
#endif
}

// ---------------- launch ----------------
extern "C" void kernel_launch(void* const* d_in, const int* in_sizes, int n_in,
                              void* d_out, int out_size)
{
    const float* x   = (const float*)d_in[0];
    const float* fr  = (const float*)d_in[1];
    const float* Wq  = (const float*)d_in[2];
    const float* bq  = (const float*)d_in[3];
    const float* Wk  = (const float*)d_in[4];
    const float* bk  = (const float*)d_in[5];
    const float* Wv  = (const float*)d_in[6];
    const float* bv  = (const float*)d_in[7];
    const float* Wo  = (const float*)d_in[8];
    const float* bo  = (const float*)d_in[9];
    const float* g1  = (const float*)d_in[10];
    const float* be1 = (const float*)d_in[11];
    const float* g2  = (const float*)d_in[12];
    const float* be2 = (const float*)d_in[13];
    const float* Wg  = (const float*)d_in[14];
    const float* bg  = (const float*)d_in[15];
    const float* Wu  = (const float*)d_in[16];
    const float* bu  = (const float*)d_in[17];
    const float* Wd  = (const float*)d_in[18];
    const float* bd  = (const float*)d_in[19];
    float* out = (float*)d_out;

    float *v, *ff1, *ff2;
    __nv_bfloat16 *Ahi, *Alo, *Bhi, *Blo, *fQh, *fQl, *fKh, *fKl, *fVh, *fVl;
    cudaGetSymbolAddress((void**)&v,    g_v);
    cudaGetSymbolAddress((void**)&ff1,  g_ff1);
    cudaGetSymbolAddress((void**)&ff2,  g_ff2);
    cudaGetSymbolAddress((void**)&Ahi,  g_Ahi);
    cudaGetSymbolAddress((void**)&Alo,  g_Alo);
    cudaGetSymbolAddress((void**)&Bhi,  g_Bhi);
    cudaGetSymbolAddress((void**)&Blo,  g_Blo);
    cudaGetSymbolAddress((void**)&fQh,  g_fQh);
    cudaGetSymbolAddress((void**)&fQl,  g_fQl);
    cudaGetSymbolAddress((void**)&fKh,  g_fKh);
    cudaGetSymbolAddress((void**)&fKl,  g_fKl);
    cudaGetSymbolAddress((void**)&fVh,  g_fVh);
    cudaGetSymbolAddress((void**)&fVl,  g_fVl);

    cudaFuncSetAttribute(mma_gemm_kernel, cudaFuncAttributeMaxDynamicSharedMemorySize, GEMM_SMEM);
    cudaFuncSetAttribute(flash_mma_kernel, cudaFuncAttributeMaxDynamicSharedMemorySize, FLASH_SMEM);

    const int DW  = Dd * Dd;     // 4M
    const int FW  = FFd * Dd;    // 16M
    const int DF  = ROWS * FFd;  // 32M

#define SPLIT(src, hi, lo, n) split_kernel<<<((n)/8 + 255)/256, 256>>>(src, hi, lo, (n)/8)

    // 1) LN1 -> bf16 hi/lo directly (A operand of QKV GEMMs)
    ln_split_kernel<<<ROWS, 256>>>(x, g1, be1, Ahi, Alo);

    // 2) Q,K,V projections. Q/K epilogues apply RoPE + split (write fQ/fK hi/lo).
    dim3 gD(2 * (Dd / 256), ROWS / 256);
    SPLIT(Wq, Bhi, Blo, DW);
    mma_gemm_kernel<<<gD, GEMM_THREADS, GEMM_SMEM>>>(
        Ahi, Alo, Bhi, Blo, bq, nullptr, nullptr, fr, fQh, fQl, ROWS, Dd, Dd);
    SPLIT(Wk, Bhi, Blo, DW);
    mma_gemm_kernel<<<gD, GEMM_THREADS, GEMM_SMEM>>>(
        Ahi, Alo, Bhi, Blo, bk, nullptr, nullptr, fr, fKh, fKl, ROWS, Dd, Dd);
    SPLIT(Wv, Bhi, Blo, DW);
    mma_gemm_kernel<<<gD, GEMM_THREADS, GEMM_SMEM>>>(
        Ahi, Alo, Bhi, Blo, bv, nullptr, v, nullptr, nullptr, nullptr, ROWS, Dd, Dd);

    // 3) V transpose+split
    vtrans_kernel<<<dim3(Tt / 64, HDd / 32, Bb * Hh), dim3(32, 8)>>>(v, fVh, fVl);

    // 4) causal flash attention (tcgen05), writing hi/lo directly (A of Wo)
    flash_mma_kernel<<<dim3(Tt / 128, Hh, Bb), 256, FLASH_SMEM>>>(
        fQh, fQl, fKh, fKl, fVh, fVl, Ahi, Alo);

    // 5) output projection + residual(x) -> out
    SPLIT(Wo, Bhi, Blo, DW);
    mma_gemm_kernel<<<gD, GEMM_THREADS, GEMM_SMEM>>>(
        Ahi, Alo, Bhi, Blo, bo, x, out, nullptr, nullptr, nullptr, ROWS, Dd, Dd);

    // 6) LN2 -> bf16 hi/lo directly
    ln_split_kernel<<<ROWS, 256>>>(out, g2, be2, Ahi, Alo);

    // 7) gate / up
    dim3 gF(2 * (FFd / 256), ROWS / 256);
    SPLIT(Wg, Bhi, Blo, FW);
    mma_gemm_kernel<<<gF, GEMM_THREADS, GEMM_SMEM>>>(
        Ahi, Alo, Bhi, Blo, bg, nullptr, ff1, nullptr, nullptr, nullptr, ROWS, FFd, Dd);
    SPLIT(Wu, Bhi, Blo, FW);
    mma_gemm_kernel<<<gF, GEMM_THREADS, GEMM_SMEM>>>(
        Ahi, Alo, Bhi, Blo, bu, nullptr, ff2, nullptr, nullptr, nullptr, ROWS, FFd, Dd);

    // 8) SiLU(gate)*up fused with split (A operand of down GEMM)
    silu_split_kernel<<<(DF / 8) / 256, 256>>>(ff1, ff2, Ahi, Alo);

    // 9) down projection + residual(out) -> out
    SPLIT(Wd, Bhi, Blo, FW);
    mma_gemm_kernel<<<gD, GEMM_THREADS, GEMM_SMEM>>>(
        Ahi, Alo, Bhi, Blo, bd, out, out, nullptr, nullptr, nullptr, ROWS, Dd, FFd);
}

// round 14
// speedup vs baseline: 6.9487x; 1.0223x over previous
#include <cuda_runtime.h>
#include <cuda_bf16.h>
#include <cstdint>
#include <math.h>

#define Bb 2
#define Tt 2048
#define Dd 2048
#define Hh 16
#define HDd 128
#define FFd 8192
#define ROWS (Bb*Tt)   /* 4096 */

// tcgen05 only exists in arch-specific (sm_10xa) compilation phases.
#if defined(__CUDA_ARCH_FEAT_SM103_ALL) || defined(__CUDA_ARCH_FEAT_SM100_ALL) || \
    defined(__CUDA_ARCH_FEAT_SM101_ALL) || \
    (defined(__CUDA_ARCH_SPECIFIC__) && (__CUDA_ARCH_SPECIFIC__ >= 1000)) || \
    (defined(__CUDA_ARCH_FAMILY_SPECIFIC__) && (__CUDA_ARCH_FAMILY_SPECIFIC__ >= 1000))
#define HAS_TCGEN05 1
#else
#define HAS_TCGEN05 0
#endif

// ---------------- scratch (no allocations allowed -> device globals) ----------------
__device__ float g_v   [ROWS*Dd];
__device__ float g_ff1 [ROWS*FFd];
// bf16 split buffers (GEMM A-side / weights)
__device__ __nv_bfloat16 g_Ahi[ROWS*FFd];
__device__ __nv_bfloat16 g_Alo[ROWS*FFd];
__device__ __nv_bfloat16 g_Bhi[FFd*Dd];
__device__ __nv_bfloat16 g_Blo[FFd*Dd];
// dedicated pair for the silu-fused up-GEMM output (down-GEMM's A operand)
__device__ __nv_bfloat16 g_Shi[ROWS*FFd];
__device__ __nv_bfloat16 g_Slo[ROWS*FFd];
// bf16 split buffers (flash): Q/K in [b,t,h*hd]; Vt in [b,h,hd,t]
__device__ __nv_bfloat16 g_fQh[ROWS*Dd];
__device__ __nv_bfloat16 g_fQl[ROWS*Dd];
__device__ __nv_bfloat16 g_fKh[ROWS*Dd];
__device__ __nv_bfloat16 g_fKl[ROWS*Dd];
__device__ __nv_bfloat16 g_fVh[ROWS*Dd];
__device__ __nv_bfloat16 g_fVl[ROWS*Dd];

// ================= helpers =================
__device__ __forceinline__ uint32_t smem_u32(const void* p) {
    uint32_t a;
    asm("{ .reg .u64 t; cvta.to.shared.u64 t, %1; cvt.u32.u64 %0, t; }"
        : "=r"(a) : "l"(p));
    return a;
}

#define SW128(o) ((o) ^ (((o) >> 3) & 0x70))

static constexpr uint64_t DESC_BASE_SW128 =
    (uint64_t(2)  << 61) | (uint64_t(1) << 46) | (uint64_t(64) << 32) | (uint64_t(1) << 16);

#define MMA_IDESC_CG2 0x10400490u   /* M=256, N=256 */
#define MMA_IDESC_QK  0x08100490u   /* M=128, N=64  */
#define MMA_IDESC_PV  0x08200490u   /* M=128, N=128 */

__device__ __forceinline__ void split1(float v, __nv_bfloat16& h, __nv_bfloat16& l) {
    h = __float2bfloat16(v);
    l = __float2bfloat16(v - __bfloat162float(h));
}
__device__ __forceinline__ void split2(float a, float b, uint32_t& hw, uint32_t& lw) {
    __nv_bfloat162 h = __floats2bfloat162_rn(a, b);
    float la = a - __bfloat162float(__low2bfloat16(h));
    float lb = b - __bfloat162float(__high2bfloat16(h));
    __nv_bfloat162 l = __floats2bfloat162_rn(la, lb);
    hw = *reinterpret_cast<uint32_t*>(&h);
    lw = *reinterpret_cast<uint32_t*>(&l);
}

#if HAS_TCGEN05
__device__ __forceinline__ uint64_t mkdesc(uint32_t addr) {
    return DESC_BASE_SW128 | ((uint64_t)(addr >> 4) & 0x3FFF);
}
__device__ __forceinline__ void mma_bf16_ss_cg2(uint32_t d, uint64_t ad, uint64_t bd, uint32_t en) {
    asm volatile(
        "{\n\t.reg .pred p;\n\tsetp.ne.u32 p, %4, 0;\n\t"
        "tcgen05.mma.cta_group::2.kind::f16 [%0], %1, %2, %3, {%5,%5,%5,%5,%5,%5,%5,%5}, p;\n\t}"
        :: "r"(d), "l"(ad), "l"(bd), "r"(MMA_IDESC_CG2), "r"(en), "r"(0u) : "memory");
}
__device__ __forceinline__ void mma_ss_cg1(uint32_t d, uint64_t ad, uint64_t bd,
                                           uint32_t idesc, uint32_t en) {
    asm volatile(
        "{\n\t.reg .pred p;\n\tsetp.ne.u32 p, %4, 0;\n\t"
        "tcgen05.mma.cta_group::1.kind::f16 [%0], %1, %2, %3, {%5,%5,%5,%5}, p;\n\t}"
        :: "r"(d), "l"(ad), "l"(bd), "r"(idesc), "r"(en), "r"(0u) : "memory");
}
__device__ __forceinline__ void mbar_init(uint32_t m, uint32_t cnt) {
    asm volatile("mbarrier.init.shared.b64 [%0], %1;" :: "r"(m), "r"(cnt) : "memory");
}
__device__ __forceinline__ void mbar_wait(uint32_t m, uint32_t parity) {
    asm volatile(
        "{\n\t.reg .pred P1;\n"
        "W%=:\n\t"
        "mbarrier.try_wait.parity.acquire.cta.shared::cta.b64 P1, [%0], %1, 0x989680;\n\t"
        "@P1 bra.uni D%=;\n\t"
        "bra.uni W%=;\n"
        "D%=:\n\t}"
        :: "r"(m), "r"(parity) : "memory");
}
__device__ __forceinline__ void tc_commit_cg1(uint32_t m) {
    asm volatile("tcgen05.commit.cta_group::1.mbarrier::arrive::one.shared::cluster.b64 [%0];"
                 :: "r"(m) : "memory");
}
__device__ __forceinline__ void tc_commit_mc2(uint32_t m) {
    asm volatile(
        "tcgen05.commit.cta_group::2.mbarrier::arrive::one.shared::cluster.multicast::cluster.b64 [%0], %1;"
        :: "r"(m), "h"((uint16_t)0x3) : "memory");
}
__device__ __forceinline__ void mbar_arrive_rank0(uint32_t local_addr) {
    asm volatile(
        "{\n\t.reg .b32 ra;\n\t"
        "mapa.shared::cluster.u32 ra, %0, %1;\n\t"
        "mbarrier.arrive.shared::cluster.b64 _, [ra];\n\t}"
        :: "r"(local_addr), "r"(0) : "memory");
}
__device__ __forceinline__ void ldtm32(uint32_t* r, uint32_t a) {
    asm volatile(
        "tcgen05.ld.sync.aligned.32x32b.x32.b32 "
        "{%0,%1,%2,%3,%4,%5,%6,%7,%8,%9,%10,%11,%12,%13,%14,%15,"
        "%16,%17,%18,%19,%20,%21,%22,%23,%24,%25,%26,%27,%28,%29,%30,%31}, [%32];"
        : "=r"(r[0]),"=r"(r[1]),"=r"(r[2]),"=r"(r[3]),"=r"(r[4]),"=r"(r[5]),"=r"(r[6]),"=r"(r[7]),
          "=r"(r[8]),"=r"(r[9]),"=r"(r[10]),"=r"(r[11]),"=r"(r[12]),"=r"(r[13]),"=r"(r[14]),"=r"(r[15]),
          "=r"(r[16]),"=r"(r[17]),"=r"(r[18]),"=r"(r[19]),"=r"(r[20]),"=r"(r[21]),"=r"(r[22]),"=r"(r[23]),
          "=r"(r[24]),"=r"(r[25]),"=r"(r[26]),"=r"(r[27]),"=r"(r[28]),"=r"(r[29]),"=r"(r[30]),"=r"(r[31])
        : "r"(a));
}
__device__ __forceinline__ void sttm32(uint32_t a, const uint32_t* r) {
    asm volatile(
        "tcgen05.st.sync.aligned.32x32b.x32.b32 [%32], "
        "{%0,%1,%2,%3,%4,%5,%6,%7,%8,%9,%10,%11,%12,%13,%14,%15,"
        "%16,%17,%18,%19,%20,%21,%22,%23,%24,%25,%26,%27,%28,%29,%30,%31};"
        :: "r"(r[0]),"r"(r[1]),"r"(r[2]),"r"(r[3]),"r"(r[4]),"r"(r[5]),"r"(r[6]),"r"(r[7]),
           "r"(r[8]),"r"(r[9]),"r"(r[10]),"r"(r[11]),"r"(r[12]),"r"(r[13]),"r"(r[14]),"r"(r[15]),
           "r"(r[16]),"r"(r[17]),"r"(r[18]),"r"(r[19]),"r"(r[20]),"r"(r[21]),"r"(r[22]),"r"(r[23]),
           "r"(r[24]),"r"(r[25]),"r"(r[26]),"r"(r[27]),"r"(r[28]),"r"(r[29]),"r"(r[30]),"r"(r[31]),
           "r"(a)
        : "memory");
}
__device__ __forceinline__ void cpasync16(uint32_t dst, const void* src) {
    asm volatile("cp.async.cg.shared.global [%0], [%1], 16;" :: "r"(dst), "l"(src) : "memory");
}
__device__ __forceinline__ void cp_arrive(uint32_t m) {
    asm volatile("cp.async.mbarrier.arrive.noinc.shared.b64 [%0];" :: "r"(m) : "memory");
}
#define CP_COMMIT() asm volatile("cp.async.commit_group;" ::: "memory")
#define CP_WAIT0()  asm volatile("cp.async.wait_group 0;" ::: "memory")
#define TC_WAIT_LD() asm volatile("tcgen05.wait::ld.sync.aligned;" ::: "memory")
#define TC_WAIT_ST() asm volatile("tcgen05.wait::st.sync.aligned;" ::: "memory")
#define TC_FENCE_BEFORE() asm volatile("tcgen05.fence::before_thread_sync;" ::: "memory")
#define TC_FENCE_AFTER()  asm volatile("tcgen05.fence::after_thread_sync;" ::: "memory")
#define CLUSTER_SYNC() do { \
    asm volatile("barrier.cluster.arrive.aligned;" ::: "memory"); \
    asm volatile("barrier.cluster.wait.aligned;" ::: "memory"); \
} while (0)
#endif  // HAS_TCGEN05

// ---------------- split fp32 -> bf16 hi/lo (8 elems/thread, 16B ld/st) ----------------
__global__ void __launch_bounds__(256) split_kernel(const float* __restrict__ src,
                                                    __nv_bfloat16* __restrict__ hi,
                                                    __nv_bfloat16* __restrict__ lo,
                                                    int n8)
{
    int idx = blockIdx.x * blockDim.x + threadIdx.x;
    if (idx >= n8) return;
    float4 a = ((const float4*)src)[2 * idx];
    float4 b = ((const float4*)src)[2 * idx + 1];
    uint4 H, L;
    split2(a.x, a.y, H.x, L.x);
    split2(a.z, a.w, H.y, L.y);
    split2(b.x, b.y, H.z, L.z);
    split2(b.z, b.w, H.w, L.w);
    ((uint4*)hi)[idx] = H;
    ((uint4*)lo)[idx] = L;
}

// ---------------- LayerNorm emitting bf16 hi/lo directly ----------------
__global__ void __launch_bounds__(256) ln_split_kernel(const float* __restrict__ x,
                                                       const float* __restrict__ g,
                                                       const float* __restrict__ b,
                                                       __nv_bfloat16* __restrict__ hi,
                                                       __nv_bfloat16* __restrict__ lo)
{
    const int row = blockIdx.x;
    const int tid = threadIdx.x;
    const float* xr = x + (size_t)row * Dd;
    __shared__ float red[256];

    float s = 0.f;
    for (int i = tid; i < Dd; i += 256) s += xr[i];
    red[tid] = s; __syncthreads();
    for (int off = 128; off > 0; off >>= 1) {
        if (tid < off) red[tid] += red[tid + off];
        __syncthreads();
    }
    const float mean = red[0] * (1.f / Dd);
    __syncthreads();

    float v = 0.f;
    for (int i = tid; i < Dd; i += 256) { float d = xr[i] - mean; v += d * d; }
    red[tid] = v; __syncthreads();
    for (int off = 128; off > 0; off >>= 1) {
        if (tid < off) red[tid] += red[tid + off];
        __syncthreads();
    }
    const float rstd = rsqrtf(red[0] * (1.f / Dd) + 1e-5f);

    const int i = tid * 8;
    float4 xa = *(const float4*)(xr + i);
    float4 xb = *(const float4*)(xr + i + 4);
    float4 ga = *(const float4*)(g + i);
    float4 gb = *(const float4*)(g + i + 4);
    float4 ba = *(const float4*)(b + i);
    float4 bb = *(const float4*)(b + i + 4);
    float v0 = (xa.x - mean) * rstd * ga.x + ba.x;
    float v1 = (xa.y - mean) * rstd * ga.y + ba.y;
    float v2 = (xa.z - mean) * rstd * ga.z + ba.z;
    float v3 = (xa.w - mean) * rstd * ga.w + ba.w;
    float v4 = (xb.x - mean) * rstd * gb.x + bb.x;
    float v5 = (xb.y - mean) * rstd * gb.y + bb.y;
    float v6 = (xb.z - mean) * rstd * gb.z + bb.z;
    float v7 = (xb.w - mean) * rstd * gb.w + bb.w;
    uint4 H, L;
    split2(v0, v1, H.x, L.x);
    split2(v2, v3, H.y, L.y);
    split2(v4, v5, H.z, L.z);
    split2(v6, v7, H.w, L.w);
    ((uint4*)(hi + (size_t)row * Dd))[tid] = H;
    ((uint4*)(lo + (size_t)row * Dd))[tid] = L;
}

// ---------------- V transpose+split ----------------
__global__ void __launch_bounds__(256) vtrans_kernel(const float* __restrict__ v,
                                                     __nv_bfloat16* __restrict__ Vth,
                                                     __nv_bfloat16* __restrict__ Vtl)
{
    __shared__ float tile[32][65];
    const int bh = blockIdx.z;
    const int b  = bh >> 4, h = bh & 15;
    const int t0 = blockIdx.x * 64;
    const int d0 = blockIdx.y * 32;
    const int x = threadIdx.x, y = threadIdx.y;  // (32,8)
#pragma unroll
    for (int i = 0; i < 8; i++) {
        const int tt = y + i * 8;
        tile[x][tt] = v[(size_t)(b * Tt + t0 + tt) * Dd + h * HDd + d0 + x];
    }
    __syncthreads();
#pragma unroll
    for (int i = 0; i < 4; i++) {
        const int hdl = y + i * 8;
        const float v0 = tile[hdl][x * 2];
        const float v1 = tile[hdl][x * 2 + 1];
        uint32_t hw, lw;
        split2(v0, v1, hw, lw);
        const size_t idx = (size_t)(bh * HDd + d0 + hdl) * Tt + t0 + x * 2;
        *(uint32_t*)(Vth + idx) = hw;
        *(uint32_t*)(Vtl + idx) = lw;
    }
}

// ============ cg2 GEMM, warp-specialized; epilogue modes: plain / rope+split / silu+split ============
#define NSTAGE 3
#define STAGE_BYTES 65536
#define GEMM_SMEM (1024 + NSTAGE * STAGE_BYTES)
#define GEMM_THREADS 288

__global__ void __launch_bounds__(GEMM_THREADS, 1) __cluster_dims__(2, 1, 1)
mma_gemm_kernel(const __nv_bfloat16* __restrict__ Ah, const __nv_bfloat16* __restrict__ Al,
                const __nv_bfloat16* __restrict__ Bh, const __nv_bfloat16* __restrict__ Bl,
                const float* __restrict__ bias, const float* __restrict__ resid,
                float* __restrict__ C,
                const float* __restrict__ rope,
                const float* __restrict__ gate,
                __nv_bfloat16* __restrict__ Chi, __nv_bfloat16* __restrict__ Clo,
                int M, int N, int K)
{
    extern __shared__ char smem[];
#if HAS_TCGEN05
    const uint32_t sbase = smem_u32(smem);
    const int tid  = threadIdx.x;
    const int wid  = tid >> 5;
    const int lane = tid & 31;
    const int rank = blockIdx.x & 1;
    const int bn   = (blockIdx.x >> 1) * 256;
    const int bm   = blockIdx.y * 256;

    const uint32_t tile_abs = (sbase + 128 + 1023) & ~1023u;
    const uint32_t mb_full  = sbase + 8;
    const uint32_t mb_f2    = sbase + 32;
    const uint32_t mb_empty = sbase + 56;

    if (wid == 0) {
        asm volatile("tcgen05.alloc.cta_group::2.sync.aligned.shared::cta.b32 [%0], %1;"
                     :: "r"(sbase), "r"(256u) : "memory");
        asm volatile("tcgen05.relinquish_alloc_permit.cta_group::2.sync.aligned;");
    }
    if (tid == 0) {
#pragma unroll
        for (int s = 0; s < NSTAGE; s++) {
            mbar_init(mb_full  + s * 8, 256);
            mbar_init(mb_f2    + s * 8, 2);
            mbar_init(mb_empty + s * 8, 1);
        }
    }
    __syncthreads();
    CLUSTER_SYNC();

    uint32_t tmem;
    asm volatile("ld.shared.b32 %0, [%1];" : "=r"(tmem) : "r"(sbase));

    const int n = K >> 6;

    if (tid < 256) {
        const int r  = tid >> 1;
        const int hh = tid & 1;
        const uint32_t off = r * 128 + hh * 64;
        const __nv_bfloat16* AgH = Ah + (size_t)(bm + rank * 128 + r) * K + hh * 32;
        const __nv_bfloat16* AgL = Al + (size_t)(bm + rank * 128 + r) * K + hh * 32;
        const __nv_bfloat16* BgH = Bh + (size_t)(bn + rank * 128 + r) * K + hh * 32;
        const __nv_bfloat16* BgL = Bl + (size_t)(bn + rank * 128 + r) * K + hh * 32;

        for (int c = 0; c < n; c++) {
            const int s = c % NSTAGE;
            const int use = c / NSTAGE;
            if (c >= NSTAGE) mbar_wait(mb_empty + s * 8, (use - 1) & 1);

            const uint32_t sb = tile_abs + s * STAGE_BYTES;
            const size_t kof = (size_t)c * 64;
#pragma unroll
            for (int j = 0; j < 4; j++) {
                const uint32_t o = SW128(off + j * 16);
                cpasync16(sb + o,         AgH + kof + j * 8);
                cpasync16(sb + 16384 + o, AgL + kof + j * 8);
                cpasync16(sb + 32768 + o, BgH + kof + j * 8);
                cpasync16(sb + 49152 + o, BgL + kof + j * 8);
            }
            cp_arrive(mb_full + s * 8);
        }
    } else if (tid == 256) {
        for (int i = 0; i < n; i++) {
            const int si = i % NSTAGE;
            mbar_wait(mb_full + si * 8, (i / NSTAGE) & 1);
            mbar_arrive_rank0(mb_f2 + si * 8);
            if (rank == 0) {
                mbar_wait(mb_f2 + si * 8, (i / NSTAGE) & 1);
                asm volatile("fence.proxy.async.shared::cta;" ::: "memory");
                const uint32_t sbi = tile_abs + si * STAGE_BYTES;
                const uint64_t ah = mkdesc(sbi);
                const uint64_t al = mkdesc(sbi + 16384);
                const uint64_t bh = mkdesc(sbi + 32768);
                const uint64_t bl = mkdesc(sbi + 49152);
#pragma unroll
                for (int k = 0; k < 4; k++)
                    mma_bf16_ss_cg2(tmem, ah + k * 2, bh + k * 2, (i > 0 || k > 0) ? 1u : 0u);
#pragma unroll
                for (int k = 0; k < 4; k++)
                    mma_bf16_ss_cg2(tmem, ah + k * 2, bl + k * 2, 1u);
#pragma unroll
                for (int k = 0; k < 4; k++)
                    mma_bf16_ss_cg2(tmem, al + k * 2, bh + k * 2, 1u);
                tc_commit_mc2(mb_empty + si * 8);
            }
        }
    }

    {
        const int i = n - 1, si = i % NSTAGE;
        mbar_wait(mb_empty + si * 8, (i / NSTAGE) & 1);
    }
    TC_FENCE_AFTER();

    if (wid < 8) {
        const int sub  = wid & 3;
        const int half = wid >> 2;
        const int row  = bm + rank * 128 + sub * 32 + lane;
        const float* rrow = resid ? resid + (size_t)row * N : nullptr;
        const float* grow = gate ? gate + (size_t)row * N : nullptr;
        float* crow = C ? C + (size_t)row * N : nullptr;
#pragma unroll 1
        for (int half2 = 0; half2 < 2; half2++) {
#pragma unroll 1
            for (int c32 = 0; c32 < 2; c32++) {
                uint32_t d[32];
                ldtm32(d, tmem + half2 * 128 + half * 64 + c32 * 32);
                TC_WAIT_LD();
                const int col0 = bn + half2 * 128 + half * 64 + c32 * 32;
                if (rope) {
                    uint2* hrow = (uint2*)(Chi + (size_t)row * N + col0);
                    uint2* lrow = (uint2*)(Clo + (size_t)row * N + col0);
#pragma unroll
                    for (int t2 = 0; t2 < 8; t2++) {
                        const int c = col0 + t2 * 4;
                        const float a0 = __uint_as_float(d[t2 * 4 + 0]) + bias[c + 0];
                        const float b0 = __uint_as_float(d[t2 * 4 + 1]) + bias[c + 1];
                        const float a1 = __uint_as_float(d[t2 * 4 + 2]) + bias[c + 2];
                        const float b1 = __uint_as_float(d[t2 * 4 + 3]) + bias[c + 3];
                        const float cr0 = rope[c + 0], ci0 = rope[c + 1];
                        const float cr1 = rope[c + 2], ci1 = rope[c + 3];
                        uint2 hv, lv;
                        split2(a0 * cr0 - b0 * ci0, a0 * ci0 + b0 * cr0, hv.x, lv.x);
                        split2(a1 * cr1 - b1 * ci1, a1 * ci1 + b1 * cr1, hv.y, lv.y);
                        hrow[t2] = hv;
                        lrow[t2] = lv;
                    }
                } else if (grow) {
                    uint2* hrow = (uint2*)(Chi + (size_t)row * N + col0);
                    uint2* lrow = (uint2*)(Clo + (size_t)row * N + col0);
#pragma unroll
                    for (int t2 = 0; t2 < 8; t2++) {
                        const int c = col0 + t2 * 4;
                        float4 gv = *(const float4*)(grow + c);
                        const float u0 = __uint_as_float(d[t2 * 4 + 0]) + bias[c + 0];
                        const float u1 = __uint_as_float(d[t2 * 4 + 1]) + bias[c + 1];
                        const float u2 = __uint_as_float(d[t2 * 4 + 2]) + bias[c + 2];
                        const float u3 = __uint_as_float(d[t2 * 4 + 3]) + bias[c + 3];
                        const float v0 = gv.x / (1.f + __expf(-gv.x)) * u0;
                        const float v1 = gv.y / (1.f + __expf(-gv.y)) * u1;
                        const float v2 = gv.z / (1.f + __expf(-gv.z)) * u2;
                        const float v3 = gv.w / (1.f + __expf(-gv.w)) * u3;
                        uint2 hv, lv;
                        split2(v0, v1, hv.x, lv.x);
                        split2(v2, v3, hv.y, lv.y);
                        hrow[t2] = hv;
                        lrow[t2] = lv;
                    }
                } else if (rrow) {
#pragma unroll
                    for (int j = 0; j < 32; j++)
                        crow[col0 + j] = __uint_as_float(d[j]) + bias[col0 + j] + rrow[col0 + j];
                } else {
#pragma unroll
                    for (int j = 0; j < 32; j++)
                        crow[col0 + j] = __uint_as_float(d[j]) + bias[col0 + j];
                }
            }
        }
    }
    __syncthreads();
    if (wid == 0) {
        asm volatile("tcgen05.dealloc.cta_group::2.sync.aligned.b32 %0, %1;"
                     :: "r"(tmem), "r"(256u));
    }
    CLUSTER_SYNC();
#else
    float* As = (float*)smem;
    float* Bs = As + 8 * 128;
    const int tid = threadIdx.x;
    const int rank = blockIdx.x & 1;
    const int bm = blockIdx.y * 256 + rank * 128;
    const int bn0 = (blockIdx.x >> 1) * 256;
    const int lr  = tid >> 1;
    const int lcc = (tid & 1) * 4;
    const int tx = tid & 15, ty = tid >> 4;

    for (int h = 0; h < 2; h++) {
        const int bn = bn0 + h * 128;
        float acc[8][8];
#pragma unroll
        for (int i = 0; i < 8; i++)
#pragma unroll
            for (int j = 0; j < 8; j++) acc[i][j] = 0.f;

        for (int k0 = 0; k0 < K; k0 += 8) {
            if (tid < 256) {
                const __nv_bfloat16* aph = Ah + (size_t)(bm + lr) * K + k0 + lcc;
                const __nv_bfloat16* apl = Al + (size_t)(bm + lr) * K + k0 + lcc;
                const __nv_bfloat16* bph = Bh + (size_t)(bn + lr) * K + k0 + lcc;
                const __nv_bfloat16* bpl = Bl + (size_t)(bn + lr) * K + k0 + lcc;
#pragma unroll
                for (int j = 0; j < 4; j++) {
                    As[(lcc + j) * 128 + lr] = __bfloat162float(aph[j]) + __bfloat162float(apl[j]);
                    Bs[(lcc + j) * 128 + lr] = __bfloat162float(bph[j]) + __bfloat162float(bpl[j]);
                }
            }
            __syncthreads();
            if (tid < 256) {
#pragma unroll
                for (int kk = 0; kk < 8; kk++) {
                    float a[8], bb[8];
#pragma unroll
                    for (int i = 0; i < 8; i++)
                        a[i] = As[kk * 128 + ((i & 4) << 4) + ty * 4 + (i & 3)];
#pragma unroll
                    for (int j = 0; j < 8; j++)
                        bb[j] = Bs[kk * 128 + ((j & 4) << 4) + tx * 4 + (j & 3)];
#pragma unroll
                    for (int i = 0; i < 8; i++)
#pragma unroll
                        for (int j = 0; j < 8; j++)
                            acc[i][j] += a[i] * bb[j];
                }
            }
            __syncthreads();
        }

        if (tid < 256) {
#pragma unroll
            for (int i = 0; i < 8; i++) {
                const int row = bm + ((i & 4) << 4) + ty * 4 + (i & 3);
                if (rope) {
#pragma unroll
                    for (int j = 0; j < 8; j += 2) {
                        const int c = bn + ((j & 4) << 4) + tx * 4 + (j & 3);
                        float a0 = acc[i][j] + bias[c];
                        float b0 = acc[i][j + 1] + bias[c + 1];
                        float r0 = a0 * rope[c] - b0 * rope[c + 1];
                        float r1 = a0 * rope[c + 1] + b0 * rope[c];
                        __nv_bfloat16 hh, ll;
                        split1(r0, hh, ll);
                        Chi[(size_t)row * N + c] = hh; Clo[(size_t)row * N + c] = ll;
                        split1(r1, hh, ll);
                        Chi[(size_t)row * N + c + 1] = hh; Clo[(size_t)row * N + c + 1] = ll;
                    }
                } else if (gate) {
#pragma unroll
                    for (int j = 0; j < 8; j++) {
                        const int c = bn + ((j & 4) << 4) + tx * 4 + (j & 3);
                        float gvv = gate[(size_t)row * N + c];
                        float u = acc[i][j] + bias[c];
                        float vv = gvv / (1.f + __expf(-gvv)) * u;
                        __nv_bfloat16 hh, ll;
                        split1(vv, hh, ll);
                        Chi[(size_t)row * N + c] = hh; Clo[(size_t)row * N + c] = ll;
                    }
                } else {
#pragma unroll
                    for (int j = 0; j < 8; j++) {
                        const int col = bn + ((j & 4) << 4) + tx * 4 + (j & 3);
                        float vv = acc[i][j] + bias[col];
                        if (resid) vv += resid[(size_t)row * N + col];
                        C[(size_t)row * N + col] = vv;
                    }
                }
            }
        }
    }
#endif
}

// ============ tcgen05 flash attention (unchanged from R13, passing) ============
#define FLASH_SMEM (1024 + 160 * 1024 + 1024)

__global__ void __launch_bounds__(256, 1) flash_mma_kernel(
    const __nv_bfloat16* __restrict__ Qh, const __nv_bfloat16* __restrict__ Ql,
    const __nv_bfloat16* __restrict__ Kh, const __nv_bfloat16* __restrict__ Kl,
    const __nv_bfloat16* __restrict__ Vh, const __nv_bfloat16* __restrict__ Vl,
    __nv_bfloat16* __restrict__ Ohi, __nv_bfloat16* __restrict__ Olo)
{
    extern __shared__ char smem[];
#if HAS_TCGEN05
    const uint32_t sbase = smem_u32(smem);
    const int tid  = threadIdx.x;
    const int wid  = tid >> 5;
    const int lane = tid & 31;
    const int qb = gridDim.x - 1 - blockIdx.x;
    const int h = blockIdx.y, b = blockIdx.z;
    const int q0 = qb * 128;

    const uint32_t mb_qk = sbase + 8;
    const uint32_t mb_pv = sbase + 16;
    int*   flags  = (int*)(smem + 24);
    float* redbuf = (float*)(smem + 64);
    const uint32_t tile_abs = (sbase + 576 + 1023) & ~1023u;
    const uint32_t tile_off = tile_abs - sbase;

    if (wid == 0) {
        asm volatile("tcgen05.alloc.cta_group::1.sync.aligned.shared::cta.b32 [%0], %1;"
                     :: "r"(sbase), "r"(256u) : "memory");
        asm volatile("tcgen05.relinquish_alloc_permit.cta_group::1.sync.aligned;");
    }
    if (tid == 0) { mbar_init(mb_qk, 1); mbar_init(mb_pv, 1); }
    __syncthreads();
    uint32_t tmem;
    asm volatile("ld.shared.b32 %0, [%1];" : "=r"(tmem) : "r"(sbase));
    const uint32_t tm_S = tmem;
    const uint32_t tm_O = tmem + 64;

#pragma unroll
    for (int i = 0; i < 2; i++) {
        int u = tid * 2 + i;
        int buf = u >> 8, rem = u & 255, half = rem >> 7, row = rem & 127;
        const __nv_bfloat16* src = (buf ? Ql : Qh)
            + (size_t)(b * Tt + q0 + row) * Dd + h * HDd + half * 64;
        uint32_t dst = tile_abs + buf * 32768 + half * 16384;
        uint32_t off = row * 128;
#pragma unroll
        for (int j = 0; j < 8; j++)
            cpasync16(dst + SW128(off + j * 16), src + j * 8);
    }
    CP_COMMIT();

    const int sw   = wid & 3;
    const int colh = wid >> 2;
    const int row  = sw * 32 + lane;
    const float scale = 0.088388347648318447f;

    float m = -1e30f, l = 0.f;
    const int nt = 2 * qb + 2;

    for (int t = 0; t < nt; t++) {
        const int j0 = t * 64;
        if (t > 0) mbar_wait(mb_pv, (t - 1) & 1);

#pragma unroll
        for (int i = 0; i < 2; i++) {
            int u = tid * 2 + i;
            const __nv_bfloat16* src;
            uint32_t dst, off;
            if (u < 256) {
                int kr = u & 63, half = (u >> 6) & 1, buf = u >> 7;
                src = (buf ? Kl : Kh) + (size_t)(b * Tt + j0 + kr) * Dd + h * HDd + half * 64;
                dst = tile_abs + 65536 + buf * 16384 + half * 8192;
                off = kr * 128;
            } else {
                int u2 = u - 256;
                int vr = u2 & 127, buf = u2 >> 7;
                src = (buf ? Vl : Vh) + (size_t)((b * Hh + h) * HDd + vr) * Tt + j0;
                dst = tile_abs + 98304 + buf * 16384;
                off = vr * 128;
            }
#pragma unroll
            for (int j = 0; j < 8; j++)
                cpasync16(dst + SW128(off + j * 16), src + j * 8);
        }
        CP_COMMIT();
        CP_WAIT0();
        __syncthreads();

        if (tid == 0) {
            asm volatile("fence.proxy.async.shared::cta;" ::: "memory");
            uint64_t qd[2][2], kd[2][2];
            qd[0][0] = mkdesc(tile_abs);          qd[0][1] = mkdesc(tile_abs + 16384);
            qd[1][0] = mkdesc(tile_abs + 32768);  qd[1][1] = mkdesc(tile_abs + 49152);
            kd[0][0] = mkdesc(tile_abs + 65536);  kd[0][1] = mkdesc(tile_abs + 73728);
            kd[1][0] = mkdesc(tile_abs + 81920);  kd[1][1] = mkdesc(tile_abs + 90112);
            int first = 1;
#pragma unroll
            for (int c3 = 0; c3 < 3; c3++) {
                const int ab = (c3 == 2) ? 1 : 0;
                const int bb = (c3 == 1) ? 1 : 0;
#pragma unroll
                for (int ks = 0; ks < 8; ks++) {
                    const int half = ks >> 2;
                    const uint64_t o = (uint64_t)((ks & 3) * 2);
                    mma_ss_cg1(tm_S, qd[ab][half] + o, kd[bb][half] + o,
                               MMA_IDESC_QK, first ? 0u : 1u);
                    first = 0;
                }
            }
            tc_commit_cg1(mb_qk);
        }
        mbar_wait(mb_qk, t & 1);
        TC_FENCE_AFTER();

        if (wid < 4) {
            uint32_t sr[64];
            ldtm32(sr,      tm_S);
            ldtm32(sr + 32, tm_S + 32);
            TC_WAIT_LD();
            float sv[64];
            float tmax = -1e30f;
#pragma unroll
            for (int c = 0; c < 64; c++) {
                float x = __uint_as_float(sr[c]) * scale;
                if (j0 + c > q0 + row) x = -1e30f;
                sv[c] = x;
                tmax = fmaxf(tmax, x);
            }
            const float mnew = fmaxf(m, tmax);
            const float alpha = __expf(m - mnew);
            m = mnew;
            float psum = 0.f;
#pragma unroll
            for (int c = 0; c < 64; c++) {
                float p = __expf(sv[c] - mnew);
                sv[c] = p;
                psum += p;
            }
            l = l * alpha + psum;
            const uint32_t prow = row * 128;
#pragma unroll
            for (int g = 0; g < 16; g++) {
                const int c = g * 4;
                uint2 hv, lv;
                split2(sv[c],     sv[c + 1], hv.x, lv.x);
                split2(sv[c + 2], sv[c + 3], hv.y, lv.y);
                const uint32_t o = SW128(prow + c * 2);
                *(uint2*)(smem + tile_off + 131072 + o) = hv;
                *(uint2*)(smem + tile_off + 147456 + o) = lv;
            }
            asm volatile("fence.proxy.async.shared::cta;" ::: "memory");
            redbuf[row] = alpha;
            unsigned bal = __ballot_sync(0xffffffffu, alpha < 0.999999f);
            if (lane == 0) flags[wid] = (bal != 0) ? 1 : 0;
        }
        __syncthreads();

        if (t > 0 && ((volatile int*)flags)[sw]) {
            const float av = ((volatile float*)redbuf)[row];
            uint32_t o0[32], o1[32];
            ldtm32(o0, tm_O + colh * 64);
            ldtm32(o1, tm_O + colh * 64 + 32);
            TC_WAIT_LD();
#pragma unroll
            for (int j = 0; j < 32; j++) {
                o0[j] = __float_as_uint(__uint_as_float(o0[j]) * av);
                o1[j] = __float_as_uint(__uint_as_float(o1[j]) * av);
            }
            sttm32(tm_O + colh * 64,      o0);
            sttm32(tm_O + colh * 64 + 32, o1);
            TC_WAIT_ST();
        }
        TC_FENCE_BEFORE();
        __syncthreads();

        if (tid == 0) {
            TC_FENCE_AFTER();
            asm volatile("fence.proxy.async.shared::cta;" ::: "memory");
            uint64_t pd[2], vd[2];
            pd[0] = mkdesc(tile_abs + 131072); pd[1] = mkdesc(tile_abs + 147456);
            vd[0] = mkdesc(tile_abs + 98304);  vd[1] = mkdesc(tile_abs + 114688);
            int first = (t == 0) ? 1 : 0;
#pragma unroll
            for (int c3 = 0; c3 < 3; c3++) {
                const int ab = (c3 == 1) ? 1 : 0;
                const int bb = (c3 == 2) ? 1 : 0;
#pragma unroll
                for (int ks = 0; ks < 4; ks++) {
                    const uint64_t o = (uint64_t)(ks * 2);
                    mma_ss_cg1(tm_O, pd[ab] + o, vd[bb] + o,
                               MMA_IDESC_PV, first ? 0u : 1u);
                    first = 0;
                }
            }
            tc_commit_cg1(mb_pv);
        }
    }

    mbar_wait(mb_pv, (nt - 1) & 1);
    TC_FENCE_AFTER();
    if (wid < 4) redbuf[row] = 1.f / l;
    __syncthreads();

    {
        const float linv = ((volatile float*)redbuf)[row];
        uint32_t o0[32], o1[32];
        ldtm32(o0, tm_O + colh * 64);
        ldtm32(o1, tm_O + colh * 64 + 32);
        TC_WAIT_LD();
        const size_t obase = (size_t)(b * Tt + q0 + row) * Dd + h * HDd + colh * 64;
        uint32_t* hrow = (uint32_t*)(Ohi + obase);
        uint32_t* lrow = (uint32_t*)(Olo + obase);
#pragma unroll
        for (int j = 0; j < 16; j++) {
            uint32_t hw, lw;
            split2(__uint_as_float(o0[2 * j]) * linv,
                   __uint_as_float(o0[2 * j + 1]) * linv, hw, lw);
            hrow[j] = hw; lrow[j] = lw;
        }
#pragma unroll
        for (int j = 0; j < 16; j++) {
            uint32_t hw, lw;
            split2(__uint_as_float(o1[2 * j]) * linv,
                   __uint_as_float(o1[2 * j + 1]) * linv, hw, lw);
            hrow[16 + j] = hw; lrow[16 + j] = lw;
        }
    }
    __syncthreads();
    if (wid == 0) {
        asm volatile("tcgen05.dealloc.cta_group::1.sync.aligned.b32 %0, %1;"
                     :: "r"(tmem), "r"(256u));
    }
#else
    const int tid = threadIdx.x;
    const int qb = gridDim.x - 1 - blockIdx.x;
    const int h = blockIdx.y, b = blockIdx.z;
    const int q0 = qb * 128;
    if (tid < 128) {
        const int rq = q0 + tid;
        float m = -1e30f, l = 0.f, o[128];
        for (int d = 0; d < 128; d++) o[d] = 0.f;
        for (int j = 0; j <= rq; j++) {
            float s = 0.f;
            const size_t qo = (size_t)(b * Tt + rq) * Dd + h * HDd;
            const size_t ko = (size_t)(b * Tt + j) * Dd + h * HDd;
            for (int d = 0; d < 128; d++) {
                float qv = __bfloat162float(Qh[qo + d]) + __bfloat162float(Ql[qo + d]);
                float kv = __bfloat162float(Kh[ko + d]) + __bfloat162float(Kl[ko + d]);
                s += qv * kv;
            }
            s *= 0.088388347648318447f;
            float mn = fmaxf(m, s);
            float al = __expf(m - mn), p = __expf(s - mn);
            m = mn;
            l = l * al + p;
            const size_t vo = (size_t)(b * Hh + h) * HDd;
            for (int d = 0; d < 128; d++) {
                float vv = __bfloat162float(Vh[(vo + d) * Tt + j]) +
                           __bfloat162float(Vl[(vo + d) * Tt + j]);
                o[d] = o[d] * al + p * vv;
            }
        }
        const size_t obase = (size_t)(b * Tt + rq) * Dd + h * HDd;
        for (int d = 0; d < 128; d++) {
            __nv_bfloat16 hi, lo;
            split1(o[d] / l, hi, lo);
            Ohi[obase + d] = hi;
            Olo[obase + d] = lo;
        }
    }
#endif
}

// ---------------- launch ----------------
extern "C" void kernel_launch(void* const* d_in, const int* in_sizes, int n_in,
                              void* d_out, int out_size)
{
    const float* x   = (const float*)d_in[0];
    const float* fr  = (const float*)d_in[1];
    const float* Wq  = (const float*)d_in[2];
    const float* bq  = (const float*)d_in[3];
    const float* Wk  = (const float*)d_in[4];
    const float* bk  = (const float*)d_in[5];
    const float* Wv  = (const float*)d_in[6];
    const float* bv  = (const float*)d_in[7];
    const float* Wo  = (const float*)d_in[8];
    const float* bo  = (const float*)d_in[9];
    const float* g1  = (const float*)d_in[10];
    const float* be1 = (const float*)d_in[11];
    const float* g2  = (const float*)d_in[12];
    const float* be2 = (const float*)d_in[13];
    const float* Wg  = (const float*)d_in[14];
    const float* bg  = (const float*)d_in[15];
    const float* Wu  = (const float*)d_in[16];
    const float* bu  = (const float*)d_in[17];
    const float* Wd  = (const float*)d_in[18];
    const float* bd  = (const float*)d_in[19];
    float* out = (float*)d_out;

    float *v, *ff1;
    __nv_bfloat16 *Ahi, *Alo, *Bhi, *Blo, *Shi, *Slo, *fQh, *fQl, *fKh, *fKl, *fVh, *fVl;
    cudaGetSymbolAddress((void**)&v,    g_v);
    cudaGetSymbolAddress((void**)&ff1,  g_ff1);
    cudaGetSymbolAddress((void**)&Ahi,  g_Ahi);
    cudaGetSymbolAddress((void**)&Alo,  g_Alo);
    cudaGetSymbolAddress((void**)&Bhi,  g_Bhi);
    cudaGetSymbolAddress((void**)&Blo,  g_Blo);
    cudaGetSymbolAddress((void**)&Shi,  g_Shi);
    cudaGetSymbolAddress((void**)&Slo,  g_Slo);
    cudaGetSymbolAddress((void**)&fQh,  g_fQh);
    cudaGetSymbolAddress((void**)&fQl,  g_fQl);
    cudaGetSymbolAddress((void**)&fKh,  g_fKh);
    cudaGetSymbolAddress((void**)&fKl,  g_fKl);
    cudaGetSymbolAddress((void**)&fVh,  g_fVh);
    cudaGetSymbolAddress((void**)&fVl,  g_fVl);

    cudaFuncSetAttribute(mma_gemm_kernel, cudaFuncAttributeMaxDynamicSharedMemorySize, GEMM_SMEM);
    cudaFuncSetAttribute(flash_mma_kernel, cudaFuncAttributeMaxDynamicSharedMemorySize, FLASH_SMEM);

    const int DW  = Dd * Dd;     // 4M
    const int FW  = FFd * Dd;    // 16M

#define SPLIT(src, hi, lo, n) split_kernel<<<((n)/8 + 255)/256, 256>>>(src, hi, lo, (n)/8)

    // 1) LN1 -> bf16 hi/lo directly
    ln_split_kernel<<<ROWS, 256>>>(x, g1, be1, Ahi, Alo);

    // 2) Q,K,V projections. Q/K epilogues apply RoPE + split.
    dim3 gD(2 * (Dd / 256), ROWS / 256);
    SPLIT(Wq, Bhi, Blo, DW);
    mma_gemm_kernel<<<gD, GEMM_THREADS, GEMM_SMEM>>>(
        Ahi, Alo, Bhi, Blo, bq, nullptr, nullptr, fr, nullptr, fQh, fQl, ROWS, Dd, Dd);
    SPLIT(Wk, Bhi, Blo, DW);
    mma_gemm_kernel<<<gD, GEMM_THREADS, GEMM_SMEM>>>(
        Ahi, Alo, Bhi, Blo, bk, nullptr, nullptr, fr, nullptr, fKh, fKl, ROWS, Dd, Dd);
    SPLIT(Wv, Bhi, Blo, DW);
    mma_gemm_kernel<<<gD, GEMM_THREADS, GEMM_SMEM>>>(
        Ahi, Alo, Bhi, Blo, bv, nullptr, v, nullptr, nullptr, nullptr, nullptr, ROWS, Dd, Dd);

    // 3) V transpose+split
    vtrans_kernel<<<dim3(Tt / 64, HDd / 32, Bb * Hh), dim3(32, 8)>>>(v, fVh, fVl);

    // 4) causal flash attention (tcgen05), writing hi/lo directly
    flash_mma_kernel<<<dim3(Tt / 128, Hh, Bb), 256, FLASH_SMEM>>>(
        fQh, fQl, fKh, fKl, fVh, fVl, Ahi, Alo);

    // 5) output projection + residual(x) -> out
    SPLIT(Wo, Bhi, Blo, DW);
    mma_gemm_kernel<<<gD, GEMM_THREADS, GEMM_SMEM>>>(
        Ahi, Alo, Bhi, Blo, bo, x, out, nullptr, nullptr, nullptr, nullptr, ROWS, Dd, Dd);

    // 6) LN2 -> bf16 hi/lo directly
    ln_split_kernel<<<ROWS, 256>>>(out, g2, be2, Ahi, Alo);

    // 7) gate (fp32 ff1), then up-GEMM with fused silu(gate)*u -> Shi/Slo
    dim3 gF(2 * (FFd / 256), ROWS / 256);
    SPLIT(Wg, Bhi, Blo, FW);
    mma_gemm_kernel<<<gF, GEMM_THREADS, GEMM_SMEM>>>(
        Ahi, Alo, Bhi, Blo, bg, nullptr, ff1, nullptr, nullptr, nullptr, nullptr, ROWS, FFd, Dd);
    SPLIT(Wu, Bhi, Blo, FW);
    mma_gemm_kernel<<<gF, GEMM_THREADS, GEMM_SMEM>>>(
        Ahi, Alo, Bhi, Blo, bu, nullptr, nullptr, nullptr, ff1, Shi, Slo, ROWS, FFd, Dd);

    // 9) down projection + residual(out) -> out
    SPLIT(Wd, Bhi, Blo, FW);
    mma_gemm_kernel<<<gD, GEMM_THREADS, GEMM_SMEM>>>(
        Shi, Slo, Bhi, Blo, bd, out, out, nullptr, nullptr, nullptr, nullptr, ROWS, Dd, FFd);
}